// round 3
// baseline (speedup 1.0000x reference)
#include <cuda_runtime.h>
#include <math.h>

#define TOKENS 8192
#define DMODEL 768
#define HEADS  12
#define DHEAD  64
#define DFF    3072
#define DEPTH  12
#define SEQ    1024
#define QKV3   2304   // 3 * 768

// ---------------- scratch (allocation-free: __device__ globals) ----------------
__device__ float g_x[TOKENS * DMODEL];        // residual stream        (25 MB)
__device__ float g_h[TOKENS * DMODEL];        // post-LN activations    (25 MB)
__device__ float g_qkv[TOKENS * QKV3];        // fused qkv              (75 MB)
__device__ float g_attnout[TOKENS * DMODEL];  // attention output       (25 MB)
__device__ float g_ff[TOKENS * DFF];          // FF hidden             (100 MB)

// ---------------- utility: vectorized copy ----------------
__global__ void copy4_kernel(const float4* __restrict__ src, float4* __restrict__ dst, int n) {
    int i = blockIdx.x * blockDim.x + threadIdx.x;
    if (i < n) dst[i] = src[i];
}

// ---------------- LayerNorm: one block per row of 768 ----------------
__global__ __launch_bounds__(256) void ln_kernel(
    const float* __restrict__ in, const float* __restrict__ w,
    const float* __restrict__ b, float* __restrict__ out)
{
    int row = blockIdx.x;
    const float* p = in + (size_t)row * DMODEL;
    __shared__ float s1[256], s2[256];
    int tid = threadIdx.x;
    float sum = 0.f, sq = 0.f;
    for (int c = tid; c < DMODEL; c += 256) { float v = p[c]; sum += v; sq += v * v; }
    s1[tid] = sum; s2[tid] = sq;
    __syncthreads();
    for (int o = 128; o > 0; o >>= 1) {
        if (tid < o) { s1[tid] += s1[tid + o]; s2[tid] += s2[tid + o]; }
        __syncthreads();
    }
    float mu  = s1[0] * (1.0f / DMODEL);
    float var = s2[0] * (1.0f / DMODEL) - mu * mu;
    float rs  = rsqrtf(var + 1e-5f);
    float* q = out + (size_t)row * DMODEL;
    for (int c = tid; c < DMODEL; c += 256) q[c] = (p[c] - mu) * rs * w[c] + b[c];
}

// ---------------- SGEMM: C[M,N] = A[M,K] @ B[K,N] (+epilogue) ----------------
// BM=BN=64, BK=16, 256 threads, 4x4 per thread.
// EPI: 0 = none, 1 = +bias +residual, 2 = +bias then exact GELU
template <int EPI>
__global__ __launch_bounds__(256) void gemm_kernel(
    const float* __restrict__ A, const float* __restrict__ B,
    const float* __restrict__ bias, const float* __restrict__ res,
    float* __restrict__ C, int M, int N, int K)
{
    __shared__ float As[16][68];  // [k][m], padded
    __shared__ float Bs[16][68];  // [k][n]

    int tid = threadIdx.x;
    int bm = blockIdx.y * 64, bn = blockIdx.x * 64;
    int rt = tid >> 4, ct = tid & 15;           // compute-thread 16x16 grid
    int am = tid >> 2, ak4 = (tid & 3) * 4;     // A load: row, 4-col group
    int bk = tid >> 4, bn4 = (tid & 15) * 4;    // B load: k-row, 4-col group

    float acc[4][4];
    #pragma unroll
    for (int i = 0; i < 4; i++)
        #pragma unroll
        for (int j = 0; j < 4; j++) acc[i][j] = 0.f;

    const float* Aptr = A + (size_t)(bm + am) * K + ak4;
    const float* Bptr = B + (size_t)bk * N + bn + bn4;

    for (int k0 = 0; k0 < K; k0 += 16) {
        float4 a  = *(const float4*)(Aptr + k0);
        float4 bv = *(const float4*)(Bptr + (size_t)k0 * N);
        As[ak4 + 0][am] = a.x; As[ak4 + 1][am] = a.y;
        As[ak4 + 2][am] = a.z; As[ak4 + 3][am] = a.w;
        *(float4*)&Bs[bk][bn4] = bv;
        __syncthreads();
        #pragma unroll
        for (int kk = 0; kk < 16; kk++) {
            float4 av = *(const float4*)&As[kk][rt * 4];
            float4 bb = *(const float4*)&Bs[kk][ct * 4];
            float aa[4] = {av.x, av.y, av.z, av.w};
            float bx[4] = {bb.x, bb.y, bb.z, bb.w};
            #pragma unroll
            for (int i = 0; i < 4; i++)
                #pragma unroll
                for (int j = 0; j < 4; j++) acc[i][j] += aa[i] * bx[j];
        }
        __syncthreads();
    }

    #pragma unroll
    for (int i = 0; i < 4; i++) {
        int m = bm + rt * 4 + i;
        #pragma unroll
        for (int j = 0; j < 4; j++) {
            int n = bn + ct * 4 + j;
            float v = acc[i][j];
            if (EPI >= 1) v += bias[n];
            if (EPI == 2) v = 0.5f * v * (1.0f + erff(v * 0.70710678118654752f));
            if (EPI == 1) v += res[(size_t)m * N + n];
            C[(size_t)m * N + n] = v;
        }
    }
}

// ---------------- Fused flash attention (static smem < 48 KB) ----------------
// One block = one 64-row q tile of one (b,h). Streams 32-row K/V tiles,
// online softmax, accumulates O in registers. No materialized scores.
__global__ __launch_bounds__(256) void attn_fused_kernel(
    const float* __restrict__ qkv, float* __restrict__ out)
{
    __shared__ float Qs[64][65];   // q tile (padded: column access over d)
    __shared__ float Ks[32][65];   // k tile
    __shared__ float Vs[32][65];   // v tile
    __shared__ float Ps[64][33];   // probability tile (padded: column access over kk)

    int bh = blockIdx.y;
    int b = bh / HEADS, h = bh % HEADS;
    int qt = blockIdx.x * 64;

    int tid = threadIdx.x;
    int rt = tid >> 4, ct = tid & 15;

    const float* qbase = qkv + (size_t)(b * SEQ) * QKV3 + h * DHEAD;
    const float* kbase = qbase + DMODEL;
    const float* vbase = qbase + 2 * DMODEL;

    // load Q tile once: 64 rows x 64 cols, float4 per thread x4
    #pragma unroll
    for (int v = 0; v < 4; v++) {
        int idx = tid + v * 256;
        int r = idx >> 4, c4 = (idx & 15) * 4;
        float4 qv = *(const float4*)(qbase + (size_t)(qt + r) * QKV3 + c4);
        Qs[r][c4 + 0] = qv.x; Qs[r][c4 + 1] = qv.y;
        Qs[r][c4 + 2] = qv.z; Qs[r][c4 + 3] = qv.w;
    }

    float acc_o[4][4];
    float m_i[4], l_i[4];
    #pragma unroll
    for (int i = 0; i < 4; i++) {
        m_i[i] = -1e30f; l_i[i] = 0.f;
        #pragma unroll
        for (int j = 0; j < 4; j++) acc_o[i][j] = 0.f;
    }

    for (int kt = 0; kt < SEQ; kt += 32) {
        __syncthreads();  // prior PV reads of Vs/Ps done
        // load K tile (32x64) and V tile (32x64): 512 float4 each, 256 threads -> 2 each
        #pragma unroll
        for (int v = 0; v < 2; v++) {
            int idx = tid + v * 256;
            int r = idx >> 4, c4 = (idx & 15) * 4;
            float4 kv = *(const float4*)(kbase + (size_t)(kt + r) * QKV3 + c4);
            Ks[r][c4 + 0] = kv.x; Ks[r][c4 + 1] = kv.y;
            Ks[r][c4 + 2] = kv.z; Ks[r][c4 + 3] = kv.w;
            float4 vv = *(const float4*)(vbase + (size_t)(kt + r) * QKV3 + c4);
            Vs[r][c4 + 0] = vv.x; Vs[r][c4 + 1] = vv.y;
            Vs[r][c4 + 2] = vv.z; Vs[r][c4 + 3] = vv.w;
        }
        __syncthreads();

        // S tile 64x32: each thread 4 q-rows (rt) x 2 k-cols (ct)
        float acc_s[4][2];
        #pragma unroll
        for (int i = 0; i < 4; i++) { acc_s[i][0] = 0.f; acc_s[i][1] = 0.f; }

        #pragma unroll 8
        for (int d = 0; d < 64; d++) {
            float a[4], bb[2];
            #pragma unroll
            for (int i = 0; i < 4; i++) a[i]  = Qs[rt * 4 + i][d];
            bb[0] = Ks[ct * 2 + 0][d];
            bb[1] = Ks[ct * 2 + 1][d];
            #pragma unroll
            for (int i = 0; i < 4; i++) {
                acc_s[i][0] += a[i] * bb[0];
                acc_s[i][1] += a[i] * bb[1];
            }
        }

        // online softmax update per q-row; row spans 16 ct lanes x 2 cols
        #pragma unroll
        for (int i = 0; i < 4; i++) {
            acc_s[i][0] *= 0.125f; acc_s[i][1] *= 0.125f;
            float tm = fmaxf(acc_s[i][0], acc_s[i][1]);
            #pragma unroll
            for (int o = 1; o < 16; o <<= 1)
                tm = fmaxf(tm, __shfl_xor_sync(0xffffffffu, tm, o));
            float new_m = fmaxf(m_i[i], tm);
            float corr = expf(m_i[i] - new_m);
            acc_s[i][0] = expf(acc_s[i][0] - new_m);
            acc_s[i][1] = expf(acc_s[i][1] - new_m);
            float ts = acc_s[i][0] + acc_s[i][1];
            #pragma unroll
            for (int o = 1; o < 16; o <<= 1)
                ts += __shfl_xor_sync(0xffffffffu, ts, o);
            l_i[i] = l_i[i] * corr + ts;
            m_i[i] = new_m;
            #pragma unroll
            for (int j = 0; j < 4; j++) acc_o[i][j] *= corr;
        }

        // write P tile
        #pragma unroll
        for (int i = 0; i < 4; i++) {
            Ps[rt * 4 + i][ct * 2 + 0] = acc_s[i][0];
            Ps[rt * 4 + i][ct * 2 + 1] = acc_s[i][1];
        }
        __syncthreads();

        // acc_o += P(64x32) @ V(32x64): each thread 4x4 via rt/ct 16x16
        #pragma unroll 8
        for (int kk = 0; kk < 32; kk++) {
            float a[4], bb[4];
            #pragma unroll
            for (int i = 0; i < 4; i++) a[i]  = Ps[rt * 4 + i][kk];
            #pragma unroll
            for (int j = 0; j < 4; j++) bb[j] = Vs[kk][ct * 4 + j];
            #pragma unroll
            for (int i = 0; i < 4; i++)
                #pragma unroll
                for (int j = 0; j < 4; j++) acc_o[i][j] += a[i] * bb[j];
        }
    }

    // normalize and write out: out[token][h*64 + d]
    #pragma unroll
    for (int i = 0; i < 4; i++) {
        float inv = 1.0f / l_i[i];
        int tok = b * SEQ + qt + rt * 4 + i;
        #pragma unroll
        for (int j = 0; j < 4; j++)
            out[(size_t)tok * DMODEL + h * DHEAD + ct * 4 + j] = acc_o[i][j] * inv;
    }
}

// ---------------- host orchestration ----------------
extern "C" void kernel_launch(void* const* d_in, const int* in_sizes, int n_in,
                              void* d_out, int out_size)
{
    const float* x     = (const float*)d_in[0];
    const float* ln1w  = (const float*)d_in[1];
    const float* ln1b  = (const float*)d_in[2];
    const float* wqkv  = (const float*)d_in[3];
    const float* wo    = (const float*)d_in[4];
    const float* bo    = (const float*)d_in[5];
    const float* ln2w  = (const float*)d_in[6];
    const float* ln2b  = (const float*)d_in[7];
    const float* w1    = (const float*)d_in[8];
    const float* b1    = (const float*)d_in[9];
    const float* w2    = (const float*)d_in[10];
    const float* b2    = (const float*)d_in[11];
    const float* lnfw  = (const float*)d_in[12];
    const float* lnfb  = (const float*)d_in[13];

    float *gx, *gh, *gqkv, *gao, *gff;
    cudaGetSymbolAddress((void**)&gx,   g_x);
    cudaGetSymbolAddress((void**)&gh,   g_h);
    cudaGetSymbolAddress((void**)&gqkv, g_qkv);
    cudaGetSymbolAddress((void**)&gao,  g_attnout);
    cudaGetSymbolAddress((void**)&gff,  g_ff);

    // x -> residual stream
    {
        int n4 = TOKENS * DMODEL / 4;
        copy4_kernel<<<(n4 + 255) / 256, 256>>>((const float4*)x, (float4*)gx, n4);
    }

    for (int l = 0; l < DEPTH; l++) {
        const float* L1w = ln1w + (size_t)l * DMODEL;
        const float* L1b = ln1b + (size_t)l * DMODEL;
        const float* Wq  = wqkv + (size_t)l * DMODEL * QKV3;
        const float* Wo  = wo   + (size_t)l * DMODEL * DMODEL;
        const float* Bo  = bo   + (size_t)l * DMODEL;
        const float* L2w = ln2w + (size_t)l * DMODEL;
        const float* L2b = ln2b + (size_t)l * DMODEL;
        const float* W1  = w1   + (size_t)l * DMODEL * DFF;
        const float* B1  = b1   + (size_t)l * DFF;
        const float* W2  = w2   + (size_t)l * DFF * DMODEL;
        const float* B2  = b2   + (size_t)l * DMODEL;

        // LN1
        ln_kernel<<<TOKENS, 256>>>(gx, L1w, L1b, gh);
        // QKV = h @ Wqkv
        gemm_kernel<0><<<dim3(QKV3 / 64, TOKENS / 64), 256>>>(gh, Wq, nullptr, nullptr, gqkv,
                                                              TOKENS, QKV3, DMODEL);
        // fused attention (scores + softmax + AV), static smem
        attn_fused_kernel<<<dim3(SEQ / 64, 8 * HEADS), 256>>>(gqkv, gao);
        // O proj + bias + residual  (x = ao @ Wo + bo + x)
        gemm_kernel<1><<<dim3(DMODEL / 64, TOKENS / 64), 256>>>(gao, Wo, Bo, gx, gx,
                                                                TOKENS, DMODEL, DMODEL);
        // LN2
        ln_kernel<<<TOKENS, 256>>>(gx, L2w, L2b, gh);
        // FF1 + bias + GELU(exact)
        gemm_kernel<2><<<dim3(DFF / 64, TOKENS / 64), 256>>>(gh, W1, B1, nullptr, gff,
                                                             TOKENS, DFF, DMODEL);
        // FF2 + bias + residual  (x = ff @ W2 + b2 + x)
        gemm_kernel<1><<<dim3(DMODEL / 64, TOKENS / 64), 256>>>(gff, W2, B2, gx, gx,
                                                                TOKENS, DMODEL, DFF);
    }

    // final LN -> output
    ln_kernel<<<TOKENS, 256>>>(gx, lnfw, lnfb, (float*)d_out);
}

// round 4
// speedup vs baseline: 2.0574x; 2.0574x over previous
#include <cuda_runtime.h>
#include <math.h>

#define TOKENS 8192
#define DMODEL 768
#define HEADS  12
#define DHEAD  64
#define DFF    3072
#define DEPTH  12
#define SEQ    1024
#define QKV3   2304   // 3 * 768

// ---------------- scratch (allocation-free: __device__ globals) ----------------
__device__ float g_x[TOKENS * DMODEL];        // residual stream        (25 MB)
__device__ float g_h[TOKENS * DMODEL];        // post-LN activations    (25 MB)
__device__ float g_qkv[TOKENS * QKV3];        // fused qkv              (75 MB)
__device__ float g_attnout[TOKENS * DMODEL];  // attention output       (25 MB)
__device__ float g_ff[TOKENS * DFF];          // FF hidden             (100 MB)

// ---------------- utility ----------------
__global__ void copy4_kernel(const float4* __restrict__ src, float4* __restrict__ dst, int n) {
    int i = blockIdx.x * blockDim.x + threadIdx.x;
    if (i < n) dst[i] = src[i];
}

__device__ __forceinline__ float to_tf32(float x) {
    float y;
    asm("cvt.rna.tf32.f32 %0, %1;" : "=f"(y) : "f"(x));
    return y;
}

__device__ __forceinline__ void mma_tf32_16x8x8(
    float* d, const float* a, const float* b)
{
    asm volatile(
        "mma.sync.aligned.m16n8k8.row.col.f32.tf32.tf32.f32 "
        "{%0,%1,%2,%3}, {%4,%5,%6,%7}, {%8,%9}, {%0,%1,%2,%3};\n"
        : "+f"(d[0]), "+f"(d[1]), "+f"(d[2]), "+f"(d[3])
        : "r"(__float_as_uint(a[0])), "r"(__float_as_uint(a[1])),
          "r"(__float_as_uint(a[2])), "r"(__float_as_uint(a[3])),
          "r"(__float_as_uint(b[0])), "r"(__float_as_uint(b[1])));
}

// ---------------- LayerNorm: one block per row of 768 ----------------
__global__ __launch_bounds__(256) void ln_kernel(
    const float* __restrict__ in, const float* __restrict__ w,
    const float* __restrict__ b, float* __restrict__ out)
{
    int row = blockIdx.x;
    const float* p = in + (size_t)row * DMODEL;
    __shared__ float s1[256], s2[256];
    int tid = threadIdx.x;
    float sum = 0.f, sq = 0.f;
    for (int c = tid; c < DMODEL; c += 256) { float v = p[c]; sum += v; sq += v * v; }
    s1[tid] = sum; s2[tid] = sq;
    __syncthreads();
    for (int o = 128; o > 0; o >>= 1) {
        if (tid < o) { s1[tid] += s1[tid + o]; s2[tid] += s2[tid + o]; }
        __syncthreads();
    }
    float mu  = s1[0] * (1.0f / DMODEL);
    float var = s2[0] * (1.0f / DMODEL) - mu * mu;
    float rs  = rsqrtf(var + 1e-5f);
    float* q = out + (size_t)row * DMODEL;
    for (int c = tid; c < DMODEL; c += 256) q[c] = (p[c] - mu) * rs * w[c] + b[c];
}

// ---------------- tf32 tensor-core GEMM: C[M,N] = A[M,K] @ B[K,N] ----------------
// 128x128 block tile, BK=16, 256 threads = 8 warps (4 M x 2 N), warp tile 32x64.
// Each warp: 2 (m16) x 8 (n8) mma tiles, k split in two k8 steps.
// EPI: 0 = none, 1 = +bias +residual, 2 = +bias then exact GELU
template <int EPI>
__global__ __launch_bounds__(256) void gemm_tc_kernel(
    const float* __restrict__ A, const float* __restrict__ B,
    const float* __restrict__ bias, const float* __restrict__ res,
    float* __restrict__ C, int M, int N, int K)
{
    __shared__ float As[128][20];   // [m][k], pad 16->20 (conflict-free frag reads)
    __shared__ float Bs[16][136];   // [k][n], pad 128->136

    int tid  = threadIdx.x;
    int lane = tid & 31;
    int wid  = tid >> 5;
    int wm = wid & 3, wn = wid >> 2;          // warp coords: 4 x 2
    int bm = blockIdx.y * 128, bn = blockIdx.x * 128;

    int grp = lane >> 2, thr = lane & 3;      // mma fragment coords

    float acc[2][8][4];
    #pragma unroll
    for (int i = 0; i < 2; i++)
        #pragma unroll
        for (int j = 0; j < 8; j++)
            #pragma unroll
            for (int v = 0; v < 4; v++) acc[i][j][v] = 0.f;

    // global load indexing (per thread: 2 float4 of A, 2 float4 of B per tile)
    int a_r0 = tid >> 2,        a_c0 = (tid & 3) * 4;           // A: rows 0..63 batch0
    int b_k0 = tid >> 5,        b_c0 = (tid & 31) * 4;          // B: k rows 0..7 batch0

    float4 pa[2], pb[2];

    // ---- preload tile k0 = 0 ----
    #pragma unroll
    for (int v = 0; v < 2; v++) {
        pa[v] = *(const float4*)(A + (size_t)(bm + a_r0 + v * 64) * K + a_c0);
        pb[v] = *(const float4*)(B + (size_t)(b_k0 + v * 8) * N + bn + b_c0);
    }
    #pragma unroll
    for (int v = 0; v < 2; v++) {
        int r = a_r0 + v * 64;
        As[r][a_c0 + 0] = to_tf32(pa[v].x); As[r][a_c0 + 1] = to_tf32(pa[v].y);
        As[r][a_c0 + 2] = to_tf32(pa[v].z); As[r][a_c0 + 3] = to_tf32(pa[v].w);
        int kr = b_k0 + v * 8;
        Bs[kr][b_c0 + 0] = to_tf32(pb[v].x); Bs[kr][b_c0 + 1] = to_tf32(pb[v].y);
        Bs[kr][b_c0 + 2] = to_tf32(pb[v].z); Bs[kr][b_c0 + 3] = to_tf32(pb[v].w);
    }
    __syncthreads();

    for (int k0 = 0; k0 < K; k0 += 16) {
        bool has_next = (k0 + 16) < K;
        if (has_next) {
            #pragma unroll
            for (int v = 0; v < 2; v++) {
                pa[v] = *(const float4*)(A + (size_t)(bm + a_r0 + v * 64) * K + k0 + 16 + a_c0);
                pb[v] = *(const float4*)(B + (size_t)(k0 + 16 + b_k0 + v * 8) * N + bn + b_c0);
            }
        }

        // ---- compute both k8 sub-steps ----
        #pragma unroll
        for (int kk = 0; kk < 16; kk += 8) {
            float afrag[2][4];
            #pragma unroll
            for (int mt = 0; mt < 2; mt++) {
                int r = wm * 32 + mt * 16 + grp;
                afrag[mt][0] = As[r    ][kk + thr];
                afrag[mt][1] = As[r + 8][kk + thr];
                afrag[mt][2] = As[r    ][kk + thr + 4];
                afrag[mt][3] = As[r + 8][kk + thr + 4];
            }
            #pragma unroll
            for (int nt = 0; nt < 8; nt++) {
                float bfrag[2];
                int c = wn * 64 + nt * 8 + grp;
                bfrag[0] = Bs[kk + thr    ][c];
                bfrag[1] = Bs[kk + thr + 4][c];
                #pragma unroll
                for (int mt = 0; mt < 2; mt++)
                    mma_tf32_16x8x8(acc[mt][nt], afrag[mt], bfrag);
            }
        }
        __syncthreads();

        if (has_next) {
            #pragma unroll
            for (int v = 0; v < 2; v++) {
                int r = a_r0 + v * 64;
                As[r][a_c0 + 0] = to_tf32(pa[v].x); As[r][a_c0 + 1] = to_tf32(pa[v].y);
                As[r][a_c0 + 2] = to_tf32(pa[v].z); As[r][a_c0 + 3] = to_tf32(pa[v].w);
                int kr = b_k0 + v * 8;
                Bs[kr][b_c0 + 0] = to_tf32(pb[v].x); Bs[kr][b_c0 + 1] = to_tf32(pb[v].y);
                Bs[kr][b_c0 + 2] = to_tf32(pb[v].z); Bs[kr][b_c0 + 3] = to_tf32(pb[v].w);
            }
            __syncthreads();
        }
    }

    // ---- epilogue ----
    #pragma unroll
    for (int mt = 0; mt < 2; mt++) {
        #pragma unroll
        for (int nt = 0; nt < 8; nt++) {
            int r0 = bm + wm * 32 + mt * 16 + grp;
            int c0 = bn + wn * 64 + nt * 8 + 2 * thr;
            #pragma unroll
            for (int half = 0; half < 2; half++) {   // rows r0, r0+8
                int m = r0 + half * 8;
                float v0 = acc[mt][nt][half * 2 + 0];
                float v1 = acc[mt][nt][half * 2 + 1];
                if (EPI >= 1) { v0 += bias[c0]; v1 += bias[c0 + 1]; }
                if (EPI == 2) {
                    v0 = 0.5f * v0 * (1.0f + erff(v0 * 0.70710678118654752f));
                    v1 = 0.5f * v1 * (1.0f + erff(v1 * 0.70710678118654752f));
                }
                if (EPI == 1) {
                    const float* rr = res + (size_t)m * N + c0;
                    v0 += rr[0]; v1 += rr[1];
                }
                float2* outp = (float2*)(C + (size_t)m * N + c0);
                *outp = make_float2(v0, v1);
            }
        }
    }
}

// ---------------- Fused flash attention (static smem < 48 KB) ----------------
__global__ __launch_bounds__(256) void attn_fused_kernel(
    const float* __restrict__ qkv, float* __restrict__ out)
{
    __shared__ float Qs[64][65];
    __shared__ float Ks[32][65];
    __shared__ float Vs[32][65];
    __shared__ float Ps[64][33];

    int bh = blockIdx.y;
    int b = bh / HEADS, h = bh % HEADS;
    int qt = blockIdx.x * 64;

    int tid = threadIdx.x;
    int rt = tid >> 4, ct = tid & 15;

    const float* qbase = qkv + (size_t)(b * SEQ) * QKV3 + h * DHEAD;
    const float* kbase = qbase + DMODEL;
    const float* vbase = qbase + 2 * DMODEL;

    #pragma unroll
    for (int v = 0; v < 4; v++) {
        int idx = tid + v * 256;
        int r = idx >> 4, c4 = (idx & 15) * 4;
        float4 qv = *(const float4*)(qbase + (size_t)(qt + r) * QKV3 + c4);
        Qs[r][c4 + 0] = qv.x; Qs[r][c4 + 1] = qv.y;
        Qs[r][c4 + 2] = qv.z; Qs[r][c4 + 3] = qv.w;
    }

    float acc_o[4][4];
    float m_i[4], l_i[4];
    #pragma unroll
    for (int i = 0; i < 4; i++) {
        m_i[i] = -1e30f; l_i[i] = 0.f;
        #pragma unroll
        for (int j = 0; j < 4; j++) acc_o[i][j] = 0.f;
    }

    for (int kt = 0; kt < SEQ; kt += 32) {
        __syncthreads();
        #pragma unroll
        for (int v = 0; v < 2; v++) {
            int idx = tid + v * 256;
            int r = idx >> 4, c4 = (idx & 15) * 4;
            float4 kv = *(const float4*)(kbase + (size_t)(kt + r) * QKV3 + c4);
            Ks[r][c4 + 0] = kv.x; Ks[r][c4 + 1] = kv.y;
            Ks[r][c4 + 2] = kv.z; Ks[r][c4 + 3] = kv.w;
            float4 vv = *(const float4*)(vbase + (size_t)(kt + r) * QKV3 + c4);
            Vs[r][c4 + 0] = vv.x; Vs[r][c4 + 1] = vv.y;
            Vs[r][c4 + 2] = vv.z; Vs[r][c4 + 3] = vv.w;
        }
        __syncthreads();

        float acc_s[4][2];
        #pragma unroll
        for (int i = 0; i < 4; i++) { acc_s[i][0] = 0.f; acc_s[i][1] = 0.f; }

        #pragma unroll 8
        for (int d = 0; d < 64; d++) {
            float a[4], bb[2];
            #pragma unroll
            for (int i = 0; i < 4; i++) a[i]  = Qs[rt * 4 + i][d];
            bb[0] = Ks[ct * 2 + 0][d];
            bb[1] = Ks[ct * 2 + 1][d];
            #pragma unroll
            for (int i = 0; i < 4; i++) {
                acc_s[i][0] += a[i] * bb[0];
                acc_s[i][1] += a[i] * bb[1];
            }
        }

        #pragma unroll
        for (int i = 0; i < 4; i++) {
            acc_s[i][0] *= 0.125f; acc_s[i][1] *= 0.125f;
            float tm = fmaxf(acc_s[i][0], acc_s[i][1]);
            #pragma unroll
            for (int o = 1; o < 16; o <<= 1)
                tm = fmaxf(tm, __shfl_xor_sync(0xffffffffu, tm, o));
            float new_m = fmaxf(m_i[i], tm);
            float corr = expf(m_i[i] - new_m);
            acc_s[i][0] = expf(acc_s[i][0] - new_m);
            acc_s[i][1] = expf(acc_s[i][1] - new_m);
            float ts = acc_s[i][0] + acc_s[i][1];
            #pragma unroll
            for (int o = 1; o < 16; o <<= 1)
                ts += __shfl_xor_sync(0xffffffffu, ts, o);
            l_i[i] = l_i[i] * corr + ts;
            m_i[i] = new_m;
            #pragma unroll
            for (int j = 0; j < 4; j++) acc_o[i][j] *= corr;
        }

        #pragma unroll
        for (int i = 0; i < 4; i++) {
            Ps[rt * 4 + i][ct * 2 + 0] = acc_s[i][0];
            Ps[rt * 4 + i][ct * 2 + 1] = acc_s[i][1];
        }
        __syncthreads();

        #pragma unroll 8
        for (int kk = 0; kk < 32; kk++) {
            float a[4], bb[4];
            #pragma unroll
            for (int i = 0; i < 4; i++) a[i]  = Ps[rt * 4 + i][kk];
            #pragma unroll
            for (int j = 0; j < 4; j++) bb[j] = Vs[kk][ct * 4 + j];
            #pragma unroll
            for (int i = 0; i < 4; i++)
                #pragma unroll
                for (int j = 0; j < 4; j++) acc_o[i][j] += a[i] * bb[j];
        }
    }

    #pragma unroll
    for (int i = 0; i < 4; i++) {
        float inv = 1.0f / l_i[i];
        int tok = b * SEQ + qt + rt * 4 + i;
        #pragma unroll
        for (int j = 0; j < 4; j++)
            out[(size_t)tok * DMODEL + h * DHEAD + ct * 4 + j] = acc_o[i][j] * inv;
    }
}

// ---------------- host orchestration ----------------
extern "C" void kernel_launch(void* const* d_in, const int* in_sizes, int n_in,
                              void* d_out, int out_size)
{
    const float* x     = (const float*)d_in[0];
    const float* ln1w  = (const float*)d_in[1];
    const float* ln1b  = (const float*)d_in[2];
    const float* wqkv  = (const float*)d_in[3];
    const float* wo    = (const float*)d_in[4];
    const float* bo    = (const float*)d_in[5];
    const float* ln2w  = (const float*)d_in[6];
    const float* ln2b  = (const float*)d_in[7];
    const float* w1    = (const float*)d_in[8];
    const float* b1    = (const float*)d_in[9];
    const float* w2    = (const float*)d_in[10];
    const float* b2    = (const float*)d_in[11];
    const float* lnfw  = (const float*)d_in[12];
    const float* lnfb  = (const float*)d_in[13];

    float *gx, *gh, *gqkv, *gao, *gff;
    cudaGetSymbolAddress((void**)&gx,   g_x);
    cudaGetSymbolAddress((void**)&gh,   g_h);
    cudaGetSymbolAddress((void**)&gqkv, g_qkv);
    cudaGetSymbolAddress((void**)&gao,  g_attnout);
    cudaGetSymbolAddress((void**)&gff,  g_ff);

    {
        int n4 = TOKENS * DMODEL / 4;
        copy4_kernel<<<(n4 + 255) / 256, 256>>>((const float4*)x, (float4*)gx, n4);
    }

    for (int l = 0; l < DEPTH; l++) {
        const float* L1w = ln1w + (size_t)l * DMODEL;
        const float* L1b = ln1b + (size_t)l * DMODEL;
        const float* Wq  = wqkv + (size_t)l * DMODEL * QKV3;
        const float* Wo  = wo   + (size_t)l * DMODEL * DMODEL;
        const float* Bo  = bo   + (size_t)l * DMODEL;
        const float* L2w = ln2w + (size_t)l * DMODEL;
        const float* L2b = ln2b + (size_t)l * DMODEL;
        const float* W1  = w1   + (size_t)l * DMODEL * DFF;
        const float* B1  = b1   + (size_t)l * DFF;
        const float* W2  = w2   + (size_t)l * DFF * DMODEL;
        const float* B2  = b2   + (size_t)l * DMODEL;

        // LN1
        ln_kernel<<<TOKENS, 256>>>(gx, L1w, L1b, gh);
        // QKV = h @ Wqkv  (tf32 tensor cores)
        gemm_tc_kernel<0><<<dim3(QKV3 / 128, TOKENS / 128), 256>>>(gh, Wq, nullptr, nullptr, gqkv,
                                                                   TOKENS, QKV3, DMODEL);
        // fused attention
        attn_fused_kernel<<<dim3(SEQ / 64, 8 * HEADS), 256>>>(gqkv, gao);
        // O proj + bias + residual
        gemm_tc_kernel<1><<<dim3(DMODEL / 128, TOKENS / 128), 256>>>(gao, Wo, Bo, gx, gx,
                                                                     TOKENS, DMODEL, DMODEL);
        // LN2
        ln_kernel<<<TOKENS, 256>>>(gx, L2w, L2b, gh);
        // FF1 + bias + GELU(exact)
        gemm_tc_kernel<2><<<dim3(DFF / 128, TOKENS / 128), 256>>>(gh, W1, B1, nullptr, gff,
                                                                  TOKENS, DFF, DMODEL);
        // FF2 + bias + residual
        gemm_tc_kernel<1><<<dim3(DMODEL / 128, TOKENS / 128), 256>>>(gff, W2, B2, gx, gx,
                                                                     TOKENS, DMODEL, DFF);
    }

    // final LN -> output
    ln_kernel<<<TOKENS, 256>>>(gx, lnfw, lnfb, (float*)d_out);
}

// round 5
// speedup vs baseline: 3.0806x; 1.4973x over previous
#include <cuda_runtime.h>
#include <math.h>

#define TOKENS 8192
#define DMODEL 768
#define HEADS  12
#define DHEAD  64
#define DFF    3072
#define DEPTH  12
#define SEQ    1024
#define QKV3   2304   // 3 * 768

// ---------------- scratch (allocation-free: __device__ globals) ----------------
__device__ float g_x[TOKENS * DMODEL];        // residual stream
__device__ float g_h[TOKENS * DMODEL];        // post-LN activations
__device__ float g_qkv[TOKENS * QKV3];        // fused qkv
__device__ float g_attnout[TOKENS * DMODEL];  // attention output
__device__ float g_ff[TOKENS * DFF];          // FF hidden

// ---------------- utility ----------------
__global__ void copy4_kernel(const float4* __restrict__ src, float4* __restrict__ dst, int n) {
    int i = blockIdx.x * blockDim.x + threadIdx.x;
    if (i < n) dst[i] = src[i];
}

__device__ __forceinline__ float to_tf32(float x) {
    float y;
    asm("cvt.rna.tf32.f32 %0, %1;" : "=f"(y) : "f"(x));
    return y;
}

__device__ __forceinline__ void mma_tf32_16x8x8(
    float* d, const float* a, const float* b)
{
    asm volatile(
        "mma.sync.aligned.m16n8k8.row.col.f32.tf32.tf32.f32 "
        "{%0,%1,%2,%3}, {%4,%5,%6,%7}, {%8,%9}, {%0,%1,%2,%3};\n"
        : "+f"(d[0]), "+f"(d[1]), "+f"(d[2]), "+f"(d[3])
        : "r"(__float_as_uint(a[0])), "r"(__float_as_uint(a[1])),
          "r"(__float_as_uint(a[2])), "r"(__float_as_uint(a[3])),
          "r"(__float_as_uint(b[0])), "r"(__float_as_uint(b[1])));
}

// ---------------- LayerNorm: one block per row of 768 ----------------
__global__ __launch_bounds__(256) void ln_kernel(
    const float* __restrict__ in, const float* __restrict__ w,
    const float* __restrict__ b, float* __restrict__ out)
{
    int row = blockIdx.x;
    const float* p = in + (size_t)row * DMODEL;
    __shared__ float s1[256], s2[256];
    int tid = threadIdx.x;
    float sum = 0.f, sq = 0.f;
    for (int c = tid; c < DMODEL; c += 256) { float v = p[c]; sum += v; sq += v * v; }
    s1[tid] = sum; s2[tid] = sq;
    __syncthreads();
    for (int o = 128; o > 0; o >>= 1) {
        if (tid < o) { s1[tid] += s1[tid + o]; s2[tid] += s2[tid + o]; }
        __syncthreads();
    }
    float mu  = s1[0] * (1.0f / DMODEL);
    float var = s2[0] * (1.0f / DMODEL) - mu * mu;
    float rs  = rsqrtf(var + 1e-5f);
    float* q = out + (size_t)row * DMODEL;
    for (int c = tid; c < DMODEL; c += 256) q[c] = (p[c] - mu) * rs * w[c] + b[c];
}

// ---------------- tf32 tensor-core GEMM: C[M,N] = A[M,K] @ B[K,N] ----------------
template <int EPI>
__global__ __launch_bounds__(256) void gemm_tc_kernel(
    const float* __restrict__ A, const float* __restrict__ B,
    const float* __restrict__ bias, const float* __restrict__ res,
    float* __restrict__ C, int M, int N, int K)
{
    __shared__ float As[128][20];
    __shared__ float Bs[16][136];

    int tid  = threadIdx.x;
    int lane = tid & 31;
    int wid  = tid >> 5;
    int wm = wid & 3, wn = wid >> 2;
    int bm = blockIdx.y * 128, bn = blockIdx.x * 128;

    int grp = lane >> 2, thr = lane & 3;

    float acc[2][8][4];
    #pragma unroll
    for (int i = 0; i < 2; i++)
        #pragma unroll
        for (int j = 0; j < 8; j++)
            #pragma unroll
            for (int v = 0; v < 4; v++) acc[i][j][v] = 0.f;

    int a_r0 = tid >> 2,        a_c0 = (tid & 3) * 4;
    int b_k0 = tid >> 5,        b_c0 = (tid & 31) * 4;

    float4 pa[2], pb[2];

    #pragma unroll
    for (int v = 0; v < 2; v++) {
        pa[v] = *(const float4*)(A + (size_t)(bm + a_r0 + v * 64) * K + a_c0);
        pb[v] = *(const float4*)(B + (size_t)(b_k0 + v * 8) * N + bn + b_c0);
    }
    #pragma unroll
    for (int v = 0; v < 2; v++) {
        int r = a_r0 + v * 64;
        As[r][a_c0 + 0] = to_tf32(pa[v].x); As[r][a_c0 + 1] = to_tf32(pa[v].y);
        As[r][a_c0 + 2] = to_tf32(pa[v].z); As[r][a_c0 + 3] = to_tf32(pa[v].w);
        int kr = b_k0 + v * 8;
        Bs[kr][b_c0 + 0] = to_tf32(pb[v].x); Bs[kr][b_c0 + 1] = to_tf32(pb[v].y);
        Bs[kr][b_c0 + 2] = to_tf32(pb[v].z); Bs[kr][b_c0 + 3] = to_tf32(pb[v].w);
    }
    __syncthreads();

    for (int k0 = 0; k0 < K; k0 += 16) {
        bool has_next = (k0 + 16) < K;
        if (has_next) {
            #pragma unroll
            for (int v = 0; v < 2; v++) {
                pa[v] = *(const float4*)(A + (size_t)(bm + a_r0 + v * 64) * K + k0 + 16 + a_c0);
                pb[v] = *(const float4*)(B + (size_t)(k0 + 16 + b_k0 + v * 8) * N + bn + b_c0);
            }
        }

        #pragma unroll
        for (int kk = 0; kk < 16; kk += 8) {
            float afrag[2][4];
            #pragma unroll
            for (int mt = 0; mt < 2; mt++) {
                int r = wm * 32 + mt * 16 + grp;
                afrag[mt][0] = As[r    ][kk + thr];
                afrag[mt][1] = As[r + 8][kk + thr];
                afrag[mt][2] = As[r    ][kk + thr + 4];
                afrag[mt][3] = As[r + 8][kk + thr + 4];
            }
            #pragma unroll
            for (int nt = 0; nt < 8; nt++) {
                float bfrag[2];
                int c = wn * 64 + nt * 8 + grp;
                bfrag[0] = Bs[kk + thr    ][c];
                bfrag[1] = Bs[kk + thr + 4][c];
                #pragma unroll
                for (int mt = 0; mt < 2; mt++)
                    mma_tf32_16x8x8(acc[mt][nt], afrag[mt], bfrag);
            }
        }
        __syncthreads();

        if (has_next) {
            #pragma unroll
            for (int v = 0; v < 2; v++) {
                int r = a_r0 + v * 64;
                As[r][a_c0 + 0] = to_tf32(pa[v].x); As[r][a_c0 + 1] = to_tf32(pa[v].y);
                As[r][a_c0 + 2] = to_tf32(pa[v].z); As[r][a_c0 + 3] = to_tf32(pa[v].w);
                int kr = b_k0 + v * 8;
                Bs[kr][b_c0 + 0] = to_tf32(pb[v].x); Bs[kr][b_c0 + 1] = to_tf32(pb[v].y);
                Bs[kr][b_c0 + 2] = to_tf32(pb[v].z); Bs[kr][b_c0 + 3] = to_tf32(pb[v].w);
            }
            __syncthreads();
        }
    }

    #pragma unroll
    for (int mt = 0; mt < 2; mt++) {
        #pragma unroll
        for (int nt = 0; nt < 8; nt++) {
            int r0 = bm + wm * 32 + mt * 16 + grp;
            int c0 = bn + wn * 64 + nt * 8 + 2 * thr;
            #pragma unroll
            for (int half = 0; half < 2; half++) {
                int m = r0 + half * 8;
                float v0 = acc[mt][nt][half * 2 + 0];
                float v1 = acc[mt][nt][half * 2 + 1];
                if (EPI >= 1) { v0 += bias[c0]; v1 += bias[c0 + 1]; }
                if (EPI == 2) {
                    v0 = 0.5f * v0 * (1.0f + erff(v0 * 0.70710678118654752f));
                    v1 = 0.5f * v1 * (1.0f + erff(v1 * 0.70710678118654752f));
                }
                if (EPI == 1) {
                    const float* rr = res + (size_t)m * N + c0;
                    v0 += rr[0]; v1 += rr[1];
                }
                float2* outp = (float2*)(C + (size_t)m * N + c0);
                *outp = make_float2(v0, v1);
            }
        }
    }
}

// ---------------- Tensor-core flash attention ----------------
// Block = 128 q rows of one (b,h); 256 threads = 8 warps, warp owns m16.
// Q held in registers as pre-scaled tf32 A-fragments. 32-key K/V tiles.
// smem strides: K=68, V=72, P=36 (per-instruction conflict-free).
#define KS_OFF 0
#define VS_OFF 2176            // 32*68
#define PS_OFF (2176 + 2304)   // + 32*72
#define SM_TOT (PS_OFF + 128 * 36)   // 9088 floats = 36.4 KB

__global__ __launch_bounds__(256) void attn_tc_kernel(
    const float* __restrict__ qkv, float* __restrict__ out)
{
    __shared__ float sm[SM_TOT];
    float* Ks = sm + KS_OFF;   // [32][68]  key-major
    float* Vs = sm + VS_OFF;   // [32][72]  key-major
    float* Ps = sm + PS_OFF;   // [128][36] q-major

    int tid = threadIdx.x;
    int lane = tid & 31, wid = tid >> 5;
    int grp = lane >> 2, thr = lane & 3;

    int bh = blockIdx.y;
    int b = bh / HEADS, h = bh % HEADS;
    int qt = blockIdx.x * 128;

    const float* qbase = qkv + (size_t)(b * SEQ) * QKV3 + h * DHEAD;
    const float* kbase = qbase + DMODEL;
    const float* vbase = qbase + 2 * DMODEL;

    // ---- stage Q (128x64) into smem (stride 68), pre-scaled, tf32 ----
    #pragma unroll
    for (int v = 0; v < 8; v++) {
        int idx = tid + v * 256;          // 2048 float4 total
        int r = idx >> 4, c4 = (idx & 15) * 4;
        float4 q4 = *(const float4*)(qbase + (size_t)(qt + r) * QKV3 + c4);
        sm[r * 68 + c4 + 0] = to_tf32(0.125f * q4.x);
        sm[r * 68 + c4 + 1] = to_tf32(0.125f * q4.y);
        sm[r * 68 + c4 + 2] = to_tf32(0.125f * q4.z);
        sm[r * 68 + c4 + 3] = to_tf32(0.125f * q4.w);
    }
    __syncthreads();

    // ---- Q A-fragments in registers: 8 k-steps x 4 ----
    float qfrag[8][4];
    int qr = wid * 16 + grp;
    #pragma unroll
    for (int ks = 0; ks < 8; ks++) {
        qfrag[ks][0] = sm[ qr      * 68 + ks * 8 + thr    ];
        qfrag[ks][1] = sm[(qr + 8) * 68 + ks * 8 + thr    ];
        qfrag[ks][2] = sm[ qr      * 68 + ks * 8 + thr + 4];
        qfrag[ks][3] = sm[(qr + 8) * 68 + ks * 8 + thr + 4];
    }
    __syncthreads();   // smem about to be reused for K/V

    float acc_o[8][4];
    #pragma unroll
    for (int nt = 0; nt < 8; nt++)
        #pragma unroll
        for (int v = 0; v < 4; v++) acc_o[nt][v] = 0.f;
    float m0 = -1e30f, m1 = -1e30f, l0 = 0.f, l1 = 0.f;

    for (int kt0 = 0; kt0 < SEQ; kt0 += 32) {
        // load K,V tiles (32x64 each), tf32
        #pragma unroll
        for (int v = 0; v < 2; v++) {
            int idx = tid + v * 256;      // 512 float4 per tensor
            int r = idx >> 4, c4 = (idx & 15) * 4;
            float4 k4 = *(const float4*)(kbase + (size_t)(kt0 + r) * QKV3 + c4);
            Ks[r * 68 + c4 + 0] = to_tf32(k4.x); Ks[r * 68 + c4 + 1] = to_tf32(k4.y);
            Ks[r * 68 + c4 + 2] = to_tf32(k4.z); Ks[r * 68 + c4 + 3] = to_tf32(k4.w);
            float4 v4 = *(const float4*)(vbase + (size_t)(kt0 + r) * QKV3 + c4);
            Vs[r * 72 + c4 + 0] = to_tf32(v4.x); Vs[r * 72 + c4 + 1] = to_tf32(v4.y);
            Vs[r * 72 + c4 + 2] = to_tf32(v4.z); Vs[r * 72 + c4 + 3] = to_tf32(v4.w);
        }
        __syncthreads();

        // ---- S = Q K^T : 4 n-tiles of 8 keys ----
        float acc_s[4][4];
        #pragma unroll
        for (int nt = 0; nt < 4; nt++)
            #pragma unroll
            for (int v = 0; v < 4; v++) acc_s[nt][v] = 0.f;

        #pragma unroll
        for (int ks = 0; ks < 8; ks++) {
            #pragma unroll
            for (int nt = 0; nt < 4; nt++) {
                float bfrag[2];
                int c = nt * 8 + grp;     // key index in tile
                bfrag[0] = Ks[c * 68 + ks * 8 + thr    ];
                bfrag[1] = Ks[c * 68 + ks * 8 + thr + 4];
                mma_tf32_16x8x8(acc_s[nt], qfrag[ks], bfrag);
            }
        }

        // ---- fragment online softmax (rows qr, qr+8) ----
        float tm0 = -1e30f, tm1 = -1e30f;
        #pragma unroll
        for (int nt = 0; nt < 4; nt++) {
            tm0 = fmaxf(tm0, fmaxf(acc_s[nt][0], acc_s[nt][1]));
            tm1 = fmaxf(tm1, fmaxf(acc_s[nt][2], acc_s[nt][3]));
        }
        tm0 = fmaxf(tm0, __shfl_xor_sync(0xffffffffu, tm0, 1));
        tm0 = fmaxf(tm0, __shfl_xor_sync(0xffffffffu, tm0, 2));
        tm1 = fmaxf(tm1, __shfl_xor_sync(0xffffffffu, tm1, 1));
        tm1 = fmaxf(tm1, __shfl_xor_sync(0xffffffffu, tm1, 2));

        float nm0 = fmaxf(m0, tm0), nm1 = fmaxf(m1, tm1);
        float c0 = expf(m0 - nm0),  c1 = expf(m1 - nm1);

        float s0 = 0.f, s1 = 0.f;
        #pragma unroll
        for (int nt = 0; nt < 4; nt++) {
            acc_s[nt][0] = expf(acc_s[nt][0] - nm0);
            acc_s[nt][1] = expf(acc_s[nt][1] - nm0);
            acc_s[nt][2] = expf(acc_s[nt][2] - nm1);
            acc_s[nt][3] = expf(acc_s[nt][3] - nm1);
            s0 += acc_s[nt][0] + acc_s[nt][1];
            s1 += acc_s[nt][2] + acc_s[nt][3];
        }
        s0 += __shfl_xor_sync(0xffffffffu, s0, 1);
        s0 += __shfl_xor_sync(0xffffffffu, s0, 2);
        s1 += __shfl_xor_sync(0xffffffffu, s1, 1);
        s1 += __shfl_xor_sync(0xffffffffu, s1, 2);

        l0 = l0 * c0 + s0;  l1 = l1 * c1 + s1;
        m0 = nm0;           m1 = nm1;

        #pragma unroll
        for (int nt = 0; nt < 8; nt++) {
            acc_o[nt][0] *= c0; acc_o[nt][1] *= c0;
            acc_o[nt][2] *= c1; acc_o[nt][3] *= c1;
        }

        // ---- write P (tf32) to smem; intra-warp only ----
        #pragma unroll
        for (int nt = 0; nt < 4; nt++) {
            int cbase = nt * 8 + 2 * thr;
            Ps[ qr      * 36 + cbase    ] = to_tf32(acc_s[nt][0]);
            Ps[ qr      * 36 + cbase + 1] = to_tf32(acc_s[nt][1]);
            Ps[(qr + 8) * 36 + cbase    ] = to_tf32(acc_s[nt][2]);
            Ps[(qr + 8) * 36 + cbase + 1] = to_tf32(acc_s[nt][3]);
        }
        __syncwarp();

        // ---- acc_o += P(16x32) @ V(32x64) ----
        #pragma unroll
        for (int ks2 = 0; ks2 < 4; ks2++) {
            float afrag[4];
            afrag[0] = Ps[ qr      * 36 + ks2 * 8 + thr    ];
            afrag[1] = Ps[(qr + 8) * 36 + ks2 * 8 + thr    ];
            afrag[2] = Ps[ qr      * 36 + ks2 * 8 + thr + 4];
            afrag[3] = Ps[(qr + 8) * 36 + ks2 * 8 + thr + 4];
            #pragma unroll
            for (int nt = 0; nt < 8; nt++) {
                float bfrag[2];
                int c = nt * 8 + grp;     // d index
                bfrag[0] = Vs[(ks2 * 8 + thr    ) * 72 + c];
                bfrag[1] = Vs[(ks2 * 8 + thr + 4) * 72 + c];
                mma_tf32_16x8x8(acc_o[nt], afrag, bfrag);
            }
        }
        __syncthreads();   // K/V reused next iteration
    }

    // ---- epilogue: out[token][h*64 + d] ----
    float il0 = 1.0f / l0, il1 = 1.0f / l1;
    int tok0 = b * SEQ + qt + wid * 16 + grp;
    #pragma unroll
    for (int nt = 0; nt < 8; nt++) {
        int col = h * DHEAD + nt * 8 + 2 * thr;
        *(float2*)(out + (size_t)tok0 * DMODEL + col) =
            make_float2(acc_o[nt][0] * il0, acc_o[nt][1] * il0);
        *(float2*)(out + (size_t)(tok0 + 8) * DMODEL + col) =
            make_float2(acc_o[nt][2] * il1, acc_o[nt][3] * il1);
    }
}

// ---------------- host orchestration ----------------
extern "C" void kernel_launch(void* const* d_in, const int* in_sizes, int n_in,
                              void* d_out, int out_size)
{
    const float* x     = (const float*)d_in[0];
    const float* ln1w  = (const float*)d_in[1];
    const float* ln1b  = (const float*)d_in[2];
    const float* wqkv  = (const float*)d_in[3];
    const float* wo    = (const float*)d_in[4];
    const float* bo    = (const float*)d_in[5];
    const float* ln2w  = (const float*)d_in[6];
    const float* ln2b  = (const float*)d_in[7];
    const float* w1    = (const float*)d_in[8];
    const float* b1    = (const float*)d_in[9];
    const float* w2    = (const float*)d_in[10];
    const float* b2    = (const float*)d_in[11];
    const float* lnfw  = (const float*)d_in[12];
    const float* lnfb  = (const float*)d_in[13];

    float *gx, *gh, *gqkv, *gao, *gff;
    cudaGetSymbolAddress((void**)&gx,   g_x);
    cudaGetSymbolAddress((void**)&gh,   g_h);
    cudaGetSymbolAddress((void**)&gqkv, g_qkv);
    cudaGetSymbolAddress((void**)&gao,  g_attnout);
    cudaGetSymbolAddress((void**)&gff,  g_ff);

    {
        int n4 = TOKENS * DMODEL / 4;
        copy4_kernel<<<(n4 + 255) / 256, 256>>>((const float4*)x, (float4*)gx, n4);
    }

    for (int l = 0; l < DEPTH; l++) {
        const float* L1w = ln1w + (size_t)l * DMODEL;
        const float* L1b = ln1b + (size_t)l * DMODEL;
        const float* Wq  = wqkv + (size_t)l * DMODEL * QKV3;
        const float* Wo  = wo   + (size_t)l * DMODEL * DMODEL;
        const float* Bo  = bo   + (size_t)l * DMODEL;
        const float* L2w = ln2w + (size_t)l * DMODEL;
        const float* L2b = ln2b + (size_t)l * DMODEL;
        const float* W1  = w1   + (size_t)l * DMODEL * DFF;
        const float* B1  = b1   + (size_t)l * DFF;
        const float* W2  = w2   + (size_t)l * DFF * DMODEL;
        const float* B2  = b2   + (size_t)l * DMODEL;

        ln_kernel<<<TOKENS, 256>>>(gx, L1w, L1b, gh);
        gemm_tc_kernel<0><<<dim3(QKV3 / 128, TOKENS / 128), 256>>>(gh, Wq, nullptr, nullptr, gqkv,
                                                                   TOKENS, QKV3, DMODEL);
        attn_tc_kernel<<<dim3(SEQ / 128, 8 * HEADS), 256>>>(gqkv, gao);
        gemm_tc_kernel<1><<<dim3(DMODEL / 128, TOKENS / 128), 256>>>(gao, Wo, Bo, gx, gx,
                                                                     TOKENS, DMODEL, DMODEL);
        ln_kernel<<<TOKENS, 256>>>(gx, L2w, L2b, gh);
        gemm_tc_kernel<2><<<dim3(DFF / 128, TOKENS / 128), 256>>>(gh, W1, B1, nullptr, gff,
                                                                  TOKENS, DFF, DMODEL);
        gemm_tc_kernel<1><<<dim3(DMODEL / 128, TOKENS / 128), 256>>>(gff, W2, B2, gx, gx,
                                                                     TOKENS, DMODEL, DFF);
    }

    ln_kernel<<<TOKENS, 256>>>(gx, lnfw, lnfb, (float*)d_out);
}

// round 6
// speedup vs baseline: 3.2045x; 1.0402x over previous
#include <cuda_runtime.h>
#include <math.h>

#define TOKENS 8192
#define DMODEL 768
#define HEADS  12
#define DHEAD  64
#define DFF    3072
#define DEPTH  12
#define SEQ    1024
#define QKV3   2304   // 3 * 768

// ---------------- scratch (allocation-free: __device__ globals) ----------------
__device__ float g_x[TOKENS * DMODEL];        // residual stream
__device__ float g_h[TOKENS * DMODEL];        // post-LN activations
__device__ float g_qkv[TOKENS * QKV3];        // fused qkv
__device__ float g_attnout[TOKENS * DMODEL];  // attention output
__device__ float g_ff[TOKENS * DFF];          // FF hidden

// ---------------- utility ----------------
__global__ void copy4_kernel(const float4* __restrict__ src, float4* __restrict__ dst, int n) {
    int i = blockIdx.x * blockDim.x + threadIdx.x;
    if (i < n) dst[i] = src[i];
}

__device__ __forceinline__ float to_tf32(float x) {
    float y;
    asm("cvt.rna.tf32.f32 %0, %1;" : "=f"(y) : "f"(x));
    return y;
}

__device__ __forceinline__ void mma_tf32_16x8x8(
    float* d, const float* a, const float* b)
{
    asm volatile(
        "mma.sync.aligned.m16n8k8.row.col.f32.tf32.tf32.f32 "
        "{%0,%1,%2,%3}, {%4,%5,%6,%7}, {%8,%9}, {%0,%1,%2,%3};\n"
        : "+f"(d[0]), "+f"(d[1]), "+f"(d[2]), "+f"(d[3])
        : "r"(__float_as_uint(a[0])), "r"(__float_as_uint(a[1])),
          "r"(__float_as_uint(a[2])), "r"(__float_as_uint(a[3])),
          "r"(__float_as_uint(b[0])), "r"(__float_as_uint(b[1])));
}

// ---------------- LayerNorm: warp per row, 8 rows per block ----------------
__global__ __launch_bounds__(256) void ln_kernel(
    const float* __restrict__ in, const float* __restrict__ w,
    const float* __restrict__ b, float* __restrict__ out)
{
    int warp = threadIdx.x >> 5, lane = threadIdx.x & 31;
    int row  = blockIdx.x * 8 + warp;
    const float4* p4 = (const float4*)(in + (size_t)row * DMODEL);

    float4 v[6];
    float sum = 0.f, sq = 0.f;
    #pragma unroll
    for (int i = 0; i < 6; i++) {
        v[i] = p4[lane + i * 32];
        sum += v[i].x + v[i].y + v[i].z + v[i].w;
        sq  += v[i].x * v[i].x + v[i].y * v[i].y + v[i].z * v[i].z + v[i].w * v[i].w;
    }
    #pragma unroll
    for (int o = 16; o > 0; o >>= 1) {
        sum += __shfl_xor_sync(0xffffffffu, sum, o);
        sq  += __shfl_xor_sync(0xffffffffu, sq,  o);
    }
    float mu  = sum * (1.0f / DMODEL);
    float var = sq * (1.0f / DMODEL) - mu * mu;
    float rs  = rsqrtf(var + 1e-5f);

    float4* q4 = (float4*)(out + (size_t)row * DMODEL);
    #pragma unroll
    for (int i = 0; i < 6; i++) {
        int c = (lane + i * 32) * 4;
        float4 wv = *(const float4*)(w + c);
        float4 bv = *(const float4*)(b + c);
        float4 r;
        r.x = (v[i].x - mu) * rs * wv.x + bv.x;
        r.y = (v[i].y - mu) * rs * wv.y + bv.y;
        r.z = (v[i].z - mu) * rs * wv.z + bv.z;
        r.w = (v[i].w - mu) * rs * wv.w + bv.w;
        q4[lane + i * 32] = r;
    }
}

// ---------------- tf32 tensor-core GEMM v2: C[M,N] = A[M,K] @ B[K,N] ----------------
// 128x128 block tile, 128 threads = 4 warps (2x2), warp tile 64x64 (4 m16 x 8 n8).
// BK=16, double-buffered smem, one sync per k-tile.
// EPI: 0 = none, 1 = +bias +residual, 2 = +bias then exact GELU
template <int EPI>
__global__ __launch_bounds__(128) void gemm_tc_kernel(
    const float* __restrict__ A, const float* __restrict__ B,
    const float* __restrict__ bias, const float* __restrict__ res,
    float* __restrict__ C, int M, int N, int K)
{
    __shared__ float As[2][128 * 20];   // [m][k], stride 20
    __shared__ float Bs[2][16 * 136];   // [k][n], stride 136

    int tid  = threadIdx.x;
    int lane = tid & 31;
    int wid  = tid >> 5;
    int wm = wid & 1, wn = wid >> 1;           // 2 x 2 warps
    int bm = blockIdx.y * 128, bn = blockIdx.x * 128;
    int grp = lane >> 2, thr = lane & 3;

    float acc[4][8][4];
    #pragma unroll
    for (int i = 0; i < 4; i++)
        #pragma unroll
        for (int j = 0; j < 8; j++)
            #pragma unroll
            for (int v = 0; v < 4; v++) acc[i][j][v] = 0.f;

    // staging indices: A 128x16 (4 float4/thread), B 16x128 (4 float4/thread)
    int a_r = tid >> 2,  a_c4 = (tid & 3) * 4;   // rows a_r + v*32
    int b_k = tid >> 5,  b_c4 = (tid & 31) * 4;  // k rows b_k + v*4

    float4 pa[4], pb[4];

    // ---- preload k0 = 0 ----
    #pragma unroll
    for (int v = 0; v < 4; v++) {
        pa[v] = *(const float4*)(A + (size_t)(bm + a_r + v * 32) * K + a_c4);
        pb[v] = *(const float4*)(B + (size_t)(b_k + v * 4) * N + bn + b_c4);
    }
    #pragma unroll
    for (int v = 0; v < 4; v++) {
        float* ar = &As[0][(a_r + v * 32) * 20 + a_c4];
        ar[0] = to_tf32(pa[v].x); ar[1] = to_tf32(pa[v].y);
        ar[2] = to_tf32(pa[v].z); ar[3] = to_tf32(pa[v].w);
        float* br = &Bs[0][(b_k + v * 4) * 136 + b_c4];
        br[0] = to_tf32(pb[v].x); br[1] = to_tf32(pb[v].y);
        br[2] = to_tf32(pb[v].z); br[3] = to_tf32(pb[v].w);
    }
    __syncthreads();

    int buf = 0;
    for (int k0 = 0; k0 < K; k0 += 16) {
        bool has_next = (k0 + 16) < K;
        if (has_next) {
            #pragma unroll
            for (int v = 0; v < 4; v++) {
                pa[v] = *(const float4*)(A + (size_t)(bm + a_r + v * 32) * K + k0 + 16 + a_c4);
                pb[v] = *(const float4*)(B + (size_t)(k0 + 16 + b_k + v * 4) * N + bn + b_c4);
            }
        }

        const float* Ab = As[buf];
        const float* Bb = Bs[buf];
        #pragma unroll
        for (int kk = 0; kk < 16; kk += 8) {
            float afrag[4][4];
            #pragma unroll
            for (int mt = 0; mt < 4; mt++) {
                int r = wm * 64 + mt * 16 + grp;
                afrag[mt][0] = Ab[ r      * 20 + kk + thr    ];
                afrag[mt][1] = Ab[(r + 8) * 20 + kk + thr    ];
                afrag[mt][2] = Ab[ r      * 20 + kk + thr + 4];
                afrag[mt][3] = Ab[(r + 8) * 20 + kk + thr + 4];
            }
            #pragma unroll
            for (int nt = 0; nt < 8; nt++) {
                float bfrag[2];
                int c = wn * 64 + nt * 8 + grp;
                bfrag[0] = Bb[(kk + thr    ) * 136 + c];
                bfrag[1] = Bb[(kk + thr + 4) * 136 + c];
                #pragma unroll
                for (int mt = 0; mt < 4; mt++)
                    mma_tf32_16x8x8(acc[mt][nt], afrag[mt], bfrag);
            }
        }

        if (has_next) {
            int nb = buf ^ 1;
            #pragma unroll
            for (int v = 0; v < 4; v++) {
                float* ar = &As[nb][(a_r + v * 32) * 20 + a_c4];
                ar[0] = to_tf32(pa[v].x); ar[1] = to_tf32(pa[v].y);
                ar[2] = to_tf32(pa[v].z); ar[3] = to_tf32(pa[v].w);
                float* br = &Bs[nb][(b_k + v * 4) * 136 + b_c4];
                br[0] = to_tf32(pb[v].x); br[1] = to_tf32(pb[v].y);
                br[2] = to_tf32(pb[v].z); br[3] = to_tf32(pb[v].w);
            }
            __syncthreads();
            buf = nb;
        }
    }

    // ---- epilogue ----
    #pragma unroll
    for (int mt = 0; mt < 4; mt++) {
        #pragma unroll
        for (int nt = 0; nt < 8; nt++) {
            int r0 = bm + wm * 64 + mt * 16 + grp;
            int c0 = bn + wn * 64 + nt * 8 + 2 * thr;
            #pragma unroll
            for (int half = 0; half < 2; half++) {
                int m = r0 + half * 8;
                float v0 = acc[mt][nt][half * 2 + 0];
                float v1 = acc[mt][nt][half * 2 + 1];
                if (EPI >= 1) { v0 += bias[c0]; v1 += bias[c0 + 1]; }
                if (EPI == 2) {
                    v0 = 0.5f * v0 * (1.0f + erff(v0 * 0.70710678118654752f));
                    v1 = 0.5f * v1 * (1.0f + erff(v1 * 0.70710678118654752f));
                }
                if (EPI == 1) {
                    const float* rr = res + (size_t)m * N + c0;
                    v0 += rr[0]; v1 += rr[1];
                }
                *(float2*)(C + (size_t)m * N + c0) = make_float2(v0, v1);
            }
        }
    }
}

// ---------------- Tensor-core flash attention (unchanged) ----------------
#define KS_OFF 0
#define VS_OFF 2176            // 32*68
#define PS_OFF (2176 + 2304)   // + 32*72
#define SM_TOT (PS_OFF + 128 * 36)   // 9088 floats = 36.4 KB

__global__ __launch_bounds__(256) void attn_tc_kernel(
    const float* __restrict__ qkv, float* __restrict__ out)
{
    __shared__ float sm[SM_TOT];
    float* Ks = sm + KS_OFF;   // [32][68]
    float* Vs = sm + VS_OFF;   // [32][72]
    float* Ps = sm + PS_OFF;   // [128][36]

    int tid = threadIdx.x;
    int lane = tid & 31, wid = tid >> 5;
    int grp = lane >> 2, thr = lane & 3;

    int bh = blockIdx.y;
    int b = bh / HEADS, h = bh % HEADS;
    int qt = blockIdx.x * 128;

    const float* qbase = qkv + (size_t)(b * SEQ) * QKV3 + h * DHEAD;
    const float* kbase = qbase + DMODEL;
    const float* vbase = qbase + 2 * DMODEL;

    #pragma unroll
    for (int v = 0; v < 8; v++) {
        int idx = tid + v * 256;
        int r = idx >> 4, c4 = (idx & 15) * 4;
        float4 q4 = *(const float4*)(qbase + (size_t)(qt + r) * QKV3 + c4);
        sm[r * 68 + c4 + 0] = to_tf32(0.125f * q4.x);
        sm[r * 68 + c4 + 1] = to_tf32(0.125f * q4.y);
        sm[r * 68 + c4 + 2] = to_tf32(0.125f * q4.z);
        sm[r * 68 + c4 + 3] = to_tf32(0.125f * q4.w);
    }
    __syncthreads();

    float qfrag[8][4];
    int qr = wid * 16 + grp;
    #pragma unroll
    for (int ks = 0; ks < 8; ks++) {
        qfrag[ks][0] = sm[ qr      * 68 + ks * 8 + thr    ];
        qfrag[ks][1] = sm[(qr + 8) * 68 + ks * 8 + thr    ];
        qfrag[ks][2] = sm[ qr      * 68 + ks * 8 + thr + 4];
        qfrag[ks][3] = sm[(qr + 8) * 68 + ks * 8 + thr + 4];
    }
    __syncthreads();

    float acc_o[8][4];
    #pragma unroll
    for (int nt = 0; nt < 8; nt++)
        #pragma unroll
        for (int v = 0; v < 4; v++) acc_o[nt][v] = 0.f;
    float m0 = -1e30f, m1 = -1e30f, l0 = 0.f, l1 = 0.f;

    for (int kt0 = 0; kt0 < SEQ; kt0 += 32) {
        #pragma unroll
        for (int v = 0; v < 2; v++) {
            int idx = tid + v * 256;
            int r = idx >> 4, c4 = (idx & 15) * 4;
            float4 k4 = *(const float4*)(kbase + (size_t)(kt0 + r) * QKV3 + c4);
            Ks[r * 68 + c4 + 0] = to_tf32(k4.x); Ks[r * 68 + c4 + 1] = to_tf32(k4.y);
            Ks[r * 68 + c4 + 2] = to_tf32(k4.z); Ks[r * 68 + c4 + 3] = to_tf32(k4.w);
            float4 v4 = *(const float4*)(vbase + (size_t)(kt0 + r) * QKV3 + c4);
            Vs[r * 72 + c4 + 0] = to_tf32(v4.x); Vs[r * 72 + c4 + 1] = to_tf32(v4.y);
            Vs[r * 72 + c4 + 2] = to_tf32(v4.z); Vs[r * 72 + c4 + 3] = to_tf32(v4.w);
        }
        __syncthreads();

        float acc_s[4][4];
        #pragma unroll
        for (int nt = 0; nt < 4; nt++)
            #pragma unroll
            for (int v = 0; v < 4; v++) acc_s[nt][v] = 0.f;

        #pragma unroll
        for (int ks = 0; ks < 8; ks++) {
            #pragma unroll
            for (int nt = 0; nt < 4; nt++) {
                float bfrag[2];
                int c = nt * 8 + grp;
                bfrag[0] = Ks[c * 68 + ks * 8 + thr    ];
                bfrag[1] = Ks[c * 68 + ks * 8 + thr + 4];
                mma_tf32_16x8x8(acc_s[nt], qfrag[ks], bfrag);
            }
        }

        float tm0 = -1e30f, tm1 = -1e30f;
        #pragma unroll
        for (int nt = 0; nt < 4; nt++) {
            tm0 = fmaxf(tm0, fmaxf(acc_s[nt][0], acc_s[nt][1]));
            tm1 = fmaxf(tm1, fmaxf(acc_s[nt][2], acc_s[nt][3]));
        }
        tm0 = fmaxf(tm0, __shfl_xor_sync(0xffffffffu, tm0, 1));
        tm0 = fmaxf(tm0, __shfl_xor_sync(0xffffffffu, tm0, 2));
        tm1 = fmaxf(tm1, __shfl_xor_sync(0xffffffffu, tm1, 1));
        tm1 = fmaxf(tm1, __shfl_xor_sync(0xffffffffu, tm1, 2));

        float nm0 = fmaxf(m0, tm0), nm1 = fmaxf(m1, tm1);
        float c0 = expf(m0 - nm0),  c1 = expf(m1 - nm1);

        float s0 = 0.f, s1 = 0.f;
        #pragma unroll
        for (int nt = 0; nt < 4; nt++) {
            acc_s[nt][0] = expf(acc_s[nt][0] - nm0);
            acc_s[nt][1] = expf(acc_s[nt][1] - nm0);
            acc_s[nt][2] = expf(acc_s[nt][2] - nm1);
            acc_s[nt][3] = expf(acc_s[nt][3] - nm1);
            s0 += acc_s[nt][0] + acc_s[nt][1];
            s1 += acc_s[nt][2] + acc_s[nt][3];
        }
        s0 += __shfl_xor_sync(0xffffffffu, s0, 1);
        s0 += __shfl_xor_sync(0xffffffffu, s0, 2);
        s1 += __shfl_xor_sync(0xffffffffu, s1, 1);
        s1 += __shfl_xor_sync(0xffffffffu, s1, 2);

        l0 = l0 * c0 + s0;  l1 = l1 * c1 + s1;
        m0 = nm0;           m1 = nm1;

        #pragma unroll
        for (int nt = 0; nt < 8; nt++) {
            acc_o[nt][0] *= c0; acc_o[nt][1] *= c0;
            acc_o[nt][2] *= c1; acc_o[nt][3] *= c1;
        }

        #pragma unroll
        for (int nt = 0; nt < 4; nt++) {
            int cbase = nt * 8 + 2 * thr;
            Ps[ qr      * 36 + cbase    ] = to_tf32(acc_s[nt][0]);
            Ps[ qr      * 36 + cbase + 1] = to_tf32(acc_s[nt][1]);
            Ps[(qr + 8) * 36 + cbase    ] = to_tf32(acc_s[nt][2]);
            Ps[(qr + 8) * 36 + cbase + 1] = to_tf32(acc_s[nt][3]);
        }
        __syncwarp();

        #pragma unroll
        for (int ks2 = 0; ks2 < 4; ks2++) {
            float afrag[4];
            afrag[0] = Ps[ qr      * 36 + ks2 * 8 + thr    ];
            afrag[1] = Ps[(qr + 8) * 36 + ks2 * 8 + thr    ];
            afrag[2] = Ps[ qr      * 36 + ks2 * 8 + thr + 4];
            afrag[3] = Ps[(qr + 8) * 36 + ks2 * 8 + thr + 4];
            #pragma unroll
            for (int nt = 0; nt < 8; nt++) {
                float bfrag[2];
                int c = nt * 8 + grp;
                bfrag[0] = Vs[(ks2 * 8 + thr    ) * 72 + c];
                bfrag[1] = Vs[(ks2 * 8 + thr + 4) * 72 + c];
                mma_tf32_16x8x8(acc_o[nt], afrag, bfrag);
            }
        }
        __syncthreads();
    }

    float il0 = 1.0f / l0, il1 = 1.0f / l1;
    int tok0 = b * SEQ + qt + wid * 16 + grp;
    #pragma unroll
    for (int nt = 0; nt < 8; nt++) {
        int col = h * DHEAD + nt * 8 + 2 * thr;
        *(float2*)(out + (size_t)tok0 * DMODEL + col) =
            make_float2(acc_o[nt][0] * il0, acc_o[nt][1] * il0);
        *(float2*)(out + (size_t)(tok0 + 8) * DMODEL + col) =
            make_float2(acc_o[nt][2] * il1, acc_o[nt][3] * il1);
    }
}

// ---------------- host orchestration ----------------
extern "C" void kernel_launch(void* const* d_in, const int* in_sizes, int n_in,
                              void* d_out, int out_size)
{
    const float* x     = (const float*)d_in[0];
    const float* ln1w  = (const float*)d_in[1];
    const float* ln1b  = (const float*)d_in[2];
    const float* wqkv  = (const float*)d_in[3];
    const float* wo    = (const float*)d_in[4];
    const float* bo    = (const float*)d_in[5];
    const float* ln2w  = (const float*)d_in[6];
    const float* ln2b  = (const float*)d_in[7];
    const float* w1    = (const float*)d_in[8];
    const float* b1    = (const float*)d_in[9];
    const float* w2    = (const float*)d_in[10];
    const float* b2    = (const float*)d_in[11];
    const float* lnfw  = (const float*)d_in[12];
    const float* lnfb  = (const float*)d_in[13];

    float *gx, *gh, *gqkv, *gao, *gff;
    cudaGetSymbolAddress((void**)&gx,   g_x);
    cudaGetSymbolAddress((void**)&gh,   g_h);
    cudaGetSymbolAddress((void**)&gqkv, g_qkv);
    cudaGetSymbolAddress((void**)&gao,  g_attnout);
    cudaGetSymbolAddress((void**)&gff,  g_ff);

    {
        int n4 = TOKENS * DMODEL / 4;
        copy4_kernel<<<(n4 + 255) / 256, 256>>>((const float4*)x, (float4*)gx, n4);
    }

    for (int l = 0; l < DEPTH; l++) {
        const float* L1w = ln1w + (size_t)l * DMODEL;
        const float* L1b = ln1b + (size_t)l * DMODEL;
        const float* Wq  = wqkv + (size_t)l * DMODEL * QKV3;
        const float* Wo  = wo   + (size_t)l * DMODEL * DMODEL;
        const float* Bo  = bo   + (size_t)l * DMODEL;
        const float* L2w = ln2w + (size_t)l * DMODEL;
        const float* L2b = ln2b + (size_t)l * DMODEL;
        const float* W1  = w1   + (size_t)l * DMODEL * DFF;
        const float* B1  = b1   + (size_t)l * DFF;
        const float* W2  = w2   + (size_t)l * DFF * DMODEL;
        const float* B2  = b2   + (size_t)l * DMODEL;

        ln_kernel<<<TOKENS / 8, 256>>>(gx, L1w, L1b, gh);
        gemm_tc_kernel<0><<<dim3(QKV3 / 128, TOKENS / 128), 128>>>(gh, Wq, nullptr, nullptr, gqkv,
                                                                   TOKENS, QKV3, DMODEL);
        attn_tc_kernel<<<dim3(SEQ / 128, 8 * HEADS), 256>>>(gqkv, gao);
        gemm_tc_kernel<1><<<dim3(DMODEL / 128, TOKENS / 128), 128>>>(gao, Wo, Bo, gx, gx,
                                                                     TOKENS, DMODEL, DMODEL);
        ln_kernel<<<TOKENS / 8, 256>>>(gx, L2w, L2b, gh);
        gemm_tc_kernel<2><<<dim3(DFF / 128, TOKENS / 128), 128>>>(gh, W1, B1, nullptr, gff,
                                                                  TOKENS, DFF, DMODEL);
        gemm_tc_kernel<1><<<dim3(DMODEL / 128, TOKENS / 128), 128>>>(gff, W2, B2, gx, gx,
                                                                     TOKENS, DMODEL, DFF);
    }

    ln_kernel<<<TOKENS / 8, 256>>>(gx, lnfw, lnfb, (float*)d_out);
}

// round 8
// speedup vs baseline: 3.2804x; 1.0237x over previous
#include <cuda_runtime.h>
#include <cuda_fp16.h>
#include <math.h>
#include <stdint.h>

#define TOKENS 8192
#define DMODEL 768
#define HEADS  12
#define DHEAD  64
#define DFF    3072
#define DEPTH  12
#define SEQ    1024
#define QKV3   2304   // 3 * 768

// ---------------- scratch (allocation-free: __device__ globals) ----------------
__device__ float g_x[TOKENS * DMODEL];
__device__ float g_h[TOKENS * DMODEL];
__device__ float g_qkv[TOKENS * QKV3];
__device__ float g_attnout[TOKENS * DMODEL];
__device__ float g_ff[TOKENS * DFF];

// pre-transposed fp16 weights: [layer][N][K]
__device__ __half g_wqkvT[DEPTH * QKV3 * DMODEL];
__device__ __half g_woT[DEPTH * DMODEL * DMODEL];
__device__ __half g_w1T[DEPTH * DFF * DMODEL];
__device__ __half g_w2T[DEPTH * DMODEL * DFF];

// ---------------- helpers ----------------
__device__ __forceinline__ float to_tf32(float x) {
    float y; asm("cvt.rna.tf32.f32 %0, %1;" : "=f"(y) : "f"(x)); return y;
}
__device__ __forceinline__ void mma_tf32_16x8x8(float* d, const float* a, const float* b) {
    asm volatile(
        "mma.sync.aligned.m16n8k8.row.col.f32.tf32.tf32.f32 "
        "{%0,%1,%2,%3}, {%4,%5,%6,%7}, {%8,%9}, {%0,%1,%2,%3};\n"
        : "+f"(d[0]), "+f"(d[1]), "+f"(d[2]), "+f"(d[3])
        : "r"(__float_as_uint(a[0])), "r"(__float_as_uint(a[1])),
          "r"(__float_as_uint(a[2])), "r"(__float_as_uint(a[3])),
          "r"(__float_as_uint(b[0])), "r"(__float_as_uint(b[1])));
}
__device__ __forceinline__ void mma_f16_16x8x16(float* d, const uint32_t* a,
                                                uint32_t b0, uint32_t b1) {
    asm volatile(
        "mma.sync.aligned.m16n8k16.row.col.f32.f16.f16.f32 "
        "{%0,%1,%2,%3}, {%4,%5,%6,%7}, {%8,%9}, {%0,%1,%2,%3};\n"
        : "+f"(d[0]), "+f"(d[1]), "+f"(d[2]), "+f"(d[3])
        : "r"(a[0]), "r"(a[1]), "r"(a[2]), "r"(a[3]), "r"(b0), "r"(b1));
}
__device__ __forceinline__ uint32_t packh2(float x, float y) {
    __half2 t = __floats2half2_rn(x, y);
    return *(uint32_t*)&t;
}

// ---------------- weight transpose: W[K][N] f32 -> WT[N][K] fp16 ----------------
__global__ __launch_bounds__(256) void wtrans_kernel(
    const float* __restrict__ W, __half* __restrict__ WT, int K, int N)
{
    __shared__ float T[32][33];
    int l = blockIdx.z;
    const float* Wl = W + (size_t)l * K * N;
    __half* Hl = WT + (size_t)l * K * N;
    int k0 = blockIdx.x * 32, n0 = blockIdx.y * 32;
    int tx = threadIdx.x & 31, ty = threadIdx.x >> 5;
    #pragma unroll
    for (int i = 0; i < 4; i++)
        T[ty + 8 * i][tx] = Wl[(size_t)(k0 + ty + 8 * i) * N + n0 + tx];
    __syncthreads();
    #pragma unroll
    for (int i = 0; i < 4; i++) {
        int n = n0 + ty + 8 * i, k = k0 + tx;
        Hl[(size_t)n * K + k] = __float2half(T[tx][ty + 8 * i]);
    }
}

// ---------------- fp16 mma GEMM: C[M,N] = A[M,K] @ B[K,N] ----------------
// A fp32 row-major; B pre-transposed fp16 [N][K]. Block 128x128, 4 warps (2x2),
// warp tile 64x64 (4 m16 x 8 n8), K chunk 32 (2 k16 steps), double-buffered.
// smem stride 40 halves (80B): banks (20r + thr) mod 32 all-distinct.
// EPI: 0 none, 1 +bias+residual, 2 +bias then exact GELU.
template <int EPI>
__global__ __launch_bounds__(128) void gemm_fp16_kernel(
    const float* __restrict__ A, const __half* __restrict__ BT,
    const float* __restrict__ bias, const float* __restrict__ res,
    float* __restrict__ C, int M, int N, int K)
{
    __shared__ __half As[2][128 * 40];
    __shared__ __half Bs[2][128 * 40];

    int tid  = threadIdx.x;
    int lane = tid & 31;
    int wid  = tid >> 5;
    int wm = wid & 1, wn = wid >> 1;
    int bm = blockIdx.y * 128, bn = blockIdx.x * 128;
    int grp = lane >> 2, thr = lane & 3;

    float acc[4][8][4];
    #pragma unroll
    for (int i = 0; i < 4; i++)
        #pragma unroll
        for (int j = 0; j < 8; j++)
            #pragma unroll
            for (int v = 0; v < 4; v++) acc[i][j][v] = 0.f;

    const float* aptr = A + (size_t)(bm + tid) * K;
    const __half* bptr = BT + (size_t)(bn + tid) * K;

    float4 fa[8];
    uint4  fb[4];

    // prefetch chunk 0
    #pragma unroll
    for (int v = 0; v < 8; v++) fa[v] = ((const float4*)aptr)[v];
    #pragma unroll
    for (int v = 0; v < 4; v++) fb[v] = ((const uint4*)bptr)[v];

    // store chunk 0 -> buffer 0
    {
        uint32_t hp[16];
        #pragma unroll
        for (int v = 0; v < 8; v++) {
            hp[2 * v]     = packh2(fa[v].x, fa[v].y);
            hp[2 * v + 1] = packh2(fa[v].z, fa[v].w);
        }
        uint4* ar = (uint4*)&As[0][tid * 40];
        ar[0] = make_uint4(hp[0], hp[1], hp[2], hp[3]);
        ar[1] = make_uint4(hp[4], hp[5], hp[6], hp[7]);
        ar[2] = make_uint4(hp[8], hp[9], hp[10], hp[11]);
        ar[3] = make_uint4(hp[12], hp[13], hp[14], hp[15]);
        uint4* br = (uint4*)&Bs[0][tid * 40];
        br[0] = fb[0]; br[1] = fb[1]; br[2] = fb[2]; br[3] = fb[3];
    }
    __syncthreads();

    int nchunk = K / 32;
    int buf = 0;
    for (int c = 0; c < nchunk; c++) {
        bool has_next = (c + 1) < nchunk;
        if (has_next) {
            int kc = (c + 1) * 32;
            #pragma unroll
            for (int v = 0; v < 8; v++) fa[v] = ((const float4*)(aptr + kc))[v];
            #pragma unroll
            for (int v = 0; v < 4; v++) fb[v] = ((const uint4*)(bptr + kc))[v];
        }

        const __half* Ab = As[buf];
        const __half* Bb = Bs[buf];
        #pragma unroll
        for (int s = 0; s < 2; s++) {
            int kb = s * 16;
            uint32_t af[4][4];
            #pragma unroll
            for (int mt = 0; mt < 4; mt++) {
                int r = wm * 64 + mt * 16 + grp;
                af[mt][0] = *(const uint32_t*)&Ab[ r      * 40 + kb + 2 * thr    ];
                af[mt][1] = *(const uint32_t*)&Ab[(r + 8) * 40 + kb + 2 * thr    ];
                af[mt][2] = *(const uint32_t*)&Ab[ r      * 40 + kb + 2 * thr + 8];
                af[mt][3] = *(const uint32_t*)&Ab[(r + 8) * 40 + kb + 2 * thr + 8];
            }
            #pragma unroll
            for (int nt = 0; nt < 8; nt++) {
                int c2 = wn * 64 + nt * 8 + grp;
                uint32_t b0 = *(const uint32_t*)&Bb[c2 * 40 + kb + 2 * thr    ];
                uint32_t b1 = *(const uint32_t*)&Bb[c2 * 40 + kb + 2 * thr + 8];
                #pragma unroll
                for (int mt = 0; mt < 4; mt++)
                    mma_f16_16x8x16(acc[mt][nt], af[mt], b0, b1);
            }
        }

        if (has_next) {
            int nb = buf ^ 1;
            uint32_t hp[16];
            #pragma unroll
            for (int v = 0; v < 8; v++) {
                hp[2 * v]     = packh2(fa[v].x, fa[v].y);
                hp[2 * v + 1] = packh2(fa[v].z, fa[v].w);
            }
            uint4* ar = (uint4*)&As[nb][tid * 40];
            ar[0] = make_uint4(hp[0], hp[1], hp[2], hp[3]);
            ar[1] = make_uint4(hp[4], hp[5], hp[6], hp[7]);
            ar[2] = make_uint4(hp[8], hp[9], hp[10], hp[11]);
            ar[3] = make_uint4(hp[12], hp[13], hp[14], hp[15]);
            uint4* br = (uint4*)&Bs[nb][tid * 40];
            br[0] = fb[0]; br[1] = fb[1]; br[2] = fb[2]; br[3] = fb[3];
            __syncthreads();
            buf = nb;
        }
    }

    // ---- epilogue (D layout identical to m16n8k8) ----
    #pragma unroll
    for (int mt = 0; mt < 4; mt++) {
        #pragma unroll
        for (int nt = 0; nt < 8; nt++) {
            int r0 = bm + wm * 64 + mt * 16 + grp;
            int c0 = bn + wn * 64 + nt * 8 + 2 * thr;
            #pragma unroll
            for (int half = 0; half < 2; half++) {
                int m = r0 + half * 8;
                float v0 = acc[mt][nt][half * 2 + 0];
                float v1 = acc[mt][nt][half * 2 + 1];
                if (EPI >= 1) { v0 += bias[c0]; v1 += bias[c0 + 1]; }
                if (EPI == 2) {
                    v0 = 0.5f * v0 * (1.0f + erff(v0 * 0.70710678118654752f));
                    v1 = 0.5f * v1 * (1.0f + erff(v1 * 0.70710678118654752f));
                }
                if (EPI == 1) {
                    const float* rr = res + (size_t)m * N + c0;
                    v0 += rr[0]; v1 += rr[1];
                }
                *(float2*)(C + (size_t)m * N + c0) = make_float2(v0, v1);
            }
        }
    }
}

// ---------------- utility ----------------
__global__ void copy4_kernel(const float4* __restrict__ src, float4* __restrict__ dst, int n) {
    int i = blockIdx.x * blockDim.x + threadIdx.x;
    if (i < n) dst[i] = src[i];
}

// ---------------- LayerNorm: warp per row ----------------
__global__ __launch_bounds__(256) void ln_kernel(
    const float* __restrict__ in, const float* __restrict__ w,
    const float* __restrict__ b, float* __restrict__ out)
{
    int warp = threadIdx.x >> 5, lane = threadIdx.x & 31;
    int row  = blockIdx.x * 8 + warp;
    const float4* p4 = (const float4*)(in + (size_t)row * DMODEL);

    float4 v[6];
    float sum = 0.f, sq = 0.f;
    #pragma unroll
    for (int i = 0; i < 6; i++) {
        v[i] = p4[lane + i * 32];
        sum += v[i].x + v[i].y + v[i].z + v[i].w;
        sq  += v[i].x * v[i].x + v[i].y * v[i].y + v[i].z * v[i].z + v[i].w * v[i].w;
    }
    #pragma unroll
    for (int o = 16; o > 0; o >>= 1) {
        sum += __shfl_xor_sync(0xffffffffu, sum, o);
        sq  += __shfl_xor_sync(0xffffffffu, sq,  o);
    }
    float mu  = sum * (1.0f / DMODEL);
    float var = sq * (1.0f / DMODEL) - mu * mu;
    float rs  = rsqrtf(var + 1e-5f);

    float4* q4 = (float4*)(out + (size_t)row * DMODEL);
    #pragma unroll
    for (int i = 0; i < 6; i++) {
        int c = (lane + i * 32) * 4;
        float4 wv = *(const float4*)(w + c);
        float4 bv = *(const float4*)(b + c);
        float4 r;
        r.x = (v[i].x - mu) * rs * wv.x + bv.x;
        r.y = (v[i].y - mu) * rs * wv.y + bv.y;
        r.z = (v[i].z - mu) * rs * wv.z + bv.z;
        r.w = (v[i].w - mu) * rs * wv.w + bv.w;
        q4[lane + i * 32] = r;
    }
}

// ---------------- Tensor-core flash attention (tf32 mma.sync, R6-passing) ----------------
#define KS_OFF 0
#define VS_OFF 2176
#define PS_OFF (2176 + 2304)
#define SM_TOT (PS_OFF + 128 * 36)

__global__ __launch_bounds__(256) void attn_tc_kernel(
    const float* __restrict__ qkv, float* __restrict__ out)
{
    __shared__ float sm[SM_TOT];
    float* Ks = sm + KS_OFF;
    float* Vs = sm + VS_OFF;
    float* Ps = sm + PS_OFF;

    int tid = threadIdx.x;
    int lane = tid & 31, wid = tid >> 5;
    int grp = lane >> 2, thr = lane & 3;

    int bh = blockIdx.y;
    int b = bh / HEADS, h = bh % HEADS;
    int qt = blockIdx.x * 128;

    const float* qbase = qkv + (size_t)(b * SEQ) * QKV3 + h * DHEAD;
    const float* kbase = qbase + DMODEL;
    const float* vbase = qbase + 2 * DMODEL;

    #pragma unroll
    for (int v = 0; v < 8; v++) {
        int idx = tid + v * 256;
        int r = idx >> 4, c4 = (idx & 15) * 4;
        float4 q4 = *(const float4*)(qbase + (size_t)(qt + r) * QKV3 + c4);
        sm[r * 68 + c4 + 0] = to_tf32(0.125f * q4.x);
        sm[r * 68 + c4 + 1] = to_tf32(0.125f * q4.y);
        sm[r * 68 + c4 + 2] = to_tf32(0.125f * q4.z);
        sm[r * 68 + c4 + 3] = to_tf32(0.125f * q4.w);
    }
    __syncthreads();

    float qfrag[8][4];
    int qr = wid * 16 + grp;
    #pragma unroll
    for (int ks = 0; ks < 8; ks++) {
        qfrag[ks][0] = sm[ qr      * 68 + ks * 8 + thr    ];
        qfrag[ks][1] = sm[(qr + 8) * 68 + ks * 8 + thr    ];
        qfrag[ks][2] = sm[ qr      * 68 + ks * 8 + thr + 4];
        qfrag[ks][3] = sm[(qr + 8) * 68 + ks * 8 + thr + 4];
    }
    __syncthreads();

    float acc_o[8][4];
    #pragma unroll
    for (int nt = 0; nt < 8; nt++)
        #pragma unroll
        for (int v = 0; v < 4; v++) acc_o[nt][v] = 0.f;
    float m0 = -1e30f, m1 = -1e30f, l0 = 0.f, l1 = 0.f;

    for (int kt0 = 0; kt0 < SEQ; kt0 += 32) {
        #pragma unroll
        for (int v = 0; v < 2; v++) {
            int idx = tid + v * 256;
            int r = idx >> 4, c4 = (idx & 15) * 4;
            float4 k4 = *(const float4*)(kbase + (size_t)(kt0 + r) * QKV3 + c4);
            Ks[r * 68 + c4 + 0] = to_tf32(k4.x); Ks[r * 68 + c4 + 1] = to_tf32(k4.y);
            Ks[r * 68 + c4 + 2] = to_tf32(k4.z); Ks[r * 68 + c4 + 3] = to_tf32(k4.w);
            float4 v4 = *(const float4*)(vbase + (size_t)(kt0 + r) * QKV3 + c4);
            Vs[r * 72 + c4 + 0] = to_tf32(v4.x); Vs[r * 72 + c4 + 1] = to_tf32(v4.y);
            Vs[r * 72 + c4 + 2] = to_tf32(v4.z); Vs[r * 72 + c4 + 3] = to_tf32(v4.w);
        }
        __syncthreads();

        float acc_s[4][4];
        #pragma unroll
        for (int nt = 0; nt < 4; nt++)
            #pragma unroll
            for (int v = 0; v < 4; v++) acc_s[nt][v] = 0.f;

        #pragma unroll
        for (int ks = 0; ks < 8; ks++) {
            #pragma unroll
            for (int nt = 0; nt < 4; nt++) {
                float bfrag[2];
                int c = nt * 8 + grp;
                bfrag[0] = Ks[c * 68 + ks * 8 + thr    ];
                bfrag[1] = Ks[c * 68 + ks * 8 + thr + 4];
                mma_tf32_16x8x8(acc_s[nt], qfrag[ks], bfrag);
            }
        }

        float tm0 = -1e30f, tm1 = -1e30f;
        #pragma unroll
        for (int nt = 0; nt < 4; nt++) {
            tm0 = fmaxf(tm0, fmaxf(acc_s[nt][0], acc_s[nt][1]));
            tm1 = fmaxf(tm1, fmaxf(acc_s[nt][2], acc_s[nt][3]));
        }
        tm0 = fmaxf(tm0, __shfl_xor_sync(0xffffffffu, tm0, 1));
        tm0 = fmaxf(tm0, __shfl_xor_sync(0xffffffffu, tm0, 2));
        tm1 = fmaxf(tm1, __shfl_xor_sync(0xffffffffu, tm1, 1));
        tm1 = fmaxf(tm1, __shfl_xor_sync(0xffffffffu, tm1, 2));

        float nm0 = fmaxf(m0, tm0), nm1 = fmaxf(m1, tm1);
        float c0 = expf(m0 - nm0),  c1 = expf(m1 - nm1);

        float s0 = 0.f, s1 = 0.f;
        #pragma unroll
        for (int nt = 0; nt < 4; nt++) {
            acc_s[nt][0] = expf(acc_s[nt][0] - nm0);
            acc_s[nt][1] = expf(acc_s[nt][1] - nm0);
            acc_s[nt][2] = expf(acc_s[nt][2] - nm1);
            acc_s[nt][3] = expf(acc_s[nt][3] - nm1);
            s0 += acc_s[nt][0] + acc_s[nt][1];
            s1 += acc_s[nt][2] + acc_s[nt][3];
        }
        s0 += __shfl_xor_sync(0xffffffffu, s0, 1);
        s0 += __shfl_xor_sync(0xffffffffu, s0, 2);
        s1 += __shfl_xor_sync(0xffffffffu, s1, 1);
        s1 += __shfl_xor_sync(0xffffffffu, s1, 2);

        l0 = l0 * c0 + s0;  l1 = l1 * c1 + s1;
        m0 = nm0;           m1 = nm1;

        #pragma unroll
        for (int nt = 0; nt < 8; nt++) {
            acc_o[nt][0] *= c0; acc_o[nt][1] *= c0;
            acc_o[nt][2] *= c1; acc_o[nt][3] *= c1;
        }

        #pragma unroll
        for (int nt = 0; nt < 4; nt++) {
            int cbase = nt * 8 + 2 * thr;
            Ps[ qr      * 36 + cbase    ] = to_tf32(acc_s[nt][0]);
            Ps[ qr      * 36 + cbase + 1] = to_tf32(acc_s[nt][1]);
            Ps[(qr + 8) * 36 + cbase    ] = to_tf32(acc_s[nt][2]);
            Ps[(qr + 8) * 36 + cbase + 1] = to_tf32(acc_s[nt][3]);
        }
        __syncwarp();

        #pragma unroll
        for (int ks2 = 0; ks2 < 4; ks2++) {
            float afrag[4];
            afrag[0] = Ps[ qr      * 36 + ks2 * 8 + thr    ];
            afrag[1] = Ps[(qr + 8) * 36 + ks2 * 8 + thr    ];
            afrag[2] = Ps[ qr      * 36 + ks2 * 8 + thr + 4];
            afrag[3] = Ps[(qr + 8) * 36 + ks2 * 8 + thr + 4];
            #pragma unroll
            for (int nt = 0; nt < 8; nt++) {
                float bfrag[2];
                int c = nt * 8 + grp;
                bfrag[0] = Vs[(ks2 * 8 + thr    ) * 72 + c];
                bfrag[1] = Vs[(ks2 * 8 + thr + 4) * 72 + c];
                mma_tf32_16x8x8(acc_o[nt], afrag, bfrag);
            }
        }
        __syncthreads();
    }

    float il0 = 1.0f / l0, il1 = 1.0f / l1;
    int tok0 = b * SEQ + qt + wid * 16 + grp;
    #pragma unroll
    for (int nt = 0; nt < 8; nt++) {
        int col = h * DHEAD + nt * 8 + 2 * thr;
        *(float2*)(out + (size_t)tok0 * DMODEL + col) =
            make_float2(acc_o[nt][0] * il0, acc_o[nt][1] * il0);
        *(float2*)(out + (size_t)(tok0 + 8) * DMODEL + col) =
            make_float2(acc_o[nt][2] * il1, acc_o[nt][3] * il1);
    }
}

// ---------------- host orchestration ----------------
extern "C" void kernel_launch(void* const* d_in, const int* in_sizes, int n_in,
                              void* d_out, int out_size)
{
    const float* x     = (const float*)d_in[0];
    const float* ln1w  = (const float*)d_in[1];
    const float* ln1b  = (const float*)d_in[2];
    const float* wqkv  = (const float*)d_in[3];
    const float* wo    = (const float*)d_in[4];
    const float* bo    = (const float*)d_in[5];
    const float* ln2w  = (const float*)d_in[6];
    const float* ln2b  = (const float*)d_in[7];
    const float* w1    = (const float*)d_in[8];
    const float* b1    = (const float*)d_in[9];
    const float* w2    = (const float*)d_in[10];
    const float* b2    = (const float*)d_in[11];
    const float* lnfw  = (const float*)d_in[12];
    const float* lnfb  = (const float*)d_in[13];

    float *gx, *gh, *gqkv, *gao, *gff;
    cudaGetSymbolAddress((void**)&gx,   g_x);
    cudaGetSymbolAddress((void**)&gh,   g_h);
    cudaGetSymbolAddress((void**)&gqkv, g_qkv);
    cudaGetSymbolAddress((void**)&gao,  g_attnout);
    cudaGetSymbolAddress((void**)&gff,  g_ff);

    __half *qkvT, *woT, *w1T, *w2T;
    cudaGetSymbolAddress((void**)&qkvT, g_wqkvT);
    cudaGetSymbolAddress((void**)&woT,  g_woT);
    cudaGetSymbolAddress((void**)&w1T,  g_w1T);
    cudaGetSymbolAddress((void**)&w2T,  g_w2T);

    // ---- weight transpose prepass ----
    wtrans_kernel<<<dim3(DMODEL / 32, QKV3 / 32, DEPTH), 256>>>(wqkv, qkvT, DMODEL, QKV3);
    wtrans_kernel<<<dim3(DMODEL / 32, DMODEL / 32, DEPTH), 256>>>(wo, woT, DMODEL, DMODEL);
    wtrans_kernel<<<dim3(DMODEL / 32, DFF / 32, DEPTH), 256>>>(w1, w1T, DMODEL, DFF);
    wtrans_kernel<<<dim3(DFF / 32, DMODEL / 32, DEPTH), 256>>>(w2, w2T, DFF, DMODEL);

    {
        int n4 = TOKENS * DMODEL / 4;
        copy4_kernel<<<(n4 + 255) / 256, 256>>>((const float4*)x, (float4*)gx, n4);
    }

    for (int l = 0; l < DEPTH; l++) {
        const float* L1w = ln1w + (size_t)l * DMODEL;
        const float* L1b = ln1b + (size_t)l * DMODEL;
        const float* Bo  = bo   + (size_t)l * DMODEL;
        const float* L2w = ln2w + (size_t)l * DMODEL;
        const float* L2b = ln2b + (size_t)l * DMODEL;
        const float* B1  = b1   + (size_t)l * DFF;
        const float* B2  = b2   + (size_t)l * DMODEL;

        const __half* Wq = qkvT + (size_t)l * QKV3 * DMODEL;
        const __half* Wo = woT  + (size_t)l * DMODEL * DMODEL;
        const __half* W1 = w1T  + (size_t)l * DFF * DMODEL;
        const __half* W2 = w2T  + (size_t)l * DMODEL * DFF;

        ln_kernel<<<TOKENS / 8, 256>>>(gx, L1w, L1b, gh);
        gemm_fp16_kernel<0><<<dim3(QKV3 / 128, TOKENS / 128), 128>>>(
            gh, Wq, nullptr, nullptr, gqkv, TOKENS, QKV3, DMODEL);
        attn_tc_kernel<<<dim3(SEQ / 128, 8 * HEADS), 256>>>(gqkv, gao);
        gemm_fp16_kernel<1><<<dim3(DMODEL / 128, TOKENS / 128), 128>>>(
            gao, Wo, Bo, gx, gx, TOKENS, DMODEL, DMODEL);
        ln_kernel<<<TOKENS / 8, 256>>>(gx, L2w, L2b, gh);
        gemm_fp16_kernel<2><<<dim3(DFF / 128, TOKENS / 128), 128>>>(
            gh, W1, B1, nullptr, gff, TOKENS, DFF, DMODEL);
        gemm_fp16_kernel<1><<<dim3(DMODEL / 128, TOKENS / 128), 128>>>(
            gff, W2, B2, gx, gx, TOKENS, DMODEL, DFF);
    }

    ln_kernel<<<TOKENS / 8, 256>>>(gx, lnfw, lnfb, (float*)d_out);
}

// round 9
// speedup vs baseline: 4.5741x; 1.3944x over previous
#include <cuda_runtime.h>
#include <cuda_fp16.h>
#include <math.h>
#include <stdint.h>

#define TOKENS 8192
#define DMODEL 768
#define HEADS  12
#define DHEAD  64
#define DFF    3072
#define DEPTH  12
#define SEQ    1024
#define QKV3   2304   // 3 * 768

// ---------------- scratch (allocation-free: __device__ globals) ----------------
__device__ float  g_x[TOKENS * DMODEL];          // residual stream (fp32)
__device__ __half g_h[TOKENS * DMODEL];          // post-LN activations (fp16)
__device__ __half g_qkv[TOKENS * QKV3];          // fused qkv (fp16)
__device__ __half g_attnout[TOKENS * DMODEL];    // attention output (fp16)
__device__ __half g_ff[TOKENS * DFF];            // FF hidden (fp16)

// pre-transposed fp16 weights: [layer][N][K]
__device__ __half g_wqkvT[DEPTH * QKV3 * DMODEL];
__device__ __half g_woT[DEPTH * DMODEL * DMODEL];
__device__ __half g_w1T[DEPTH * DFF * DMODEL];
__device__ __half g_w2T[DEPTH * DMODEL * DFF];

// ---------------- helpers ----------------
__device__ __forceinline__ uint32_t smem_u32(const void* p) {
    uint32_t a;
    asm("{ .reg .u64 t; cvta.to.shared.u64 t, %1; cvt.u32.u64 %0, t; }" : "=r"(a) : "l"(p));
    return a;
}
__device__ __forceinline__ void cp_async16(uint32_t dst, const void* src) {
    asm volatile("cp.async.cg.shared.global [%0], [%1], 16;" :: "r"(dst), "l"(src));
}
#define CP_COMMIT() asm volatile("cp.async.commit_group;" ::: "memory")
#define CP_WAIT1()  asm volatile("cp.async.wait_group 1;" ::: "memory")

__device__ __forceinline__ void mma_tf32_16x8x8(float* d, const float* a, const float* b) {
    asm volatile(
        "mma.sync.aligned.m16n8k8.row.col.f32.tf32.tf32.f32 "
        "{%0,%1,%2,%3}, {%4,%5,%6,%7}, {%8,%9}, {%0,%1,%2,%3};\n"
        : "+f"(d[0]), "+f"(d[1]), "+f"(d[2]), "+f"(d[3])
        : "r"(__float_as_uint(a[0])), "r"(__float_as_uint(a[1])),
          "r"(__float_as_uint(a[2])), "r"(__float_as_uint(a[3])),
          "r"(__float_as_uint(b[0])), "r"(__float_as_uint(b[1])));
}
__device__ __forceinline__ void mma_f16_16x8x16(float* d, const uint32_t* a,
                                                uint32_t b0, uint32_t b1) {
    asm volatile(
        "mma.sync.aligned.m16n8k16.row.col.f32.f16.f16.f32 "
        "{%0,%1,%2,%3}, {%4,%5,%6,%7}, {%8,%9}, {%0,%1,%2,%3};\n"
        : "+f"(d[0]), "+f"(d[1]), "+f"(d[2]), "+f"(d[3])
        : "r"(a[0]), "r"(a[1]), "r"(a[2]), "r"(a[3]), "r"(b0), "r"(b1));
}
__device__ __forceinline__ uint32_t packh2(float x, float y) {
    __half2 t = __floats2half2_rn(x, y);
    return *(uint32_t*)&t;
}

// ---------------- weight transpose: W[K][N] f32 -> WT[N][K] fp16 ----------------
__global__ __launch_bounds__(256) void wtrans_kernel(
    const float* __restrict__ W, __half* __restrict__ WT, int K, int N)
{
    __shared__ float T[32][33];
    int l = blockIdx.z;
    const float* Wl = W + (size_t)l * K * N;
    __half* Hl = WT + (size_t)l * K * N;
    int k0 = blockIdx.x * 32, n0 = blockIdx.y * 32;
    int tx = threadIdx.x & 31, ty = threadIdx.x >> 5;
    #pragma unroll
    for (int i = 0; i < 4; i++)
        T[ty + 8 * i][tx] = Wl[(size_t)(k0 + ty + 8 * i) * N + n0 + tx];
    __syncthreads();
    #pragma unroll
    for (int i = 0; i < 4; i++) {
        int n = n0 + ty + 8 * i, k = k0 + tx;
        Hl[(size_t)n * K + k] = __float2half(T[tx][ty + 8 * i]);
    }
}

// ---------------- cp.async pipelined fp16 GEMM: C[M,N] = A[M,K] @ B[K,N] ----------------
// A fp16 [M][K]; B fp16 [N][K]. 128x128 tile, BK=32, 2-stage cp.async pipeline,
// 256 threads = 8 warps (4m x 2n), warp tile 32x64. smem stride 40 halves.
// EPI: 0 none, 1 +bias+residual(fp32), 2 +bias + exact GELU. OUTH: 1 fp16 out, 0 fp32 out.
#define GK_STAGE_B 10240   // 128*40*2 bytes

template <int EPI, int OUTH>
__global__ __launch_bounds__(256) void gemm_fp16_kernel(
    const __half* __restrict__ A, const __half* __restrict__ BT,
    const float* __restrict__ bias, const float* __restrict__ res,
    void* __restrict__ Cout, int M, int N, int K)
{
    __shared__ __half As[2][128 * 40];
    __shared__ __half Bs[2][128 * 40];

    int tid  = threadIdx.x;
    int lane = tid & 31;
    int wid  = tid >> 5;
    int wm = wid & 3, wn = wid >> 2;           // 4 x 2 warps, warp tile 32x64
    int bm = blockIdx.y * 128, bn = blockIdx.x * 128;
    int grp = lane >> 2, thr = lane & 3;

    float acc[2][8][4];
    #pragma unroll
    for (int i = 0; i < 2; i++)
        #pragma unroll
        for (int j = 0; j < 8; j++)
            #pragma unroll
            for (int v = 0; v < 4; v++) acc[i][j][v] = 0.f;

    // cp.async mapping: thread -> row tid/2, 32B half-row (tid&1)
    int ar = tid >> 1;
    int ao = (tid & 1) * 32;                    // byte offset within row (2 granules)
    const __half* agp = A  + (size_t)(bm + ar) * K + (tid & 1) * 16;
    const __half* bgp = BT + (size_t)(bn + ar) * K + (tid & 1) * 16;
    uint32_t sA = smem_u32(As) + ar * 80 + ao;
    uint32_t sB = smem_u32(Bs) + ar * 80 + ao;

    int ktiles = K / 32;

    // prologue: stage 0 = tile 0
    {
        cp_async16(sA, agp);      cp_async16(sA + 16, agp + 8);
        cp_async16(sB, bgp);      cp_async16(sB + 16, bgp + 8);
        CP_COMMIT();
    }

    for (int c = 0; c < ktiles; c++) {
        // issue tile c+1 into stage (c+1)&1
        if (c + 1 < ktiles) {
            int s = (c + 1) & 1;
            const __half* ap = agp + (c + 1) * 32;
            const __half* bp = bgp + (c + 1) * 32;
            cp_async16(sA + s * GK_STAGE_B, ap);      cp_async16(sA + s * GK_STAGE_B + 16, ap + 8);
            cp_async16(sB + s * GK_STAGE_B, bp);      cp_async16(sB + s * GK_STAGE_B + 16, bp + 8);
        }
        CP_COMMIT();
        CP_WAIT1();            // tile c landed
        __syncthreads();

        const __half* Ab = As[c & 1];
        const __half* Bb = Bs[c & 1];
        #pragma unroll
        for (int s2 = 0; s2 < 2; s2++) {
            int kb = s2 * 16;
            uint32_t af[2][4];
            #pragma unroll
            for (int mt = 0; mt < 2; mt++) {
                int r = wm * 32 + mt * 16 + grp;
                af[mt][0] = *(const uint32_t*)&Ab[ r      * 40 + kb + 2 * thr    ];
                af[mt][1] = *(const uint32_t*)&Ab[(r + 8) * 40 + kb + 2 * thr    ];
                af[mt][2] = *(const uint32_t*)&Ab[ r      * 40 + kb + 2 * thr + 8];
                af[mt][3] = *(const uint32_t*)&Ab[(r + 8) * 40 + kb + 2 * thr + 8];
            }
            #pragma unroll
            for (int nt = 0; nt < 8; nt++) {
                int c2 = wn * 64 + nt * 8 + grp;
                uint32_t b0 = *(const uint32_t*)&Bb[c2 * 40 + kb + 2 * thr    ];
                uint32_t b1 = *(const uint32_t*)&Bb[c2 * 40 + kb + 2 * thr + 8];
                #pragma unroll
                for (int mt = 0; mt < 2; mt++)
                    mma_f16_16x8x16(acc[mt][nt], af[mt], b0, b1);
            }
        }
        __syncthreads();       // protect stage (c&1) before iter c+1 re-targets it
    }

    // ---- epilogue ----
    #pragma unroll
    for (int mt = 0; mt < 2; mt++) {
        #pragma unroll
        for (int nt = 0; nt < 8; nt++) {
            int r0 = bm + wm * 32 + mt * 16 + grp;
            int c0 = bn + wn * 64 + nt * 8 + 2 * thr;
            #pragma unroll
            for (int hh = 0; hh < 2; hh++) {
                int m = r0 + hh * 8;
                float v0 = acc[mt][nt][hh * 2 + 0];
                float v1 = acc[mt][nt][hh * 2 + 1];
                if (EPI >= 1) { v0 += bias[c0]; v1 += bias[c0 + 1]; }
                if (EPI == 2) {
                    v0 = 0.5f * v0 * (1.0f + erff(v0 * 0.70710678118654752f));
                    v1 = 0.5f * v1 * (1.0f + erff(v1 * 0.70710678118654752f));
                }
                if (EPI == 1) {
                    const float* rr = res + (size_t)m * N + c0;
                    v0 += rr[0]; v1 += rr[1];
                }
                if (OUTH) {
                    *(uint32_t*)((__half*)Cout + (size_t)m * N + c0) = packh2(v0, v1);
                } else {
                    *(float2*)((float*)Cout + (size_t)m * N + c0) = make_float2(v0, v1);
                }
            }
        }
    }
}

// ---------------- utility ----------------
__global__ void copy4_kernel(const float4* __restrict__ src, float4* __restrict__ dst, int n) {
    int i = blockIdx.x * blockDim.x + threadIdx.x;
    if (i < n) dst[i] = src[i];
}

// ---------------- LayerNorm: warp per row; OUTH: fp16 or fp32 output ----------------
template <int OUTH>
__global__ __launch_bounds__(256) void ln_kernel(
    const float* __restrict__ in, const float* __restrict__ w,
    const float* __restrict__ b, void* __restrict__ out)
{
    int warp = threadIdx.x >> 5, lane = threadIdx.x & 31;
    int row  = blockIdx.x * 8 + warp;
    const float4* p4 = (const float4*)(in + (size_t)row * DMODEL);

    float4 v[6];
    float sum = 0.f, sq = 0.f;
    #pragma unroll
    for (int i = 0; i < 6; i++) {
        v[i] = p4[lane + i * 32];
        sum += v[i].x + v[i].y + v[i].z + v[i].w;
        sq  += v[i].x * v[i].x + v[i].y * v[i].y + v[i].z * v[i].z + v[i].w * v[i].w;
    }
    #pragma unroll
    for (int o = 16; o > 0; o >>= 1) {
        sum += __shfl_xor_sync(0xffffffffu, sum, o);
        sq  += __shfl_xor_sync(0xffffffffu, sq,  o);
    }
    float mu  = sum * (1.0f / DMODEL);
    float var = sq * (1.0f / DMODEL) - mu * mu;
    float rs  = rsqrtf(var + 1e-5f);

    #pragma unroll
    for (int i = 0; i < 6; i++) {
        int c = (lane + i * 32) * 4;
        float4 wv = *(const float4*)(w + c);
        float4 bv = *(const float4*)(b + c);
        float4 r;
        r.x = (v[i].x - mu) * rs * wv.x + bv.x;
        r.y = (v[i].y - mu) * rs * wv.y + bv.y;
        r.z = (v[i].z - mu) * rs * wv.z + bv.z;
        r.w = (v[i].w - mu) * rs * wv.w + bv.w;
        if (OUTH) {
            uint2 pk = make_uint2(packh2(r.x, r.y), packh2(r.z, r.w));
            ((uint2*)((__half*)out + (size_t)row * DMODEL))[lane + i * 32] = pk;
        } else {
            ((float4*)((float*)out + (size_t)row * DMODEL))[lane + i * 32] = r;
        }
    }
}

// ---------------- Tensor-core flash attention (tf32 mma, fp16 I/O) ----------------
#define KS_OFF 0
#define VS_OFF 2176
#define PS_OFF (2176 + 2304)
#define SM_TOT (PS_OFF + 128 * 36)

__global__ __launch_bounds__(256) void attn_tc_kernel(
    const __half* __restrict__ qkv, __half* __restrict__ out)
{
    __shared__ float sm[SM_TOT];
    float* Ks = sm + KS_OFF;
    float* Vs = sm + VS_OFF;
    float* Ps = sm + PS_OFF;

    int tid = threadIdx.x;
    int lane = tid & 31, wid = tid >> 5;
    int grp = lane >> 2, thr = lane & 3;

    int bh = blockIdx.y;
    int b = bh / HEADS, h = bh % HEADS;
    int qt = blockIdx.x * 128;

    const __half* qbase = qkv + (size_t)(b * SEQ) * QKV3 + h * DHEAD;
    const __half* kbase = qbase + DMODEL;
    const __half* vbase = qbase + 2 * DMODEL;

    // Q tile 128x64: 1024 uint4 (8 halves each), pre-scaled by 0.125
    #pragma unroll
    for (int v = 0; v < 4; v++) {
        int idx = tid + v * 256;
        int r = idx >> 3, c8 = (idx & 7) * 8;
        uint4 q4 = *(const uint4*)(qbase + (size_t)(qt + r) * QKV3 + c8);
        const __half2* hp = (const __half2*)&q4;
        #pragma unroll
        for (int j = 0; j < 4; j++) {
            float2 f = __half22float2(hp[j]);
            sm[r * 68 + c8 + 2 * j + 0] = 0.125f * f.x;
            sm[r * 68 + c8 + 2 * j + 1] = 0.125f * f.y;
        }
    }
    __syncthreads();

    float qfrag[8][4];
    int qr = wid * 16 + grp;
    #pragma unroll
    for (int ks = 0; ks < 8; ks++) {
        qfrag[ks][0] = sm[ qr      * 68 + ks * 8 + thr    ];
        qfrag[ks][1] = sm[(qr + 8) * 68 + ks * 8 + thr    ];
        qfrag[ks][2] = sm[ qr      * 68 + ks * 8 + thr + 4];
        qfrag[ks][3] = sm[(qr + 8) * 68 + ks * 8 + thr + 4];
    }
    __syncthreads();

    float acc_o[8][4];
    #pragma unroll
    for (int nt = 0; nt < 8; nt++)
        #pragma unroll
        for (int v = 0; v < 4; v++) acc_o[nt][v] = 0.f;
    float m0 = -1e30f, m1 = -1e30f, l0 = 0.f, l1 = 0.f;

    for (int kt0 = 0; kt0 < SEQ; kt0 += 32) {
        // K,V tiles 32x64 fp16 -> fp32 smem (256 uint4 each; 1 per thread)
        {
            int r = tid >> 3, c8 = (tid & 7) * 8;
            uint4 k4 = *(const uint4*)(kbase + (size_t)(kt0 + r) * QKV3 + c8);
            const __half2* kp = (const __half2*)&k4;
            uint4 v4 = *(const uint4*)(vbase + (size_t)(kt0 + r) * QKV3 + c8);
            const __half2* vp = (const __half2*)&v4;
            #pragma unroll
            for (int j = 0; j < 4; j++) {
                float2 fk = __half22float2(kp[j]);
                Ks[r * 68 + c8 + 2 * j + 0] = fk.x;
                Ks[r * 68 + c8 + 2 * j + 1] = fk.y;
                float2 fv = __half22float2(vp[j]);
                Vs[r * 72 + c8 + 2 * j + 0] = fv.x;
                Vs[r * 72 + c8 + 2 * j + 1] = fv.y;
            }
        }
        __syncthreads();

        float acc_s[4][4];
        #pragma unroll
        for (int nt = 0; nt < 4; nt++)
            #pragma unroll
            for (int v = 0; v < 4; v++) acc_s[nt][v] = 0.f;

        #pragma unroll
        for (int ks = 0; ks < 8; ks++) {
            #pragma unroll
            for (int nt = 0; nt < 4; nt++) {
                float bfrag[2];
                int c = nt * 8 + grp;
                bfrag[0] = Ks[c * 68 + ks * 8 + thr    ];
                bfrag[1] = Ks[c * 68 + ks * 8 + thr + 4];
                mma_tf32_16x8x8(acc_s[nt], qfrag[ks], bfrag);
            }
        }

        float tm0 = -1e30f, tm1 = -1e30f;
        #pragma unroll
        for (int nt = 0; nt < 4; nt++) {
            tm0 = fmaxf(tm0, fmaxf(acc_s[nt][0], acc_s[nt][1]));
            tm1 = fmaxf(tm1, fmaxf(acc_s[nt][2], acc_s[nt][3]));
        }
        tm0 = fmaxf(tm0, __shfl_xor_sync(0xffffffffu, tm0, 1));
        tm0 = fmaxf(tm0, __shfl_xor_sync(0xffffffffu, tm0, 2));
        tm1 = fmaxf(tm1, __shfl_xor_sync(0xffffffffu, tm1, 1));
        tm1 = fmaxf(tm1, __shfl_xor_sync(0xffffffffu, tm1, 2));

        float nm0 = fmaxf(m0, tm0), nm1 = fmaxf(m1, tm1);
        float c0 = expf(m0 - nm0),  c1 = expf(m1 - nm1);

        float s0 = 0.f, s1 = 0.f;
        #pragma unroll
        for (int nt = 0; nt < 4; nt++) {
            acc_s[nt][0] = expf(acc_s[nt][0] - nm0);
            acc_s[nt][1] = expf(acc_s[nt][1] - nm0);
            acc_s[nt][2] = expf(acc_s[nt][2] - nm1);
            acc_s[nt][3] = expf(acc_s[nt][3] - nm1);
            s0 += acc_s[nt][0] + acc_s[nt][1];
            s1 += acc_s[nt][2] + acc_s[nt][3];
        }
        s0 += __shfl_xor_sync(0xffffffffu, s0, 1);
        s0 += __shfl_xor_sync(0xffffffffu, s0, 2);
        s1 += __shfl_xor_sync(0xffffffffu, s1, 1);
        s1 += __shfl_xor_sync(0xffffffffu, s1, 2);

        l0 = l0 * c0 + s0;  l1 = l1 * c1 + s1;
        m0 = nm0;           m1 = nm1;

        #pragma unroll
        for (int nt = 0; nt < 8; nt++) {
            acc_o[nt][0] *= c0; acc_o[nt][1] *= c0;
            acc_o[nt][2] *= c1; acc_o[nt][3] *= c1;
        }

        #pragma unroll
        for (int nt = 0; nt < 4; nt++) {
            int cbase = nt * 8 + 2 * thr;
            Ps[ qr      * 36 + cbase    ] = acc_s[nt][0];
            Ps[ qr      * 36 + cbase + 1] = acc_s[nt][1];
            Ps[(qr + 8) * 36 + cbase    ] = acc_s[nt][2];
            Ps[(qr + 8) * 36 + cbase + 1] = acc_s[nt][3];
        }
        __syncwarp();

        #pragma unroll
        for (int ks2 = 0; ks2 < 4; ks2++) {
            float afrag[4];
            afrag[0] = Ps[ qr      * 36 + ks2 * 8 + thr    ];
            afrag[1] = Ps[(qr + 8) * 36 + ks2 * 8 + thr    ];
            afrag[2] = Ps[ qr      * 36 + ks2 * 8 + thr + 4];
            afrag[3] = Ps[(qr + 8) * 36 + ks2 * 8 + thr + 4];
            #pragma unroll
            for (int nt = 0; nt < 8; nt++) {
                float bfrag[2];
                int c = nt * 8 + grp;
                bfrag[0] = Vs[(ks2 * 8 + thr    ) * 72 + c];
                bfrag[1] = Vs[(ks2 * 8 + thr + 4) * 72 + c];
                mma_tf32_16x8x8(acc_o[nt], afrag, bfrag);
            }
        }
        __syncthreads();
    }

    float il0 = 1.0f / l0, il1 = 1.0f / l1;
    int tok0 = b * SEQ + qt + wid * 16 + grp;
    #pragma unroll
    for (int nt = 0; nt < 8; nt++) {
        int col = h * DHEAD + nt * 8 + 2 * thr;
        *(uint32_t*)(out + (size_t)tok0 * DMODEL + col) =
            packh2(acc_o[nt][0] * il0, acc_o[nt][1] * il0);
        *(uint32_t*)(out + (size_t)(tok0 + 8) * DMODEL + col) =
            packh2(acc_o[nt][2] * il1, acc_o[nt][3] * il1);
    }
}

// ---------------- host orchestration ----------------
extern "C" void kernel_launch(void* const* d_in, const int* in_sizes, int n_in,
                              void* d_out, int out_size)
{
    const float* x     = (const float*)d_in[0];
    const float* ln1w  = (const float*)d_in[1];
    const float* ln1b  = (const float*)d_in[2];
    const float* wqkv  = (const float*)d_in[3];
    const float* wo    = (const float*)d_in[4];
    const float* bo    = (const float*)d_in[5];
    const float* ln2w  = (const float*)d_in[6];
    const float* ln2b  = (const float*)d_in[7];
    const float* w1    = (const float*)d_in[8];
    const float* b1    = (const float*)d_in[9];
    const float* w2    = (const float*)d_in[10];
    const float* b2    = (const float*)d_in[11];
    const float* lnfw  = (const float*)d_in[12];
    const float* lnfb  = (const float*)d_in[13];

    float *gx;
    __half *gh, *gqkv, *gao, *gff;
    cudaGetSymbolAddress((void**)&gx,   g_x);
    cudaGetSymbolAddress((void**)&gh,   g_h);
    cudaGetSymbolAddress((void**)&gqkv, g_qkv);
    cudaGetSymbolAddress((void**)&gao,  g_attnout);
    cudaGetSymbolAddress((void**)&gff,  g_ff);

    __half *qkvT, *woT, *w1T, *w2T;
    cudaGetSymbolAddress((void**)&qkvT, g_wqkvT);
    cudaGetSymbolAddress((void**)&woT,  g_woT);
    cudaGetSymbolAddress((void**)&w1T,  g_w1T);
    cudaGetSymbolAddress((void**)&w2T,  g_w2T);

    // ---- weight transpose prepass ----
    wtrans_kernel<<<dim3(DMODEL / 32, QKV3 / 32, DEPTH), 256>>>(wqkv, qkvT, DMODEL, QKV3);
    wtrans_kernel<<<dim3(DMODEL / 32, DMODEL / 32, DEPTH), 256>>>(wo, woT, DMODEL, DMODEL);
    wtrans_kernel<<<dim3(DMODEL / 32, DFF / 32, DEPTH), 256>>>(w1, w1T, DMODEL, DFF);
    wtrans_kernel<<<dim3(DFF / 32, DMODEL / 32, DEPTH), 256>>>(w2, w2T, DFF, DMODEL);

    {
        int n4 = TOKENS * DMODEL / 4;
        copy4_kernel<<<(n4 + 255) / 256, 256>>>((const float4*)x, (float4*)gx, n4);
    }

    for (int l = 0; l < DEPTH; l++) {
        const float* L1w = ln1w + (size_t)l * DMODEL;
        const float* L1b = ln1b + (size_t)l * DMODEL;
        const float* Bo  = bo   + (size_t)l * DMODEL;
        const float* L2w = ln2w + (size_t)l * DMODEL;
        const float* L2b = ln2b + (size_t)l * DMODEL;
        const float* B1  = b1   + (size_t)l * DFF;
        const float* B2  = b2   + (size_t)l * DMODEL;

        const __half* Wq = qkvT + (size_t)l * QKV3 * DMODEL;
        const __half* Wo = woT  + (size_t)l * DMODEL * DMODEL;
        const __half* W1 = w1T  + (size_t)l * DFF * DMODEL;
        const __half* W2 = w2T  + (size_t)l * DMODEL * DFF;

        ln_kernel<1><<<TOKENS / 8, 256>>>(gx, L1w, L1b, gh);
        gemm_fp16_kernel<0, 1><<<dim3(QKV3 / 128, TOKENS / 128), 256>>>(
            gh, Wq, nullptr, nullptr, gqkv, TOKENS, QKV3, DMODEL);
        attn_tc_kernel<<<dim3(SEQ / 128, 8 * HEADS), 256>>>(gqkv, gao);
        gemm_fp16_kernel<1, 0><<<dim3(DMODEL / 128, TOKENS / 128), 256>>>(
            gao, Wo, Bo, gx, gx, TOKENS, DMODEL, DMODEL);
        ln_kernel<1><<<TOKENS / 8, 256>>>(gx, L2w, L2b, gh);
        gemm_fp16_kernel<2, 1><<<dim3(DFF / 128, TOKENS / 128), 256>>>(
            gh, W1, B1, nullptr, gff, TOKENS, DFF, DMODEL);
        gemm_fp16_kernel<1, 0><<<dim3(DMODEL / 128, TOKENS / 128), 256>>>(
            gff, W2, B2, gx, gx, TOKENS, DMODEL, DFF);
    }

    ln_kernel<0><<<TOKENS / 8, 256>>>(gx, lnfw, lnfb, (float*)d_out);
}

// round 12
// speedup vs baseline: 4.9904x; 1.0910x over previous
#include <cuda_runtime.h>
#include <cuda_fp16.h>
#include <math.h>
#include <stdint.h>

#define TOKENS 8192
#define DMODEL 768
#define HEADS  12
#define DHEAD  64
#define DFF    3072
#define DEPTH  12
#define SEQ    1024
#define QKV3   2304   // 3 * 768

// ---------------- scratch (allocation-free: __device__ globals) ----------------
__device__ float  g_x[TOKENS * DMODEL];          // residual stream (fp32)
__device__ __half g_h[TOKENS * DMODEL];          // post-LN activations (fp16)
__device__ __half g_qkv[TOKENS * QKV3];          // fused qkv (fp16)
__device__ __half g_attnout[TOKENS * DMODEL];    // attention output (fp16)
__device__ __half g_ff[TOKENS * DFF];            // FF hidden (fp16)

// pre-transposed fp16 weights: [layer][N][K]
__device__ __half g_wqkvT[DEPTH * QKV3 * DMODEL];
__device__ __half g_woT[DEPTH * DMODEL * DMODEL];
__device__ __half g_w1T[DEPTH * DFF * DMODEL];
__device__ __half g_w2T[DEPTH * DMODEL * DFF];

// ---------------- helpers ----------------
__device__ __forceinline__ uint32_t smem_u32(const void* p) {
    uint32_t a;
    asm("{ .reg .u64 t; cvta.to.shared.u64 t, %1; cvt.u32.u64 %0, t; }" : "=r"(a) : "l"(p));
    return a;
}
__device__ __forceinline__ void cp_async16(uint32_t dst, const void* src) {
    asm volatile("cp.async.cg.shared.global [%0], [%1], 16;" :: "r"(dst), "l"(src));
}
#define CP_COMMIT() asm volatile("cp.async.commit_group;" ::: "memory")
#define CP_WAIT1()  asm volatile("cp.async.wait_group 1;" ::: "memory")

__device__ __forceinline__ void mma_f16_16x8x16(float* d, const uint32_t* a,
                                                uint32_t b0, uint32_t b1) {
    asm volatile(
        "mma.sync.aligned.m16n8k16.row.col.f32.f16.f16.f32 "
        "{%0,%1,%2,%3}, {%4,%5,%6,%7}, {%8,%9}, {%0,%1,%2,%3};\n"
        : "+f"(d[0]), "+f"(d[1]), "+f"(d[2]), "+f"(d[3])
        : "r"(a[0]), "r"(a[1]), "r"(a[2]), "r"(a[3]), "r"(b0), "r"(b1));
}
__device__ __forceinline__ uint32_t packh2(float x, float y) {
    __half2 t = __floats2half2_rn(x, y);
    return *(uint32_t*)&t;
}

// ---------------- weight transpose: W[K][N] f32 -> WT[N][K] fp16 ----------------
__global__ __launch_bounds__(256) void wtrans_kernel(
    const float* __restrict__ W, __half* __restrict__ WT, int K, int N)
{
    __shared__ float T[32][33];
    int l = blockIdx.z;
    const float* Wl = W + (size_t)l * K * N;
    __half* Hl = WT + (size_t)l * K * N;
    int k0 = blockIdx.x * 32, n0 = blockIdx.y * 32;
    int tx = threadIdx.x & 31, ty = threadIdx.x >> 5;
    #pragma unroll
    for (int i = 0; i < 4; i++)
        T[ty + 8 * i][tx] = Wl[(size_t)(k0 + ty + 8 * i) * N + n0 + tx];
    __syncthreads();
    #pragma unroll
    for (int i = 0; i < 4; i++) {
        int n = n0 + ty + 8 * i, k = k0 + tx;
        Hl[(size_t)n * K + k] = __float2half(T[tx][ty + 8 * i]);
    }
}

// ---------------- cp.async pipelined fp16 GEMM (validated in R9) ----------------
#define GK_STAGE_B 10240   // 128*40*2 bytes

template <int EPI, int OUTH>
__global__ __launch_bounds__(256) void gemm_fp16_kernel(
    const __half* __restrict__ A, const __half* __restrict__ BT,
    const float* __restrict__ bias, const float* __restrict__ res,
    void* __restrict__ Cout, int M, int N, int K)
{
    __shared__ __half As[2][128 * 40];
    __shared__ __half Bs[2][128 * 40];

    int tid  = threadIdx.x;
    int lane = tid & 31;
    int wid  = tid >> 5;
    int wm = wid & 3, wn = wid >> 2;
    int bm = blockIdx.y * 128, bn = blockIdx.x * 128;
    int grp = lane >> 2, thr = lane & 3;

    float acc[2][8][4];
    #pragma unroll
    for (int i = 0; i < 2; i++)
        #pragma unroll
        for (int j = 0; j < 8; j++)
            #pragma unroll
            for (int v = 0; v < 4; v++) acc[i][j][v] = 0.f;

    int ar = tid >> 1;
    int ao = (tid & 1) * 32;
    const __half* agp = A  + (size_t)(bm + ar) * K + (tid & 1) * 16;
    const __half* bgp = BT + (size_t)(bn + ar) * K + (tid & 1) * 16;
    uint32_t sA = smem_u32(As) + ar * 80 + ao;
    uint32_t sB = smem_u32(Bs) + ar * 80 + ao;

    int ktiles = K / 32;
    {
        cp_async16(sA, agp);      cp_async16(sA + 16, agp + 8);
        cp_async16(sB, bgp);      cp_async16(sB + 16, bgp + 8);
        CP_COMMIT();
    }

    for (int c = 0; c < ktiles; c++) {
        if (c + 1 < ktiles) {
            int s = (c + 1) & 1;
            const __half* ap = agp + (c + 1) * 32;
            const __half* bp = bgp + (c + 1) * 32;
            cp_async16(sA + s * GK_STAGE_B, ap);      cp_async16(sA + s * GK_STAGE_B + 16, ap + 8);
            cp_async16(sB + s * GK_STAGE_B, bp);      cp_async16(sB + s * GK_STAGE_B + 16, bp + 8);
        }
        CP_COMMIT();
        CP_WAIT1();
        __syncthreads();

        const __half* Ab = As[c & 1];
        const __half* Bb = Bs[c & 1];
        #pragma unroll
        for (int s2 = 0; s2 < 2; s2++) {
            int kb = s2 * 16;
            uint32_t af[2][4];
            #pragma unroll
            for (int mt = 0; mt < 2; mt++) {
                int r = wm * 32 + mt * 16 + grp;
                af[mt][0] = *(const uint32_t*)&Ab[ r      * 40 + kb + 2 * thr    ];
                af[mt][1] = *(const uint32_t*)&Ab[(r + 8) * 40 + kb + 2 * thr    ];
                af[mt][2] = *(const uint32_t*)&Ab[ r      * 40 + kb + 2 * thr + 8];
                af[mt][3] = *(const uint32_t*)&Ab[(r + 8) * 40 + kb + 2 * thr + 8];
            }
            #pragma unroll
            for (int nt = 0; nt < 8; nt++) {
                int c2 = wn * 64 + nt * 8 + grp;
                uint32_t b0 = *(const uint32_t*)&Bb[c2 * 40 + kb + 2 * thr    ];
                uint32_t b1 = *(const uint32_t*)&Bb[c2 * 40 + kb + 2 * thr + 8];
                #pragma unroll
                for (int mt = 0; mt < 2; mt++)
                    mma_f16_16x8x16(acc[mt][nt], af[mt], b0, b1);
            }
        }
        __syncthreads();
    }

    #pragma unroll
    for (int mt = 0; mt < 2; mt++) {
        #pragma unroll
        for (int nt = 0; nt < 8; nt++) {
            int r0 = bm + wm * 32 + mt * 16 + grp;
            int c0 = bn + wn * 64 + nt * 8 + 2 * thr;
            #pragma unroll
            for (int hh = 0; hh < 2; hh++) {
                int m = r0 + hh * 8;
                float v0 = acc[mt][nt][hh * 2 + 0];
                float v1 = acc[mt][nt][hh * 2 + 1];
                if (EPI >= 1) { v0 += bias[c0]; v1 += bias[c0 + 1]; }
                if (EPI == 2) {
                    v0 = 0.5f * v0 * (1.0f + erff(v0 * 0.70710678118654752f));
                    v1 = 0.5f * v1 * (1.0f + erff(v1 * 0.70710678118654752f));
                }
                if (EPI == 1) {
                    const float* rr = res + (size_t)m * N + c0;
                    v0 += rr[0]; v1 += rr[1];
                }
                if (OUTH) {
                    *(uint32_t*)((__half*)Cout + (size_t)m * N + c0) = packh2(v0, v1);
                } else {
                    *(float2*)((float*)Cout + (size_t)m * N + c0) = make_float2(v0, v1);
                }
            }
        }
    }
}

// ---------------- utility ----------------
__global__ void copy4_kernel(const float4* __restrict__ src, float4* __restrict__ dst, int n) {
    int i = blockIdx.x * blockDim.x + threadIdx.x;
    if (i < n) dst[i] = src[i];
}

// ---------------- LayerNorm: warp per row ----------------
template <int OUTH>
__global__ __launch_bounds__(256) void ln_kernel(
    const float* __restrict__ in, const float* __restrict__ w,
    const float* __restrict__ b, void* __restrict__ out)
{
    int warp = threadIdx.x >> 5, lane = threadIdx.x & 31;
    int row  = blockIdx.x * 8 + warp;
    const float4* p4 = (const float4*)(in + (size_t)row * DMODEL);

    float4 v[6];
    float sum = 0.f, sq = 0.f;
    #pragma unroll
    for (int i = 0; i < 6; i++) {
        v[i] = p4[lane + i * 32];
        sum += v[i].x + v[i].y + v[i].z + v[i].w;
        sq  += v[i].x * v[i].x + v[i].y * v[i].y + v[i].z * v[i].z + v[i].w * v[i].w;
    }
    #pragma unroll
    for (int o = 16; o > 0; o >>= 1) {
        sum += __shfl_xor_sync(0xffffffffu, sum, o);
        sq  += __shfl_xor_sync(0xffffffffu, sq,  o);
    }
    float mu  = sum * (1.0f / DMODEL);
    float var = sq * (1.0f / DMODEL) - mu * mu;
    float rs  = rsqrtf(var + 1e-5f);

    #pragma unroll
    for (int i = 0; i < 6; i++) {
        int c = (lane + i * 32) * 4;
        float4 wv = *(const float4*)(w + c);
        float4 bv = *(const float4*)(b + c);
        float4 r;
        r.x = (v[i].x - mu) * rs * wv.x + bv.x;
        r.y = (v[i].y - mu) * rs * wv.y + bv.y;
        r.z = (v[i].z - mu) * rs * wv.z + bv.z;
        r.w = (v[i].w - mu) * rs * wv.w + bv.w;
        if (OUTH) {
            uint2 pk = make_uint2(packh2(r.x, r.y), packh2(r.z, r.w));
            ((uint2*)((__half*)out + (size_t)row * DMODEL))[lane + i * 32] = pk;
        } else {
            ((float4*)((float*)out + (size_t)row * DMODEL))[lane + i * 32] = r;
        }
    }
}

// ---------------- fp16 tensor-core flash attention ----------------
// Block = 128 q rows of one (b,h); 256 threads = 8 warps, warp owns m16.
// fp16 m16n8k16 for S=QK^T and O+=PV. V stored TRANSPOSED (Vt[d][kk], stride 40).
// STRIDES: Q/K tiles are 64 halves wide -> stride 72 (NOT 40; R10/R11 bug).
// smem halves: Ks[32][72]=2304 | Vt[64][40]=2560 | Ps[128][40]=5120  -> 9984
// Q staging overlays the first 128*72=9216 halves before the mainloop.
__global__ __launch_bounds__(256, 2) void attn_fp16_kernel(
    const __half* __restrict__ qkv, __half* __restrict__ out)
{
    __shared__ __half sm[9984];          // 19968 B
    __half* Qs = sm;                     // [128][72] (staging only)
    __half* Ks = sm;                     // [32][72]
    __half* Vt = sm + 2304;              // [64][40]  transposed V
    __half* Ps = sm + 4864;              // [128][40]

    int tid = threadIdx.x;
    int lane = tid & 31, wid = tid >> 5;
    int grp = lane >> 2, thr = lane & 3;

    int bh = blockIdx.y;
    int b = bh / HEADS, h = bh % HEADS;
    int qt = blockIdx.x * 128;

    const __half* qbase = qkv + (size_t)(b * SEQ) * QKV3 + h * DHEAD;
    const __half* kbase = qbase + DMODEL;
    const __half* vbase = qbase + 2 * DMODEL;

    // ---- stage Q (128x64 fp16, pre-scaled by 0.125), stride 72 ----
    {
        const __half2 s2 = __floats2half2_rn(0.125f, 0.125f);
        #pragma unroll
        for (int v = 0; v < 4; v++) {
            int idx = tid + v * 256;                 // 1024 uint4
            int r = idx >> 3, c8 = (idx & 7) * 8;
            uint4 q4 = *(const uint4*)(qbase + (size_t)(qt + r) * QKV3 + c8);
            __half2* hp = (__half2*)&q4;
            #pragma unroll
            for (int j = 0; j < 4; j++) hp[j] = __hmul2(hp[j], s2);
            *(uint4*)&Qs[r * 72 + c8] = q4;
        }
    }
    __syncthreads();

    // ---- Q A-fragments: 4 k16 steps x 4 regs ----
    uint32_t qfrag[4][4];
    int qr = wid * 16 + grp;
    #pragma unroll
    for (int ks = 0; ks < 4; ks++) {
        qfrag[ks][0] = *(const uint32_t*)&Qs[ qr      * 72 + ks * 16 + 2 * thr    ];
        qfrag[ks][1] = *(const uint32_t*)&Qs[(qr + 8) * 72 + ks * 16 + 2 * thr    ];
        qfrag[ks][2] = *(const uint32_t*)&Qs[ qr      * 72 + ks * 16 + 2 * thr + 8];
        qfrag[ks][3] = *(const uint32_t*)&Qs[(qr + 8) * 72 + ks * 16 + 2 * thr + 8];
    }
    __syncthreads();    // Q smem about to be reused for K/Vt/P

    float acc_o[8][4];
    #pragma unroll
    for (int nt = 0; nt < 8; nt++)
        #pragma unroll
        for (int v = 0; v < 4; v++) acc_o[nt][v] = 0.f;
    float m0 = -1e30f, m1 = -1e30f, l0 = 0.f, l1 = 0.f;

    for (int kt0 = 0; kt0 < SEQ; kt0 += 32) {
        // ---- load K tile (stride 72) and V tile transposed (Vt[d][kk], stride 40) ----
        {
            int r = tid >> 3, c8 = (tid & 7) * 8;   // key row r, d cols c8..c8+7
            *(uint4*)&Ks[r * 72 + c8] = *(const uint4*)(kbase + (size_t)(kt0 + r) * QKV3 + c8);
            uint4 v4 = *(const uint4*)(vbase + (size_t)(kt0 + r) * QKV3 + c8);
            const __half* vh = (const __half*)&v4;
            #pragma unroll
            for (int j = 0; j < 8; j++)
                Vt[(c8 + j) * 40 + r] = vh[j];      // Vt[d][kk]
        }
        __syncthreads();

        // ---- S = Q K^T : 4 ksteps x 4 n-tiles ----
        float acc_s[4][4];
        #pragma unroll
        for (int nt = 0; nt < 4; nt++)
            #pragma unroll
            for (int v = 0; v < 4; v++) acc_s[nt][v] = 0.f;

        #pragma unroll
        for (int ks = 0; ks < 4; ks++) {
            #pragma unroll
            for (int nt = 0; nt < 4; nt++) {
                int c = nt * 8 + grp;               // key index
                uint32_t b0 = *(const uint32_t*)&Ks[c * 72 + ks * 16 + 2 * thr    ];
                uint32_t b1 = *(const uint32_t*)&Ks[c * 72 + ks * 16 + 2 * thr + 8];
                mma_f16_16x8x16(acc_s[nt], qfrag[ks], b0, b1);
            }
        }

        // ---- fragment online softmax (rows qr, qr+8) ----
        float tm0 = -1e30f, tm1 = -1e30f;
        #pragma unroll
        for (int nt = 0; nt < 4; nt++) {
            tm0 = fmaxf(tm0, fmaxf(acc_s[nt][0], acc_s[nt][1]));
            tm1 = fmaxf(tm1, fmaxf(acc_s[nt][2], acc_s[nt][3]));
        }
        tm0 = fmaxf(tm0, __shfl_xor_sync(0xffffffffu, tm0, 1));
        tm0 = fmaxf(tm0, __shfl_xor_sync(0xffffffffu, tm0, 2));
        tm1 = fmaxf(tm1, __shfl_xor_sync(0xffffffffu, tm1, 1));
        tm1 = fmaxf(tm1, __shfl_xor_sync(0xffffffffu, tm1, 2));

        float nm0 = fmaxf(m0, tm0), nm1 = fmaxf(m1, tm1);
        float c0 = expf(m0 - nm0),  c1 = expf(m1 - nm1);

        float s0 = 0.f, s1 = 0.f;
        #pragma unroll
        for (int nt = 0; nt < 4; nt++) {
            acc_s[nt][0] = expf(acc_s[nt][0] - nm0);
            acc_s[nt][1] = expf(acc_s[nt][1] - nm0);
            acc_s[nt][2] = expf(acc_s[nt][2] - nm1);
            acc_s[nt][3] = expf(acc_s[nt][3] - nm1);
            s0 += acc_s[nt][0] + acc_s[nt][1];
            s1 += acc_s[nt][2] + acc_s[nt][3];
        }
        s0 += __shfl_xor_sync(0xffffffffu, s0, 1);
        s0 += __shfl_xor_sync(0xffffffffu, s0, 2);
        s1 += __shfl_xor_sync(0xffffffffu, s1, 1);
        s1 += __shfl_xor_sync(0xffffffffu, s1, 2);

        l0 = l0 * c0 + s0;  l1 = l1 * c1 + s1;
        m0 = nm0;           m1 = nm1;

        #pragma unroll
        for (int nt = 0; nt < 8; nt++) {
            acc_o[nt][0] *= c0; acc_o[nt][1] *= c0;
            acc_o[nt][2] *= c1; acc_o[nt][3] *= c1;
        }

        // ---- write P (fp16, stride 40) to smem; intra-warp rows only ----
        #pragma unroll
        for (int nt = 0; nt < 4; nt++) {
            *(uint32_t*)&Ps[ qr      * 40 + nt * 8 + 2 * thr] = packh2(acc_s[nt][0], acc_s[nt][1]);
            *(uint32_t*)&Ps[(qr + 8) * 40 + nt * 8 + 2 * thr] = packh2(acc_s[nt][2], acc_s[nt][3]);
        }
        __syncwarp();

        // ---- O += P(16x32) @ V(32x64): GEMM-validated B pattern from Vt[d][kk] ----
        #pragma unroll
        for (int ks2 = 0; ks2 < 2; ks2++) {
            uint32_t af[4];
            af[0] = *(const uint32_t*)&Ps[ qr      * 40 + ks2 * 16 + 2 * thr    ];
            af[1] = *(const uint32_t*)&Ps[(qr + 8) * 40 + ks2 * 16 + 2 * thr    ];
            af[2] = *(const uint32_t*)&Ps[ qr      * 40 + ks2 * 16 + 2 * thr + 8];
            af[3] = *(const uint32_t*)&Ps[(qr + 8) * 40 + ks2 * 16 + 2 * thr + 8];
            #pragma unroll
            for (int nt = 0; nt < 8; nt++) {
                int d = nt * 8 + grp;               // output d index
                uint32_t b0 = *(const uint32_t*)&Vt[d * 40 + ks2 * 16 + 2 * thr    ];
                uint32_t b1 = *(const uint32_t*)&Vt[d * 40 + ks2 * 16 + 2 * thr + 8];
                mma_f16_16x8x16(acc_o[nt], af, b0, b1);
            }
        }
        __syncthreads();   // K/Vt/P reused next iteration
    }

    // ---- epilogue: out[token][h*64 + d], fp16 ----
    float il0 = 1.0f / l0, il1 = 1.0f / l1;
    int tok0 = b * SEQ + qt + wid * 16 + grp;
    #pragma unroll
    for (int nt = 0; nt < 8; nt++) {
        int col = h * DHEAD + nt * 8 + 2 * thr;
        *(uint32_t*)(out + (size_t)tok0 * DMODEL + col) =
            packh2(acc_o[nt][0] * il0, acc_o[nt][1] * il0);
        *(uint32_t*)(out + (size_t)(tok0 + 8) * DMODEL + col) =
            packh2(acc_o[nt][2] * il1, acc_o[nt][3] * il1);
    }
}

// ---------------- host orchestration ----------------
extern "C" void kernel_launch(void* const* d_in, const int* in_sizes, int n_in,
                              void* d_out, int out_size)
{
    const float* x     = (const float*)d_in[0];
    const float* ln1w  = (const float*)d_in[1];
    const float* ln1b  = (const float*)d_in[2];
    const float* wqkv  = (const float*)d_in[3];
    const float* wo    = (const float*)d_in[4];
    const float* bo    = (const float*)d_in[5];
    const float* ln2w  = (const float*)d_in[6];
    const float* ln2b  = (const float*)d_in[7];
    const float* w1    = (const float*)d_in[8];
    const float* b1    = (const float*)d_in[9];
    const float* w2    = (const float*)d_in[10];
    const float* b2    = (const float*)d_in[11];
    const float* lnfw  = (const float*)d_in[12];
    const float* lnfb  = (const float*)d_in[13];

    float *gx;
    __half *gh, *gqkv, *gao, *gff;
    cudaGetSymbolAddress((void**)&gx,   g_x);
    cudaGetSymbolAddress((void**)&gh,   g_h);
    cudaGetSymbolAddress((void**)&gqkv, g_qkv);
    cudaGetSymbolAddress((void**)&gao,  g_attnout);
    cudaGetSymbolAddress((void**)&gff,  g_ff);

    __half *qkvT, *woT, *w1T, *w2T;
    cudaGetSymbolAddress((void**)&qkvT, g_wqkvT);
    cudaGetSymbolAddress((void**)&woT,  g_woT);
    cudaGetSymbolAddress((void**)&w1T,  g_w1T);
    cudaGetSymbolAddress((void**)&w2T,  g_w2T);

    // ---- weight transpose prepass ----
    wtrans_kernel<<<dim3(DMODEL / 32, QKV3 / 32, DEPTH), 256>>>(wqkv, qkvT, DMODEL, QKV3);
    wtrans_kernel<<<dim3(DMODEL / 32, DMODEL / 32, DEPTH), 256>>>(wo, woT, DMODEL, DMODEL);
    wtrans_kernel<<<dim3(DMODEL / 32, DFF / 32, DEPTH), 256>>>(w1, w1T, DMODEL, DFF);
    wtrans_kernel<<<dim3(DFF / 32, DMODEL / 32, DEPTH), 256>>>(w2, w2T, DFF, DMODEL);

    {
        int n4 = TOKENS * DMODEL / 4;
        copy4_kernel<<<(n4 + 255) / 256, 256>>>((const float4*)x, (float4*)gx, n4);
    }

    for (int l = 0; l < DEPTH; l++) {
        const float* L1w = ln1w + (size_t)l * DMODEL;
        const float* L1b = ln1b + (size_t)l * DMODEL;
        const float* Bo  = bo   + (size_t)l * DMODEL;
        const float* L2w = ln2w + (size_t)l * DMODEL;
        const float* L2b = ln2b + (size_t)l * DMODEL;
        const float* B1  = b1   + (size_t)l * DFF;
        const float* B2  = b2   + (size_t)l * DMODEL;

        const __half* Wq = qkvT + (size_t)l * QKV3 * DMODEL;
        const __half* Wo = woT  + (size_t)l * DMODEL * DMODEL;
        const __half* W1 = w1T  + (size_t)l * DFF * DMODEL;
        const __half* W2 = w2T  + (size_t)l * DMODEL * DFF;

        ln_kernel<1><<<TOKENS / 8, 256>>>(gx, L1w, L1b, gh);
        gemm_fp16_kernel<0, 1><<<dim3(QKV3 / 128, TOKENS / 128), 256>>>(
            gh, Wq, nullptr, nullptr, gqkv, TOKENS, QKV3, DMODEL);
        attn_fp16_kernel<<<dim3(SEQ / 128, 8 * HEADS), 256>>>(gqkv, gao);
        gemm_fp16_kernel<1, 0><<<dim3(DMODEL / 128, TOKENS / 128), 256>>>(
            gao, Wo, Bo, gx, gx, TOKENS, DMODEL, DMODEL);
        ln_kernel<1><<<TOKENS / 8, 256>>>(gx, L2w, L2b, gh);
        gemm_fp16_kernel<2, 1><<<dim3(DFF / 128, TOKENS / 128), 256>>>(
            gh, W1, B1, nullptr, gff, TOKENS, DFF, DMODEL);
        gemm_fp16_kernel<1, 0><<<dim3(DMODEL / 128, TOKENS / 128), 256>>>(
            gff, W2, B2, gx, gx, TOKENS, DMODEL, DFF);
    }

    ln_kernel<0><<<TOKENS / 8, 256>>>(gx, lnfw, lnfb, (float*)d_out);
}

// round 13
// speedup vs baseline: 5.3557x; 1.0732x over previous
#include <cuda_runtime.h>
#include <cuda_fp16.h>
#include <math.h>
#include <stdint.h>

#define TOKENS 8192
#define DMODEL 768
#define HEADS  12
#define DHEAD  64
#define DFF    3072
#define DEPTH  12
#define SEQ    1024
#define QKV3   2304   // 3 * 768

// ---------------- scratch (allocation-free: __device__ globals) ----------------
__device__ float  g_x[TOKENS * DMODEL];          // residual stream (fp32)
__device__ __half g_h[TOKENS * DMODEL];          // post-LN activations (fp16)
__device__ __half g_qkv[TOKENS * QKV3];          // fused qkv (fp16)
__device__ __half g_attnout[TOKENS * DMODEL];    // attention output (fp16)
__device__ __half g_ff[TOKENS * DFF];            // FF hidden (fp16)

// pre-transposed fp16 weights: [layer][N][K]
__device__ __half g_wqkvT[DEPTH * QKV3 * DMODEL];
__device__ __half g_woT[DEPTH * DMODEL * DMODEL];
__device__ __half g_w1T[DEPTH * DFF * DMODEL];
__device__ __half g_w2T[DEPTH * DMODEL * DFF];

// ---------------- helpers ----------------
__device__ __forceinline__ uint32_t smem_u32(const void* p) {
    uint32_t a;
    asm("{ .reg .u64 t; cvta.to.shared.u64 t, %1; cvt.u32.u64 %0, t; }" : "=r"(a) : "l"(p));
    return a;
}
__device__ __forceinline__ void cp_async16(uint32_t dst, const void* src) {
    asm volatile("cp.async.cg.shared.global [%0], [%1], 16;" :: "r"(dst), "l"(src));
}
#define CP_COMMIT() asm volatile("cp.async.commit_group;" ::: "memory")
#define CP_WAIT0()  asm volatile("cp.async.wait_group 0;" ::: "memory")

__device__ __forceinline__ void mma_f16_16x8x16(float* d, const uint32_t* a,
                                                uint32_t b0, uint32_t b1) {
    asm volatile(
        "mma.sync.aligned.m16n8k16.row.col.f32.f16.f16.f32 "
        "{%0,%1,%2,%3}, {%4,%5,%6,%7}, {%8,%9}, {%0,%1,%2,%3};\n"
        : "+f"(d[0]), "+f"(d[1]), "+f"(d[2]), "+f"(d[3])
        : "r"(a[0]), "r"(a[1]), "r"(a[2]), "r"(a[3]), "r"(b0), "r"(b1));
}
__device__ __forceinline__ uint32_t packh2(float x, float y) {
    __half2 t = __floats2half2_rn(x, y);
    return *(uint32_t*)&t;
}

// ---------------- weight transpose: W[K][N] f32 -> WT[N][K] fp16 ----------------
__global__ __launch_bounds__(256) void wtrans_kernel(
    const float* __restrict__ W, __half* __restrict__ WT, int K, int N)
{
    __shared__ float T[32][33];
    int l = blockIdx.z;
    const float* Wl = W + (size_t)l * K * N;
    __half* Hl = WT + (size_t)l * K * N;
    int k0 = blockIdx.x * 32, n0 = blockIdx.y * 32;
    int tx = threadIdx.x & 31, ty = threadIdx.x >> 5;
    #pragma unroll
    for (int i = 0; i < 4; i++)
        T[ty + 8 * i][tx] = Wl[(size_t)(k0 + ty + 8 * i) * N + n0 + tx];
    __syncthreads();
    #pragma unroll
    for (int i = 0; i < 4; i++) {
        int n = n0 + ty + 8 * i, k = k0 + tx;
        Hl[(size_t)n * K + k] = __float2half(T[tx][ty + 8 * i]);
    }
}

// ---------------- cp.async pipelined fp16 GEMM, single barrier per k-tile ----------------
// wait(c) -> sync -> issue(c+1) -> compute(c): the sync separates iter c-1's
// compute reads of buf (c+1)&1 from its overwrite, so ONE barrier suffices.
#define GK_STAGE_B 10240   // 128*40*2 bytes

template <int EPI, int OUTH>
__global__ __launch_bounds__(256) void gemm_fp16_kernel(
    const __half* __restrict__ A, const __half* __restrict__ BT,
    const float* __restrict__ bias, const float* __restrict__ res,
    void* __restrict__ Cout, int M, int N, int K)
{
    __shared__ __half As[2][128 * 40];
    __shared__ __half Bs[2][128 * 40];

    int tid  = threadIdx.x;
    int lane = tid & 31;
    int wid  = tid >> 5;
    int wm = wid & 3, wn = wid >> 2;
    int bm = blockIdx.y * 128, bn = blockIdx.x * 128;
    int grp = lane >> 2, thr = lane & 3;

    float acc[2][8][4];
    #pragma unroll
    for (int i = 0; i < 2; i++)
        #pragma unroll
        for (int j = 0; j < 8; j++)
            #pragma unroll
            for (int v = 0; v < 4; v++) acc[i][j][v] = 0.f;

    int ar = tid >> 1;
    int ao = (tid & 1) * 32;
    const __half* agp = A  + (size_t)(bm + ar) * K + (tid & 1) * 16;
    const __half* bgp = BT + (size_t)(bn + ar) * K + (tid & 1) * 16;
    uint32_t sA = smem_u32(As) + ar * 80 + ao;
    uint32_t sB = smem_u32(Bs) + ar * 80 + ao;

    int ktiles = K / 32;
    // prologue: issue tile 0 into stage 0
    cp_async16(sA, agp);      cp_async16(sA + 16, agp + 8);
    cp_async16(sB, bgp);      cp_async16(sB + 16, bgp + 8);
    CP_COMMIT();

    for (int c = 0; c < ktiles; c++) {
        CP_WAIT0();            // tile c landed
        __syncthreads();       // also: all threads done computing tile c-1

        if (c + 1 < ktiles) {  // issue tile c+1 into the other stage
            int s = (c + 1) & 1;
            const __half* ap = agp + (c + 1) * 32;
            const __half* bp = bgp + (c + 1) * 32;
            cp_async16(sA + s * GK_STAGE_B, ap);      cp_async16(sA + s * GK_STAGE_B + 16, ap + 8);
            cp_async16(sB + s * GK_STAGE_B, bp);      cp_async16(sB + s * GK_STAGE_B + 16, bp + 8);
            CP_COMMIT();
        }

        const __half* Ab = As[c & 1];
        const __half* Bb = Bs[c & 1];
        #pragma unroll
        for (int s2 = 0; s2 < 2; s2++) {
            int kb = s2 * 16;
            uint32_t af[2][4];
            #pragma unroll
            for (int mt = 0; mt < 2; mt++) {
                int r = wm * 32 + mt * 16 + grp;
                af[mt][0] = *(const uint32_t*)&Ab[ r      * 40 + kb + 2 * thr    ];
                af[mt][1] = *(const uint32_t*)&Ab[(r + 8) * 40 + kb + 2 * thr    ];
                af[mt][2] = *(const uint32_t*)&Ab[ r      * 40 + kb + 2 * thr + 8];
                af[mt][3] = *(const uint32_t*)&Ab[(r + 8) * 40 + kb + 2 * thr + 8];
            }
            #pragma unroll
            for (int nt = 0; nt < 8; nt++) {
                int c2 = wn * 64 + nt * 8 + grp;
                uint32_t b0 = *(const uint32_t*)&Bb[c2 * 40 + kb + 2 * thr    ];
                uint32_t b1 = *(const uint32_t*)&Bb[c2 * 40 + kb + 2 * thr + 8];
                #pragma unroll
                for (int mt = 0; mt < 2; mt++)
                    mma_f16_16x8x16(acc[mt][nt], af[mt], b0, b1);
            }
        }
    }

    #pragma unroll
    for (int mt = 0; mt < 2; mt++) {
        #pragma unroll
        for (int nt = 0; nt < 8; nt++) {
            int r0 = bm + wm * 32 + mt * 16 + grp;
            int c0 = bn + wn * 64 + nt * 8 + 2 * thr;
            #pragma unroll
            for (int hh = 0; hh < 2; hh++) {
                int m = r0 + hh * 8;
                float v0 = acc[mt][nt][hh * 2 + 0];
                float v1 = acc[mt][nt][hh * 2 + 1];
                if (EPI >= 1) { v0 += bias[c0]; v1 += bias[c0 + 1]; }
                if (EPI == 2) {
                    v0 = 0.5f * v0 * (1.0f + erff(v0 * 0.70710678118654752f));
                    v1 = 0.5f * v1 * (1.0f + erff(v1 * 0.70710678118654752f));
                }
                if (EPI == 1) {
                    const float* rr = res + (size_t)m * N + c0;
                    v0 += rr[0]; v1 += rr[1];
                }
                if (OUTH) {
                    *(uint32_t*)((__half*)Cout + (size_t)m * N + c0) = packh2(v0, v1);
                } else {
                    *(float2*)((float*)Cout + (size_t)m * N + c0) = make_float2(v0, v1);
                }
            }
        }
    }
}

// ---------------- utility ----------------
__global__ void copy4_kernel(const float4* __restrict__ src, float4* __restrict__ dst, int n) {
    int i = blockIdx.x * blockDim.x + threadIdx.x;
    if (i < n) dst[i] = src[i];
}

// ---------------- LayerNorm: warp per row ----------------
template <int OUTH>
__global__ __launch_bounds__(256) void ln_kernel(
    const float* __restrict__ in, const float* __restrict__ w,
    const float* __restrict__ b, void* __restrict__ out)
{
    int warp = threadIdx.x >> 5, lane = threadIdx.x & 31;
    int row  = blockIdx.x * 8 + warp;
    const float4* p4 = (const float4*)(in + (size_t)row * DMODEL);

    float4 v[6];
    float sum = 0.f, sq = 0.f;
    #pragma unroll
    for (int i = 0; i < 6; i++) {
        v[i] = p4[lane + i * 32];
        sum += v[i].x + v[i].y + v[i].z + v[i].w;
        sq  += v[i].x * v[i].x + v[i].y * v[i].y + v[i].z * v[i].z + v[i].w * v[i].w;
    }
    #pragma unroll
    for (int o = 16; o > 0; o >>= 1) {
        sum += __shfl_xor_sync(0xffffffffu, sum, o);
        sq  += __shfl_xor_sync(0xffffffffu, sq,  o);
    }
    float mu  = sum * (1.0f / DMODEL);
    float var = sq * (1.0f / DMODEL) - mu * mu;
    float rs  = rsqrtf(var + 1e-5f);

    #pragma unroll
    for (int i = 0; i < 6; i++) {
        int c = (lane + i * 32) * 4;
        float4 wv = *(const float4*)(w + c);
        float4 bv = *(const float4*)(b + c);
        float4 r;
        r.x = (v[i].x - mu) * rs * wv.x + bv.x;
        r.y = (v[i].y - mu) * rs * wv.y + bv.y;
        r.z = (v[i].z - mu) * rs * wv.z + bv.z;
        r.w = (v[i].w - mu) * rs * wv.w + bv.w;
        if (OUTH) {
            uint2 pk = make_uint2(packh2(r.x, r.y), packh2(r.z, r.w));
            ((uint2*)((__half*)out + (size_t)row * DMODEL))[lane + i * 32] = pk;
        } else {
            ((float4*)((float*)out + (size_t)row * DMODEL))[lane + i * 32] = r;
        }
    }
}

// ---------------- fp16 tensor-core flash attention, 64-key tiles ----------------
// Block = 128 q rows of one (b,h); 256 threads = 8 warps, warp owns m16.
// 64-key tiles halve barriers + softmax passes vs R12. Strides all 72
// (B-operand bank = 4*grp+thr, all-distinct; verified family).
// smem halves: Ks[64][72]=4608 | Vt[64][72]=4608 | Ps[128][72]=9216 -> 18432 (36.9 KB)
// Q staging (128*72=9216) overlays Ks+Vt before the mainloop.
__global__ __launch_bounds__(256, 2) void attn_fp16_kernel(
    const __half* __restrict__ qkv, __half* __restrict__ out)
{
    __shared__ __half sm[18432];
    __half* Qs = sm;                     // [128][72] (staging only)
    __half* Ks = sm;                     // [64][72]
    __half* Vt = sm + 4608;              // [64][72]  transposed V: Vt[d][kk]
    __half* Ps = sm + 9216;              // [128][72]

    int tid = threadIdx.x;
    int lane = tid & 31, wid = tid >> 5;
    int grp = lane >> 2, thr = lane & 3;

    int bh = blockIdx.y;
    int b = bh / HEADS, h = bh % HEADS;
    int qt = blockIdx.x * 128;

    const __half* qbase = qkv + (size_t)(b * SEQ) * QKV3 + h * DHEAD;
    const __half* kbase = qbase + DMODEL;
    const __half* vbase = qbase + 2 * DMODEL;

    // ---- stage Q (128x64 fp16, pre-scaled by 0.125), stride 72 ----
    {
        const __half2 s2 = __floats2half2_rn(0.125f, 0.125f);
        #pragma unroll
        for (int v = 0; v < 4; v++) {
            int idx = tid + v * 256;                 // 1024 uint4
            int r = idx >> 3, c8 = (idx & 7) * 8;
            uint4 q4 = *(const uint4*)(qbase + (size_t)(qt + r) * QKV3 + c8);
            __half2* hp = (__half2*)&q4;
            #pragma unroll
            for (int j = 0; j < 4; j++) hp[j] = __hmul2(hp[j], s2);
            *(uint4*)&Qs[r * 72 + c8] = q4;
        }
    }
    __syncthreads();

    // ---- Q A-fragments: 4 k16 steps x 4 regs ----
    uint32_t qfrag[4][4];
    int qr = wid * 16 + grp;
    #pragma unroll
    for (int ks = 0; ks < 4; ks++) {
        qfrag[ks][0] = *(const uint32_t*)&Qs[ qr      * 72 + ks * 16 + 2 * thr    ];
        qfrag[ks][1] = *(const uint32_t*)&Qs[(qr + 8) * 72 + ks * 16 + 2 * thr    ];
        qfrag[ks][2] = *(const uint32_t*)&Qs[ qr      * 72 + ks * 16 + 2 * thr + 8];
        qfrag[ks][3] = *(const uint32_t*)&Qs[(qr + 8) * 72 + ks * 16 + 2 * thr + 8];
    }
    __syncthreads();    // Q smem about to be reused for K/Vt

    float acc_o[8][4];
    #pragma unroll
    for (int nt = 0; nt < 8; nt++)
        #pragma unroll
        for (int v = 0; v < 4; v++) acc_o[nt][v] = 0.f;
    float m0 = -1e30f, m1 = -1e30f, l0 = 0.f, l1 = 0.f;

    for (int kt0 = 0; kt0 < SEQ; kt0 += 64) {
        // ---- load K tile (64x64, stride 72) and V transposed (Vt[d][kk]) ----
        #pragma unroll
        for (int v = 0; v < 2; v++) {
            int idx = tid + v * 256;                // 512 uint4 per tensor
            int r = idx >> 3, c8 = (idx & 7) * 8;
            *(uint4*)&Ks[r * 72 + c8] = *(const uint4*)(kbase + (size_t)(kt0 + r) * QKV3 + c8);
            uint4 v4 = *(const uint4*)(vbase + (size_t)(kt0 + r) * QKV3 + c8);
            const __half* vh = (const __half*)&v4;
            int rot = idx & 7;                      // stagger to break store conflicts
            #pragma unroll
            for (int j = 0; j < 8; j++) {
                int jj = (j + rot) & 7;
                Vt[(c8 + jj) * 72 + r] = vh[jj];
            }
        }
        __syncthreads();

        // ---- S = Q K^T : 4 ksteps x 8 n-tiles ----
        float acc_s[8][4];
        #pragma unroll
        for (int nt = 0; nt < 8; nt++)
            #pragma unroll
            for (int v = 0; v < 4; v++) acc_s[nt][v] = 0.f;

        #pragma unroll
        for (int ks = 0; ks < 4; ks++) {
            #pragma unroll
            for (int nt = 0; nt < 8; nt++) {
                int c = nt * 8 + grp;               // key index
                uint32_t b0 = *(const uint32_t*)&Ks[c * 72 + ks * 16 + 2 * thr    ];
                uint32_t b1 = *(const uint32_t*)&Ks[c * 72 + ks * 16 + 2 * thr + 8];
                mma_f16_16x8x16(acc_s[nt], qfrag[ks], b0, b1);
            }
        }

        // ---- fragment online softmax (rows qr, qr+8) ----
        float tm0 = -1e30f, tm1 = -1e30f;
        #pragma unroll
        for (int nt = 0; nt < 8; nt++) {
            tm0 = fmaxf(tm0, fmaxf(acc_s[nt][0], acc_s[nt][1]));
            tm1 = fmaxf(tm1, fmaxf(acc_s[nt][2], acc_s[nt][3]));
        }
        tm0 = fmaxf(tm0, __shfl_xor_sync(0xffffffffu, tm0, 1));
        tm0 = fmaxf(tm0, __shfl_xor_sync(0xffffffffu, tm0, 2));
        tm1 = fmaxf(tm1, __shfl_xor_sync(0xffffffffu, tm1, 1));
        tm1 = fmaxf(tm1, __shfl_xor_sync(0xffffffffu, tm1, 2));

        float nm0 = fmaxf(m0, tm0), nm1 = fmaxf(m1, tm1);
        float c0 = __expf(m0 - nm0),  c1 = __expf(m1 - nm1);

        float s0 = 0.f, s1 = 0.f;
        #pragma unroll
        for (int nt = 0; nt < 8; nt++) {
            acc_s[nt][0] = __expf(acc_s[nt][0] - nm0);
            acc_s[nt][1] = __expf(acc_s[nt][1] - nm0);
            acc_s[nt][2] = __expf(acc_s[nt][2] - nm1);
            acc_s[nt][3] = __expf(acc_s[nt][3] - nm1);
            s0 += acc_s[nt][0] + acc_s[nt][1];
            s1 += acc_s[nt][2] + acc_s[nt][3];
        }
        s0 += __shfl_xor_sync(0xffffffffu, s0, 1);
        s0 += __shfl_xor_sync(0xffffffffu, s0, 2);
        s1 += __shfl_xor_sync(0xffffffffu, s1, 1);
        s1 += __shfl_xor_sync(0xffffffffu, s1, 2);

        l0 = l0 * c0 + s0;  l1 = l1 * c1 + s1;
        m0 = nm0;           m1 = nm1;

        #pragma unroll
        for (int nt = 0; nt < 8; nt++) {
            acc_o[nt][0] *= c0; acc_o[nt][1] *= c0;
            acc_o[nt][2] *= c1; acc_o[nt][3] *= c1;
        }

        // ---- write P (fp16, stride 72); intra-warp rows only ----
        #pragma unroll
        for (int nt = 0; nt < 8; nt++) {
            *(uint32_t*)&Ps[ qr      * 72 + nt * 8 + 2 * thr] = packh2(acc_s[nt][0], acc_s[nt][1]);
            *(uint32_t*)&Ps[(qr + 8) * 72 + nt * 8 + 2 * thr] = packh2(acc_s[nt][2], acc_s[nt][3]);
        }
        __syncwarp();

        // ---- O += P(16x64) @ V(64x64): B pattern from Vt[d][kk] ----
        #pragma unroll
        for (int ks2 = 0; ks2 < 4; ks2++) {
            uint32_t af[4];
            af[0] = *(const uint32_t*)&Ps[ qr      * 72 + ks2 * 16 + 2 * thr    ];
            af[1] = *(const uint32_t*)&Ps[(qr + 8) * 72 + ks2 * 16 + 2 * thr    ];
            af[2] = *(const uint32_t*)&Ps[ qr      * 72 + ks2 * 16 + 2 * thr + 8];
            af[3] = *(const uint32_t*)&Ps[(qr + 8) * 72 + ks2 * 16 + 2 * thr + 8];
            #pragma unroll
            for (int nt = 0; nt < 8; nt++) {
                int d = nt * 8 + grp;               // output d index
                uint32_t b0 = *(const uint32_t*)&Vt[d * 72 + ks2 * 16 + 2 * thr    ];
                uint32_t b1 = *(const uint32_t*)&Vt[d * 72 + ks2 * 16 + 2 * thr + 8];
                mma_f16_16x8x16(acc_o[nt], af, b0, b1);
            }
        }
        __syncthreads();   // K/Vt/Ps reused next iteration
    }

    // ---- epilogue: out[token][h*64 + d], fp16 ----
    float il0 = 1.0f / l0, il1 = 1.0f / l1;
    int tok0 = b * SEQ + qt + wid * 16 + grp;
    #pragma unroll
    for (int nt = 0; nt < 8; nt++) {
        int col = h * DHEAD + nt * 8 + 2 * thr;
        *(uint32_t*)(out + (size_t)tok0 * DMODEL + col) =
            packh2(acc_o[nt][0] * il0, acc_o[nt][1] * il0);
        *(uint32_t*)(out + (size_t)(tok0 + 8) * DMODEL + col) =
            packh2(acc_o[nt][2] * il1, acc_o[nt][3] * il1);
    }
}

// ---------------- host orchestration ----------------
extern "C" void kernel_launch(void* const* d_in, const int* in_sizes, int n_in,
                              void* d_out, int out_size)
{
    const float* x     = (const float*)d_in[0];
    const float* ln1w  = (const float*)d_in[1];
    const float* ln1b  = (const float*)d_in[2];
    const float* wqkv  = (const float*)d_in[3];
    const float* wo    = (const float*)d_in[4];
    const float* bo    = (const float*)d_in[5];
    const float* ln2w  = (const float*)d_in[6];
    const float* ln2b  = (const float*)d_in[7];
    const float* w1    = (const float*)d_in[8];
    const float* b1    = (const float*)d_in[9];
    const float* w2    = (const float*)d_in[10];
    const float* b2    = (const float*)d_in[11];
    const float* lnfw  = (const float*)d_in[12];
    const float* lnfb  = (const float*)d_in[13];

    float *gx;
    __half *gh, *gqkv, *gao, *gff;
    cudaGetSymbolAddress((void**)&gx,   g_x);
    cudaGetSymbolAddress((void**)&gh,   g_h);
    cudaGetSymbolAddress((void**)&gqkv, g_qkv);
    cudaGetSymbolAddress((void**)&gao,  g_attnout);
    cudaGetSymbolAddress((void**)&gff,  g_ff);

    __half *qkvT, *woT, *w1T, *w2T;
    cudaGetSymbolAddress((void**)&qkvT, g_wqkvT);
    cudaGetSymbolAddress((void**)&woT,  g_woT);
    cudaGetSymbolAddress((void**)&w1T,  g_w1T);
    cudaGetSymbolAddress((void**)&w2T,  g_w2T);

    // ---- weight transpose prepass ----
    wtrans_kernel<<<dim3(DMODEL / 32, QKV3 / 32, DEPTH), 256>>>(wqkv, qkvT, DMODEL, QKV3);
    wtrans_kernel<<<dim3(DMODEL / 32, DMODEL / 32, DEPTH), 256>>>(wo, woT, DMODEL, DMODEL);
    wtrans_kernel<<<dim3(DMODEL / 32, DFF / 32, DEPTH), 256>>>(w1, w1T, DMODEL, DFF);
    wtrans_kernel<<<dim3(DFF / 32, DMODEL / 32, DEPTH), 256>>>(w2, w2T, DFF, DMODEL);

    {
        int n4 = TOKENS * DMODEL / 4;
        copy4_kernel<<<(n4 + 255) / 256, 256>>>((const float4*)x, (float4*)gx, n4);
    }

    for (int l = 0; l < DEPTH; l++) {
        const float* L1w = ln1w + (size_t)l * DMODEL;
        const float* L1b = ln1b + (size_t)l * DMODEL;
        const float* Bo  = bo   + (size_t)l * DMODEL;
        const float* L2w = ln2w + (size_t)l * DMODEL;
        const float* L2b = ln2b + (size_t)l * DMODEL;
        const float* B1  = b1   + (size_t)l * DFF;
        const float* B2  = b2   + (size_t)l * DMODEL;

        const __half* Wq = qkvT + (size_t)l * QKV3 * DMODEL;
        const __half* Wo = woT  + (size_t)l * DMODEL * DMODEL;
        const __half* W1 = w1T  + (size_t)l * DFF * DMODEL;
        const __half* W2 = w2T  + (size_t)l * DMODEL * DFF;

        ln_kernel<1><<<TOKENS / 8, 256>>>(gx, L1w, L1b, gh);
        gemm_fp16_kernel<0, 1><<<dim3(QKV3 / 128, TOKENS / 128), 256>>>(
            gh, Wq, nullptr, nullptr, gqkv, TOKENS, QKV3, DMODEL);
        attn_fp16_kernel<<<dim3(SEQ / 128, 8 * HEADS), 256>>>(gqkv, gao);
        gemm_fp16_kernel<1, 0><<<dim3(DMODEL / 128, TOKENS / 128), 256>>>(
            gao, Wo, Bo, gx, gx, TOKENS, DMODEL, DMODEL);
        ln_kernel<1><<<TOKENS / 8, 256>>>(gx, L2w, L2b, gh);
        gemm_fp16_kernel<2, 1><<<dim3(DFF / 128, TOKENS / 128), 256>>>(
            gh, W1, B1, nullptr, gff, TOKENS, DFF, DMODEL);
        gemm_fp16_kernel<1, 0><<<dim3(DMODEL / 128, TOKENS / 128), 256>>>(
            gff, W2, B2, gx, gx, TOKENS, DMODEL, DFF);
    }

    ln_kernel<0><<<TOKENS / 8, 256>>>(gx, lnfw, lnfb, (float*)d_out);
}

// round 14
// speedup vs baseline: 5.4074x; 1.0097x over previous
#include <cuda_runtime.h>
#include <cuda_fp16.h>
#include <math.h>
#include <stdint.h>

#define TOKENS 8192
#define DMODEL 768
#define HEADS  12
#define DHEAD  64
#define DFF    3072
#define DEPTH  12
#define SEQ    1024
#define QKV3   2304   // 3 * 768

// ---------------- scratch (allocation-free: __device__ globals) ----------------
__device__ float  g_x[TOKENS * DMODEL];          // residual stream (fp32)
__device__ __half g_h[TOKENS * DMODEL];          // post-LN activations (fp16)
__device__ __half g_qkv[TOKENS * QKV3];          // fused qkv (fp16)
__device__ __half g_attnout[TOKENS * DMODEL];    // attention output (fp16)
__device__ __half g_ff[TOKENS * DFF];            // FF hidden (fp16)

// pre-transposed fp16 weights: [layer][N][K]
__device__ __half g_wqkvT[DEPTH * QKV3 * DMODEL];
__device__ __half g_woT[DEPTH * DMODEL * DMODEL];
__device__ __half g_w1T[DEPTH * DFF * DMODEL];
__device__ __half g_w2T[DEPTH * DMODEL * DFF];

// ---------------- helpers ----------------
__device__ __forceinline__ uint32_t smem_u32(const void* p) {
    uint32_t a;
    asm("{ .reg .u64 t; cvta.to.shared.u64 t, %1; cvt.u32.u64 %0, t; }" : "=r"(a) : "l"(p));
    return a;
}
__device__ __forceinline__ void cp_async16(uint32_t dst, const void* src) {
    asm volatile("cp.async.cg.shared.global [%0], [%1], 16;" :: "r"(dst), "l"(src));
}
#define CP_COMMIT() asm volatile("cp.async.commit_group;" ::: "memory")
#define CP_WAIT0()  asm volatile("cp.async.wait_group 0;" ::: "memory")

__device__ __forceinline__ void mma_f16_16x8x16(float* d, const uint32_t* a,
                                                uint32_t b0, uint32_t b1) {
    asm volatile(
        "mma.sync.aligned.m16n8k16.row.col.f32.f16.f16.f32 "
        "{%0,%1,%2,%3}, {%4,%5,%6,%7}, {%8,%9}, {%0,%1,%2,%3};\n"
        : "+f"(d[0]), "+f"(d[1]), "+f"(d[2]), "+f"(d[3])
        : "r"(a[0]), "r"(a[1]), "r"(a[2]), "r"(a[3]), "r"(b0), "r"(b1));
}
__device__ __forceinline__ uint32_t packh2(float x, float y) {
    __half2 t = __floats2half2_rn(x, y);
    return *(uint32_t*)&t;
}

// ---------------- weight transpose: W[K][N] f32 -> WT[N][K] fp16 ----------------
__global__ __launch_bounds__(256) void wtrans_kernel(
    const float* __restrict__ W, __half* __restrict__ WT, int K, int N)
{
    __shared__ float T[32][33];
    int l = blockIdx.z;
    const float* Wl = W + (size_t)l * K * N;
    __half* Hl = WT + (size_t)l * K * N;
    int k0 = blockIdx.x * 32, n0 = blockIdx.y * 32;
    int tx = threadIdx.x & 31, ty = threadIdx.x >> 5;
    #pragma unroll
    for (int i = 0; i < 4; i++)
        T[ty + 8 * i][tx] = Wl[(size_t)(k0 + ty + 8 * i) * N + n0 + tx];
    __syncthreads();
    #pragma unroll
    for (int i = 0; i < 4; i++) {
        int n = n0 + ty + 8 * i, k = k0 + tx;
        Hl[(size_t)n * K + k] = __float2half(T[tx][ty + 8 * i]);
    }
}

// ---------------- cp.async pipelined fp16 GEMM, single barrier per k-tile ----------------
#define GK_STAGE_B 10240   // 128*40*2 bytes

template <int EPI, int OUTH>
__global__ __launch_bounds__(256) void gemm_fp16_kernel(
    const __half* __restrict__ A, const __half* __restrict__ BT,
    const float* __restrict__ bias, const float* __restrict__ res,
    void* __restrict__ Cout, int M, int N, int K)
{
    __shared__ __half As[2][128 * 40];
    __shared__ __half Bs[2][128 * 40];

    int tid  = threadIdx.x;
    int lane = tid & 31;
    int wid  = tid >> 5;
    int wm = wid & 3, wn = wid >> 2;
    int bm = blockIdx.y * 128, bn = blockIdx.x * 128;
    int grp = lane >> 2, thr = lane & 3;

    float acc[2][8][4];
    #pragma unroll
    for (int i = 0; i < 2; i++)
        #pragma unroll
        for (int j = 0; j < 8; j++)
            #pragma unroll
            for (int v = 0; v < 4; v++) acc[i][j][v] = 0.f;

    int ar = tid >> 1;
    int ao = (tid & 1) * 32;
    const __half* agp = A  + (size_t)(bm + ar) * K + (tid & 1) * 16;
    const __half* bgp = BT + (size_t)(bn + ar) * K + (tid & 1) * 16;
    uint32_t sA = smem_u32(As) + ar * 80 + ao;
    uint32_t sB = smem_u32(Bs) + ar * 80 + ao;

    int ktiles = K / 32;
    cp_async16(sA, agp);      cp_async16(sA + 16, agp + 8);
    cp_async16(sB, bgp);      cp_async16(sB + 16, bgp + 8);
    CP_COMMIT();

    for (int c = 0; c < ktiles; c++) {
        CP_WAIT0();
        __syncthreads();

        if (c + 1 < ktiles) {
            int s = (c + 1) & 1;
            const __half* ap = agp + (c + 1) * 32;
            const __half* bp = bgp + (c + 1) * 32;
            cp_async16(sA + s * GK_STAGE_B, ap);      cp_async16(sA + s * GK_STAGE_B + 16, ap + 8);
            cp_async16(sB + s * GK_STAGE_B, bp);      cp_async16(sB + s * GK_STAGE_B + 16, bp + 8);
            CP_COMMIT();
        }

        const __half* Ab = As[c & 1];
        const __half* Bb = Bs[c & 1];
        #pragma unroll
        for (int s2 = 0; s2 < 2; s2++) {
            int kb = s2 * 16;
            uint32_t af[2][4];
            #pragma unroll
            for (int mt = 0; mt < 2; mt++) {
                int r = wm * 32 + mt * 16 + grp;
                af[mt][0] = *(const uint32_t*)&Ab[ r      * 40 + kb + 2 * thr    ];
                af[mt][1] = *(const uint32_t*)&Ab[(r + 8) * 40 + kb + 2 * thr    ];
                af[mt][2] = *(const uint32_t*)&Ab[ r      * 40 + kb + 2 * thr + 8];
                af[mt][3] = *(const uint32_t*)&Ab[(r + 8) * 40 + kb + 2 * thr + 8];
            }
            #pragma unroll
            for (int nt = 0; nt < 8; nt++) {
                int c2 = wn * 64 + nt * 8 + grp;
                uint32_t b0 = *(const uint32_t*)&Bb[c2 * 40 + kb + 2 * thr    ];
                uint32_t b1 = *(const uint32_t*)&Bb[c2 * 40 + kb + 2 * thr + 8];
                #pragma unroll
                for (int mt = 0; mt < 2; mt++)
                    mma_f16_16x8x16(acc[mt][nt], af[mt], b0, b1);
            }
        }
    }

    #pragma unroll
    for (int mt = 0; mt < 2; mt++) {
        #pragma unroll
        for (int nt = 0; nt < 8; nt++) {
            int r0 = bm + wm * 32 + mt * 16 + grp;
            int c0 = bn + wn * 64 + nt * 8 + 2 * thr;
            #pragma unroll
            for (int hh = 0; hh < 2; hh++) {
                int m = r0 + hh * 8;
                float v0 = acc[mt][nt][hh * 2 + 0];
                float v1 = acc[mt][nt][hh * 2 + 1];
                if (EPI >= 1) { v0 += bias[c0]; v1 += bias[c0 + 1]; }
                if (EPI == 2) {
                    v0 = 0.5f * v0 * (1.0f + erff(v0 * 0.70710678118654752f));
                    v1 = 0.5f * v1 * (1.0f + erff(v1 * 0.70710678118654752f));
                }
                if (EPI == 1) {
                    const float* rr = res + (size_t)m * N + c0;
                    v0 += rr[0]; v1 += rr[1];
                }
                if (OUTH) {
                    *(uint32_t*)((__half*)Cout + (size_t)m * N + c0) = packh2(v0, v1);
                } else {
                    *(float2*)((float*)Cout + (size_t)m * N + c0) = make_float2(v0, v1);
                }
            }
        }
    }
}

// ---------------- utility ----------------
__global__ void copy4_kernel(const float4* __restrict__ src, float4* __restrict__ dst, int n) {
    int i = blockIdx.x * blockDim.x + threadIdx.x;
    if (i < n) dst[i] = src[i];
}

// ---------------- LayerNorm: warp per 2 rows (doubled MLP) ----------------
template <int OUTH>
__global__ __launch_bounds__(256) void ln_kernel(
    const float* __restrict__ in, const float* __restrict__ w,
    const float* __restrict__ b, void* __restrict__ out)
{
    int warp = threadIdx.x >> 5, lane = threadIdx.x & 31;
    int row0 = blockIdx.x * 16 + warp * 2;
    const float4* pa = (const float4*)(in + (size_t)row0 * DMODEL);
    const float4* pb = (const float4*)(in + (size_t)(row0 + 1) * DMODEL);

    float4 va[6], vb[6];
    float sa = 0.f, qa = 0.f, sb = 0.f, qb = 0.f;
    #pragma unroll
    for (int i = 0; i < 6; i++) {
        va[i] = pa[lane + i * 32];
        vb[i] = pb[lane + i * 32];
        sa += va[i].x + va[i].y + va[i].z + va[i].w;
        qa += va[i].x * va[i].x + va[i].y * va[i].y + va[i].z * va[i].z + va[i].w * va[i].w;
        sb += vb[i].x + vb[i].y + vb[i].z + vb[i].w;
        qb += vb[i].x * vb[i].x + vb[i].y * vb[i].y + vb[i].z * vb[i].z + vb[i].w * vb[i].w;
    }
    #pragma unroll
    for (int o = 16; o > 0; o >>= 1) {
        sa += __shfl_xor_sync(0xffffffffu, sa, o);
        qa += __shfl_xor_sync(0xffffffffu, qa, o);
        sb += __shfl_xor_sync(0xffffffffu, sb, o);
        qb += __shfl_xor_sync(0xffffffffu, qb, o);
    }
    float mua = sa * (1.0f / DMODEL), mub = sb * (1.0f / DMODEL);
    float rsa = rsqrtf(qa * (1.0f / DMODEL) - mua * mua + 1e-5f);
    float rsb = rsqrtf(qb * (1.0f / DMODEL) - mub * mub + 1e-5f);

    #pragma unroll
    for (int i = 0; i < 6; i++) {
        int c = (lane + i * 32) * 4;
        float4 wv = *(const float4*)(w + c);
        float4 bv = *(const float4*)(b + c);
        float4 ra, rb;
        ra.x = (va[i].x - mua) * rsa * wv.x + bv.x;
        ra.y = (va[i].y - mua) * rsa * wv.y + bv.y;
        ra.z = (va[i].z - mua) * rsa * wv.z + bv.z;
        ra.w = (va[i].w - mua) * rsa * wv.w + bv.w;
        rb.x = (vb[i].x - mub) * rsb * wv.x + bv.x;
        rb.y = (vb[i].y - mub) * rsb * wv.y + bv.y;
        rb.z = (vb[i].z - mub) * rsb * wv.z + bv.z;
        rb.w = (vb[i].w - mub) * rsb * wv.w + bv.w;
        if (OUTH) {
            ((uint2*)((__half*)out + (size_t)row0 * DMODEL))[lane + i * 32] =
                make_uint2(packh2(ra.x, ra.y), packh2(ra.z, ra.w));
            ((uint2*)((__half*)out + (size_t)(row0 + 1) * DMODEL))[lane + i * 32] =
                make_uint2(packh2(rb.x, rb.y), packh2(rb.z, rb.w));
        } else {
            ((float4*)((float*)out + (size_t)row0 * DMODEL))[lane + i * 32] = ra;
            ((float4*)((float*)out + (size_t)(row0 + 1) * DMODEL))[lane + i * 32] = rb;
        }
    }
}

// ---------------- fp16 tensor-core flash attention, 64-key tiles + reg prefetch ----------------
// Block = 128 q rows of one (b,h); 256 threads = 8 warps, warp owns m16.
// K/V tiles for step c+1 are LDG-prefetched into registers during compute of c.
// Strides all 72. smem halves: Ks[64][72] | Vt[64][72] | Ps[128][72] -> 18432 (36.9 KB)
__global__ __launch_bounds__(256, 2) void attn_fp16_kernel(
    const __half* __restrict__ qkv, __half* __restrict__ out)
{
    __shared__ __half sm[18432];
    __half* Qs = sm;                     // [128][72] (staging only)
    __half* Ks = sm;                     // [64][72]
    __half* Vt = sm + 4608;              // [64][72]  transposed V: Vt[d][kk]
    __half* Ps = sm + 9216;              // [128][72]

    int tid = threadIdx.x;
    int lane = tid & 31, wid = tid >> 5;
    int grp = lane >> 2, thr = lane & 3;

    int bh = blockIdx.y;
    int b = bh / HEADS, h = bh % HEADS;
    int qt = blockIdx.x * 128;

    const __half* qbase = qkv + (size_t)(b * SEQ) * QKV3 + h * DHEAD;
    const __half* kbase = qbase + DMODEL;
    const __half* vbase = qbase + 2 * DMODEL;

    int lr = tid >> 3, lc8 = (tid & 7) * 8;   // load coords: rows lr, lr+32
    int rot0 = tid & 7, rot1 = (tid + 256) & 7;

    // ---- prologue: issue K/V LDG for tile 0 (latency hidden by Q staging) ----
    uint4 kreg[2], vreg[2];
    kreg[0] = *(const uint4*)(kbase + (size_t)lr * QKV3 + lc8);
    kreg[1] = *(const uint4*)(kbase + (size_t)(lr + 32) * QKV3 + lc8);
    vreg[0] = *(const uint4*)(vbase + (size_t)lr * QKV3 + lc8);
    vreg[1] = *(const uint4*)(vbase + (size_t)(lr + 32) * QKV3 + lc8);

    // ---- stage Q (128x64 fp16, pre-scaled by 0.125), stride 72 ----
    {
        const __half2 s2 = __floats2half2_rn(0.125f, 0.125f);
        #pragma unroll
        for (int v = 0; v < 4; v++) {
            int idx = tid + v * 256;
            int r = idx >> 3, c8 = (idx & 7) * 8;
            uint4 q4 = *(const uint4*)(qbase + (size_t)(qt + r) * QKV3 + c8);
            __half2* hp = (__half2*)&q4;
            #pragma unroll
            for (int j = 0; j < 4; j++) hp[j] = __hmul2(hp[j], s2);
            *(uint4*)&Qs[r * 72 + c8] = q4;
        }
    }
    __syncthreads();

    // ---- Q A-fragments ----
    uint32_t qfrag[4][4];
    int qr = wid * 16 + grp;
    #pragma unroll
    for (int ks = 0; ks < 4; ks++) {
        qfrag[ks][0] = *(const uint32_t*)&Qs[ qr      * 72 + ks * 16 + 2 * thr    ];
        qfrag[ks][1] = *(const uint32_t*)&Qs[(qr + 8) * 72 + ks * 16 + 2 * thr    ];
        qfrag[ks][2] = *(const uint32_t*)&Qs[ qr      * 72 + ks * 16 + 2 * thr + 8];
        qfrag[ks][3] = *(const uint32_t*)&Qs[(qr + 8) * 72 + ks * 16 + 2 * thr + 8];
    }
    __syncthreads();

    float acc_o[8][4];
    #pragma unroll
    for (int nt = 0; nt < 8; nt++)
        #pragma unroll
        for (int v = 0; v < 4; v++) acc_o[nt][v] = 0.f;
    float m0 = -1e30f, m1 = -1e30f, l0 = 0.f, l1 = 0.f;

    for (int kt0 = 0; kt0 < SEQ; kt0 += 64) {
        // ---- store registered K/V tile to smem ----
        {
            *(uint4*)&Ks[lr * 72 + lc8] = kreg[0];
            *(uint4*)&Ks[(lr + 32) * 72 + lc8] = kreg[1];
            const __half* vh0 = (const __half*)&vreg[0];
            const __half* vh1 = (const __half*)&vreg[1];
            #pragma unroll
            for (int j = 0; j < 8; j++) {
                int j0 = (j + rot0) & 7;
                Vt[(lc8 + j0) * 72 + lr] = vh0[j0];
                int j1 = (j + rot1) & 7;
                Vt[(lc8 + j1) * 72 + lr + 32] = vh1[j1];
            }
        }
        __syncthreads();

        // ---- prefetch next K/V tile into registers (hidden by compute) ----
        if (kt0 + 64 < SEQ) {
            const __half* kp = kbase + (size_t)(kt0 + 64) * QKV3;
            const __half* vp = vbase + (size_t)(kt0 + 64) * QKV3;
            kreg[0] = *(const uint4*)(kp + (size_t)lr * QKV3 + lc8);
            kreg[1] = *(const uint4*)(kp + (size_t)(lr + 32) * QKV3 + lc8);
            vreg[0] = *(const uint4*)(vp + (size_t)lr * QKV3 + lc8);
            vreg[1] = *(const uint4*)(vp + (size_t)(lr + 32) * QKV3 + lc8);
        }

        // ---- S = Q K^T : 4 ksteps x 8 n-tiles ----
        float acc_s[8][4];
        #pragma unroll
        for (int nt = 0; nt < 8; nt++)
            #pragma unroll
            for (int v = 0; v < 4; v++) acc_s[nt][v] = 0.f;

        #pragma unroll
        for (int ks = 0; ks < 4; ks++) {
            #pragma unroll
            for (int nt = 0; nt < 8; nt++) {
                int c = nt * 8 + grp;
                uint32_t b0 = *(const uint32_t*)&Ks[c * 72 + ks * 16 + 2 * thr    ];
                uint32_t b1 = *(const uint32_t*)&Ks[c * 72 + ks * 16 + 2 * thr + 8];
                mma_f16_16x8x16(acc_s[nt], qfrag[ks], b0, b1);
            }
        }

        // ---- fragment online softmax ----
        float tm0 = -1e30f, tm1 = -1e30f;
        #pragma unroll
        for (int nt = 0; nt < 8; nt++) {
            tm0 = fmaxf(tm0, fmaxf(acc_s[nt][0], acc_s[nt][1]));
            tm1 = fmaxf(tm1, fmaxf(acc_s[nt][2], acc_s[nt][3]));
        }
        tm0 = fmaxf(tm0, __shfl_xor_sync(0xffffffffu, tm0, 1));
        tm0 = fmaxf(tm0, __shfl_xor_sync(0xffffffffu, tm0, 2));
        tm1 = fmaxf(tm1, __shfl_xor_sync(0xffffffffu, tm1, 1));
        tm1 = fmaxf(tm1, __shfl_xor_sync(0xffffffffu, tm1, 2));

        float nm0 = fmaxf(m0, tm0), nm1 = fmaxf(m1, tm1);
        float c0 = __expf(m0 - nm0),  c1 = __expf(m1 - nm1);

        float s0 = 0.f, s1 = 0.f;
        #pragma unroll
        for (int nt = 0; nt < 8; nt++) {
            acc_s[nt][0] = __expf(acc_s[nt][0] - nm0);
            acc_s[nt][1] = __expf(acc_s[nt][1] - nm0);
            acc_s[nt][2] = __expf(acc_s[nt][2] - nm1);
            acc_s[nt][3] = __expf(acc_s[nt][3] - nm1);
            s0 += acc_s[nt][0] + acc_s[nt][1];
            s1 += acc_s[nt][2] + acc_s[nt][3];
        }
        s0 += __shfl_xor_sync(0xffffffffu, s0, 1);
        s0 += __shfl_xor_sync(0xffffffffu, s0, 2);
        s1 += __shfl_xor_sync(0xffffffffu, s1, 1);
        s1 += __shfl_xor_sync(0xffffffffu, s1, 2);

        l0 = l0 * c0 + s0;  l1 = l1 * c1 + s1;
        m0 = nm0;           m1 = nm1;

        #pragma unroll
        for (int nt = 0; nt < 8; nt++) {
            acc_o[nt][0] *= c0; acc_o[nt][1] *= c0;
            acc_o[nt][2] *= c1; acc_o[nt][3] *= c1;
        }

        // ---- write P (fp16, stride 72) ----
        #pragma unroll
        for (int nt = 0; nt < 8; nt++) {
            *(uint32_t*)&Ps[ qr      * 72 + nt * 8 + 2 * thr] = packh2(acc_s[nt][0], acc_s[nt][1]);
            *(uint32_t*)&Ps[(qr + 8) * 72 + nt * 8 + 2 * thr] = packh2(acc_s[nt][2], acc_s[nt][3]);
        }
        __syncwarp();

        // ---- O += P(16x64) @ V(64x64) ----
        #pragma unroll
        for (int ks2 = 0; ks2 < 4; ks2++) {
            uint32_t af[4];
            af[0] = *(const uint32_t*)&Ps[ qr      * 72 + ks2 * 16 + 2 * thr    ];
            af[1] = *(const uint32_t*)&Ps[(qr + 8) * 72 + ks2 * 16 + 2 * thr    ];
            af[2] = *(const uint32_t*)&Ps[ qr      * 72 + ks2 * 16 + 2 * thr + 8];
            af[3] = *(const uint32_t*)&Ps[(qr + 8) * 72 + ks2 * 16 + 2 * thr + 8];
            #pragma unroll
            for (int nt = 0; nt < 8; nt++) {
                int d = nt * 8 + grp;
                uint32_t b0 = *(const uint32_t*)&Vt[d * 72 + ks2 * 16 + 2 * thr    ];
                uint32_t b1 = *(const uint32_t*)&Vt[d * 72 + ks2 * 16 + 2 * thr + 8];
                mma_f16_16x8x16(acc_o[nt], af, b0, b1);
            }
        }
        __syncthreads();   // K/Vt/Ps reused next iteration
    }

    // ---- epilogue ----
    float il0 = 1.0f / l0, il1 = 1.0f / l1;
    int tok0 = b * SEQ + qt + wid * 16 + grp;
    #pragma unroll
    for (int nt = 0; nt < 8; nt++) {
        int col = h * DHEAD + nt * 8 + 2 * thr;
        *(uint32_t*)(out + (size_t)tok0 * DMODEL + col) =
            packh2(acc_o[nt][0] * il0, acc_o[nt][1] * il0);
        *(uint32_t*)(out + (size_t)(tok0 + 8) * DMODEL + col) =
            packh2(acc_o[nt][2] * il1, acc_o[nt][3] * il1);
    }
}

// ---------------- host orchestration ----------------
extern "C" void kernel_launch(void* const* d_in, const int* in_sizes, int n_in,
                              void* d_out, int out_size)
{
    const float* x     = (const float*)d_in[0];
    const float* ln1w  = (const float*)d_in[1];
    const float* ln1b  = (const float*)d_in[2];
    const float* wqkv  = (const float*)d_in[3];
    const float* wo    = (const float*)d_in[4];
    const float* bo    = (const float*)d_in[5];
    const float* ln2w  = (const float*)d_in[6];
    const float* ln2b  = (const float*)d_in[7];
    const float* w1    = (const float*)d_in[8];
    const float* b1    = (const float*)d_in[9];
    const float* w2    = (const float*)d_in[10];
    const float* b2    = (const float*)d_in[11];
    const float* lnfw  = (const float*)d_in[12];
    const float* lnfb  = (const float*)d_in[13];

    float *gx;
    __half *gh, *gqkv, *gao, *gff;
    cudaGetSymbolAddress((void**)&gx,   g_x);
    cudaGetSymbolAddress((void**)&gh,   g_h);
    cudaGetSymbolAddress((void**)&gqkv, g_qkv);
    cudaGetSymbolAddress((void**)&gao,  g_attnout);
    cudaGetSymbolAddress((void**)&gff,  g_ff);

    __half *qkvT, *woT, *w1T, *w2T;
    cudaGetSymbolAddress((void**)&qkvT, g_wqkvT);
    cudaGetSymbolAddress((void**)&woT,  g_woT);
    cudaGetSymbolAddress((void**)&w1T,  g_w1T);
    cudaGetSymbolAddress((void**)&w2T,  g_w2T);

    // ---- weight transpose prepass ----
    wtrans_kernel<<<dim3(DMODEL / 32, QKV3 / 32, DEPTH), 256>>>(wqkv, qkvT, DMODEL, QKV3);
    wtrans_kernel<<<dim3(DMODEL / 32, DMODEL / 32, DEPTH), 256>>>(wo, woT, DMODEL, DMODEL);
    wtrans_kernel<<<dim3(DMODEL / 32, DFF / 32, DEPTH), 256>>>(w1, w1T, DMODEL, DFF);
    wtrans_kernel<<<dim3(DFF / 32, DMODEL / 32, DEPTH), 256>>>(w2, w2T, DFF, DMODEL);

    {
        int n4 = TOKENS * DMODEL / 4;
        copy4_kernel<<<(n4 + 255) / 256, 256>>>((const float4*)x, (float4*)gx, n4);
    }

    for (int l = 0; l < DEPTH; l++) {
        const float* L1w = ln1w + (size_t)l * DMODEL;
        const float* L1b = ln1b + (size_t)l * DMODEL;
        const float* Bo  = bo   + (size_t)l * DMODEL;
        const float* L2w = ln2w + (size_t)l * DMODEL;
        const float* L2b = ln2b + (size_t)l * DMODEL;
        const float* B1  = b1   + (size_t)l * DFF;
        const float* B2  = b2   + (size_t)l * DMODEL;

        const __half* Wq = qkvT + (size_t)l * QKV3 * DMODEL;
        const __half* Wo = woT  + (size_t)l * DMODEL * DMODEL;
        const __half* W1 = w1T  + (size_t)l * DFF * DMODEL;
        const __half* W2 = w2T  + (size_t)l * DMODEL * DFF;

        ln_kernel<1><<<TOKENS / 16, 256>>>(gx, L1w, L1b, gh);
        gemm_fp16_kernel<0, 1><<<dim3(QKV3 / 128, TOKENS / 128), 256>>>(
            gh, Wq, nullptr, nullptr, gqkv, TOKENS, QKV3, DMODEL);
        attn_fp16_kernel<<<dim3(SEQ / 128, 8 * HEADS), 256>>>(gqkv, gao);
        gemm_fp16_kernel<1, 0><<<dim3(DMODEL / 128, TOKENS / 128), 256>>>(
            gao, Wo, Bo, gx, gx, TOKENS, DMODEL, DMODEL);
        ln_kernel<1><<<TOKENS / 16, 256>>>(gx, L2w, L2b, gh);
        gemm_fp16_kernel<2, 1><<<dim3(DFF / 128, TOKENS / 128), 256>>>(
            gh, W1, B1, nullptr, gff, TOKENS, DFF, DMODEL);
        gemm_fp16_kernel<1, 0><<<dim3(DMODEL / 128, TOKENS / 128), 256>>>(
            gff, W2, B2, gx, gx, TOKENS, DMODEL, DFF);
    }

    ln_kernel<0><<<TOKENS / 16, 256>>>(gx, lnfw, lnfb, (float*)d_out);
}